// round 1
// baseline (speedup 1.0000x reference)
#include <cuda_runtime.h>

#define NN 50000
#define NE 800000
#define ET 850000            // NE + NN self loops
#define FIN 128
#define HID 64
#define HEADS 4

// ---------------- device scratch (static allocation only) ----------------
static __device__ float g_h0[NN * HID];            // 12.8 MB
static __device__ float g_hA[NN * HEADS * HID];    // 51.2 MB
static __device__ float g_hB[NN * HEADS * HID];    // 51.2 MB
static __device__ float g_as[NN * HEADS];
static __device__ float g_ad[NN * HEADS];
static __device__ float g_alpha[(size_t)ET * HEADS]; // 13.6 MB (exp numerators)
static __device__ int   g_cnt[NN];
static __device__ int   g_rowptr[NN + 1];
static __device__ int   g_cursor[NN];
static __device__ int   g_csrc[ET];

__device__ __forceinline__ float leaky(float v) { return v > 0.f ? v : 0.2f * v; }

// ---------------- CSR construction ----------------
__global__ void k_zero(int* p, int n) {
    int i = blockIdx.x * blockDim.x + threadIdx.x;
    if (i < n) p[i] = 0;
}

__global__ void k_hist(const int* __restrict__ ei) {
    int i = blockIdx.x * blockDim.x + threadIdx.x;
    if (i >= ET) return;
    int d = (i < NE) ? ei[NE + i] : (i - NE);
    atomicAdd(&g_cnt[d], 1);
}

__global__ void k_scan() {
    __shared__ int warp_sums[32];
    __shared__ int s_carry;
    const int tid = threadIdx.x, lane = tid & 31, wid = tid >> 5;
    if (tid == 0) s_carry = 0;
    __syncthreads();
    for (int base = 0; base < NN; base += 1024) {
        int i = base + tid;
        int v = (i < NN) ? g_cnt[i] : 0;
        int x = v;
        #pragma unroll
        for (int o = 1; o < 32; o <<= 1) {
            int y = __shfl_up_sync(0xffffffffu, x, o);
            if (lane >= o) x += y;
        }
        if (lane == 31) warp_sums[wid] = x;
        __syncthreads();
        if (wid == 0) {
            int w = warp_sums[lane];
            #pragma unroll
            for (int o = 1; o < 32; o <<= 1) {
                int y = __shfl_up_sync(0xffffffffu, w, o);
                if (lane >= o) w += y;
            }
            warp_sums[lane] = w;
        }
        __syncthreads();
        int offset = s_carry + (wid > 0 ? warp_sums[wid - 1] : 0);
        int excl = offset + x - v;
        if (i < NN) { g_rowptr[i] = excl; g_cursor[i] = excl; }
        __syncthreads();
        if (tid == 1023) s_carry += warp_sums[31];
        __syncthreads();
    }
    if (tid == 0) g_rowptr[NN] = s_carry;
}

__global__ void k_scatter(const int* __restrict__ ei) {
    int i = blockIdx.x * blockDim.x + threadIdx.x;
    if (i >= ET) return;
    int s, d;
    if (i < NE) { s = ei[i]; d = ei[NE + i]; }
    else        { s = i - NE; d = s; }
    int pos = atomicAdd(&g_cursor[d], 1);
    g_csrc[pos] = s;
}

// ---------------- fp32 SGEMM: C[M,N] = A[M,K] @ B[K,N] (+bias, +relu) ------
// BM=BN=64, BK=16, 256 threads, 4x4 microtile. K%16==0, N%64==0 required.
template<bool BIAS, bool RELU>
__global__ void k_gemm(const float* __restrict__ A, const float* __restrict__ B,
                       const float* __restrict__ bias, float* __restrict__ C,
                       int M, int K, int N) {
    __shared__ float As[16][64];
    __shared__ float Bs[16][64];
    const int t = threadIdx.x;
    const int tx = t & 15, ty = t >> 4;
    const int m0 = blockIdx.x * 64, n0 = blockIdx.y * 64;
    const int arow = t >> 2, akk = (t & 3) << 2;
    const int brow = t >> 4, bcol = (t & 15) << 2;
    float acc[4][4];
    #pragma unroll
    for (int i = 0; i < 4; i++)
        #pragma unroll
        for (int j = 0; j < 4; j++) acc[i][j] = 0.f;

    const bool aval = (m0 + arow) < M;
    const float* Ap = A + (size_t)(m0 + arow) * K + akk;
    const float* Bp = B + (size_t)brow * N + n0 + bcol;

    for (int k0 = 0; k0 < K; k0 += 16) {
        float4 av = aval ? *(const float4*)(Ap + k0) : make_float4(0.f, 0.f, 0.f, 0.f);
        float4 bv = *(const float4*)(Bp + (size_t)k0 * N);
        As[akk + 0][arow] = av.x; As[akk + 1][arow] = av.y;
        As[akk + 2][arow] = av.z; As[akk + 3][arow] = av.w;
        *(float4*)&Bs[brow][bcol] = bv;
        __syncthreads();
        #pragma unroll
        for (int k = 0; k < 16; k++) {
            float4 a = *(const float4*)&As[k][ty << 2];
            float4 b = *(const float4*)&Bs[k][tx << 2];
            acc[0][0] += a.x * b.x; acc[0][1] += a.x * b.y; acc[0][2] += a.x * b.z; acc[0][3] += a.x * b.w;
            acc[1][0] += a.y * b.x; acc[1][1] += a.y * b.y; acc[1][2] += a.y * b.z; acc[1][3] += a.y * b.w;
            acc[2][0] += a.z * b.x; acc[2][1] += a.z * b.y; acc[2][2] += a.z * b.z; acc[2][3] += a.z * b.w;
            acc[3][0] += a.w * b.x; acc[3][1] += a.w * b.y; acc[3][2] += a.w * b.z; acc[3][3] += a.w * b.w;
        }
        __syncthreads();
    }
    float4 b4 = make_float4(0.f, 0.f, 0.f, 0.f);
    if (BIAS) b4 = *(const float4*)(bias + n0 + (tx << 2));
    #pragma unroll
    for (int i = 0; i < 4; i++) {
        int m = m0 + (ty << 2) + i;
        if (m < M) {
            float4 v;
            v.x = acc[i][0] + b4.x; v.y = acc[i][1] + b4.y;
            v.z = acc[i][2] + b4.z; v.w = acc[i][3] + b4.w;
            if (RELU) {
                v.x = fmaxf(v.x, 0.f); v.y = fmaxf(v.y, 0.f);
                v.z = fmaxf(v.z, 0.f); v.w = fmaxf(v.w, 0.f);
            }
            *(float4*)(C + (size_t)m * N + n0 + (tx << 2)) = v;
        }
    }
}

// ---------------- per-node attention coefficients ----------------
// warp per node; lane owns channels [lane*EPL, lane*EPL+EPL), all same head.
template<int H>
__global__ void k_alpha(const float* __restrict__ h, const float* __restrict__ a_s,
                        const float* __restrict__ a_d) {
    constexpr int HC = H * 64, EPL = HC / 32, LPH = 32 / H;
    int gw = (blockIdx.x * blockDim.x + threadIdx.x) >> 5;
    int lane = threadIdx.x & 31;
    if (gw >= NN) return;
    const float* row = h + (size_t)gw * HC + lane * EPL;
    const float* asp = a_s + lane * EPL;
    const float* adp = a_d + lane * EPL;
    float ps = 0.f, pd = 0.f;
    if constexpr (EPL >= 4) {
        #pragma unroll
        for (int k = 0; k < EPL; k += 4) {
            float4 hv = *(const float4*)(row + k);
            float4 sv = *(const float4*)(asp + k);
            float4 dv = *(const float4*)(adp + k);
            ps += hv.x * sv.x + hv.y * sv.y + hv.z * sv.z + hv.w * sv.w;
            pd += hv.x * dv.x + hv.y * dv.y + hv.z * dv.z + hv.w * dv.w;
        }
    } else {
        float2 hv = *(const float2*)row;
        float2 sv = *(const float2*)asp;
        float2 dv = *(const float2*)adp;
        ps = hv.x * sv.x + hv.y * sv.y;
        pd = hv.x * dv.x + hv.y * dv.y;
    }
    #pragma unroll
    for (int o = 1; o < LPH; o <<= 1) {
        ps += __shfl_xor_sync(0xffffffffu, ps, o);
        pd += __shfl_xor_sync(0xffffffffu, pd, o);
    }
    if ((lane & (LPH - 1)) == 0) {
        int head = lane / LPH;
        g_as[gw * H + head] = ps;
        g_ad[gw * H + head] = pd;
    }
}

// ---------------- warp-per-dst-node softmax + aggregation ----------------
template<int H, bool RELU>
__global__ void k_agg(const float* __restrict__ h, const float* __restrict__ bias,
                      float* __restrict__ out) {
    constexpr int HC = H * 64, EPL = HC / 32, LPH = 32 / H;
    int gw = (blockIdx.x * blockDim.x + threadIdx.x) >> 5;
    int lane = threadIdx.x & 31;
    if (gw >= NN) return;
    const int beg = g_rowptr[gw], end = g_rowptr[gw + 1];

    float adv[H], m[H], ssum[H];
    #pragma unroll
    for (int t = 0; t < H; t++) { adv[t] = g_ad[gw * H + t]; m[t] = -1e30f; ssum[t] = 0.f; }

    // pass 1: per-head max over incoming edges (lane-parallel)
    for (int i = beg + lane; i < end; i += 32) {
        int s = g_csrc[i];
        if constexpr (H == 4) {
            float4 av = *(const float4*)&g_as[s * 4];
            m[0] = fmaxf(m[0], leaky(av.x + adv[0]));
            m[1] = fmaxf(m[1], leaky(av.y + adv[1]));
            m[2] = fmaxf(m[2], leaky(av.z + adv[2]));
            m[3] = fmaxf(m[3], leaky(av.w + adv[3]));
        } else {
            m[0] = fmaxf(m[0], leaky(g_as[s] + adv[0]));
        }
    }
    #pragma unroll
    for (int t = 0; t < H; t++)
        #pragma unroll
        for (int o = 1; o < 32; o <<= 1)
            m[t] = fmaxf(m[t], __shfl_xor_sync(0xffffffffu, m[t], o));

    // pass 2: exp numerators (stored) + per-head sum
    for (int i = beg + lane; i < end; i += 32) {
        int s = g_csrc[i];
        if constexpr (H == 4) {
            float4 av = *(const float4*)&g_as[s * 4];
            float e0 = __expf(leaky(av.x + adv[0]) - m[0]);
            float e1 = __expf(leaky(av.y + adv[1]) - m[1]);
            float e2 = __expf(leaky(av.z + adv[2]) - m[2]);
            float e3 = __expf(leaky(av.w + adv[3]) - m[3]);
            *(float4*)&g_alpha[(size_t)i * 4] = make_float4(e0, e1, e2, e3);
            ssum[0] += e0; ssum[1] += e1; ssum[2] += e2; ssum[3] += e3;
        } else {
            float e0 = __expf(leaky(g_as[s] + adv[0]) - m[0]);
            g_alpha[i] = e0;
            ssum[0] += e0;
        }
    }
    #pragma unroll
    for (int t = 0; t < H; t++)
        #pragma unroll
        for (int o = 1; o < 32; o <<= 1)
            ssum[t] += __shfl_xor_sync(0xffffffffu, ssum[t], o);

    float rinv[H];
    #pragma unroll
    for (int t = 0; t < H; t++) rinv[t] = 1.f / (ssum[t] + 1e-16f);
    __syncwarp();  // make pass-2 alpha stores visible to all lanes

    const int head = lane / LPH;
    float ri = rinv[0];
    if constexpr (H == 4)
        ri = (lane < 16) ? ((lane < 8) ? rinv[0] : rinv[1])
                         : ((lane < 24) ? rinv[2] : rinv[3]);

    // pass 3: weighted gather of h[src] (lane owns EPL contiguous channels)
    float acc[EPL];
    #pragma unroll
    for (int k = 0; k < EPL; k++) acc[k] = 0.f;
    const float* hb = h + lane * EPL;
    for (int i = beg; i < end; i++) {
        int s = g_csrc[i];
        float w = g_alpha[(size_t)i * H + head] * ri;
        const float* hp = hb + (size_t)s * HC;
        if constexpr (EPL >= 4) {
            #pragma unroll
            for (int k = 0; k < EPL; k += 4) {
                float4 hv = *(const float4*)(hp + k);
                acc[k] += w * hv.x; acc[k + 1] += w * hv.y;
                acc[k + 2] += w * hv.z; acc[k + 3] += w * hv.w;
            }
        } else {
            float2 hv = *(const float2*)hp;
            acc[0] += w * hv.x; acc[1] += w * hv.y;
        }
    }

    const float* bp = bias + lane * EPL;
    #pragma unroll
    for (int k = 0; k < EPL; k++) {
        float v = acc[k] + bp[k];
        if (RELU) v = fmaxf(v, 0.f);
        acc[k] = v;
    }
    float* op = out + (size_t)gw * HC + lane * EPL;
    if constexpr (EPL >= 4) {
        #pragma unroll
        for (int k = 0; k < EPL; k += 4)
            *(float4*)(op + k) = make_float4(acc[k], acc[k + 1], acc[k + 2], acc[k + 3]);
    } else {
        *(float2*)op = make_float2(acc[0], acc[1]);
    }
}

// ---------------- fused output MLP: relu(h@Wo1+bo1)@Wo2+bo2 ----------------
__global__ void k_mlp(const float* __restrict__ hin, const float* __restrict__ Wo1,
                      const float* __restrict__ bo1, const float* __restrict__ Wo2,
                      const float* __restrict__ bo2, float* __restrict__ out) {
    __shared__ float sW1[64 * 32];
    __shared__ float sW2[32];
    __shared__ float sb1[32];
    const int tid = threadIdx.x;
    for (int i = tid; i < 64 * 32; i += blockDim.x) sW1[i] = Wo1[i];
    if (tid < 32) { sW2[tid] = Wo2[tid]; sb1[tid] = bo1[tid]; }
    __syncthreads();
    int gw = (blockIdx.x * blockDim.x + tid) >> 5;
    int lane = tid & 31;
    if (gw >= NN) return;
    const float* row = hin + (size_t)gw * 64;
    float acc = sb1[lane];
    #pragma unroll 8
    for (int k = 0; k < 64; k++) acc += row[k] * sW1[k * 32 + lane];
    acc = fmaxf(acc, 0.f);
    float v = acc * sW2[lane];
    #pragma unroll
    for (int o = 1; o < 32; o <<= 1) v += __shfl_xor_sync(0xffffffffu, v, o);
    if (lane == 0) out[gw] = v + bo2[0];
}

// ---------------- launch ----------------
extern "C" void kernel_launch(void* const* d_in, const int* in_sizes, int n_in,
                              void* d_out, int out_size) {
    const float* x     = (const float*)d_in[0];
    const float* W_emb = (const float*)d_in[1];
    const float* b_emb = (const float*)d_in[2];
    const float* W0    = (const float*)d_in[3];
    const float* as0   = (const float*)d_in[4];
    const float* ad0   = (const float*)d_in[5];
    const float* b0    = (const float*)d_in[6];
    const float* W1    = (const float*)d_in[7];
    const float* as1   = (const float*)d_in[8];
    const float* ad1   = (const float*)d_in[9];
    const float* b1    = (const float*)d_in[10];
    const float* W2    = (const float*)d_in[11];
    const float* as2   = (const float*)d_in[12];
    const float* ad2   = (const float*)d_in[13];
    const float* b2    = (const float*)d_in[14];
    const float* Wo1   = (const float*)d_in[15];
    const float* bo1   = (const float*)d_in[16];
    const float* Wo2   = (const float*)d_in[17];
    const float* bo2   = (const float*)d_in[18];
    const int*   ei    = (const int*)d_in[19];
    float* out = (float*)d_out;

    float *p_h0, *p_hA, *p_hB;
    int* p_cnt;
    cudaGetSymbolAddress((void**)&p_h0, g_h0);
    cudaGetSymbolAddress((void**)&p_hA, g_hA);
    cudaGetSymbolAddress((void**)&p_hB, g_hB);
    cudaGetSymbolAddress((void**)&p_cnt, g_cnt);

    const int MB = (NN + 63) / 64;                 // 782 row tiles
    const int WARP_GRID = (NN * 32 + 255) / 256;   // warp-per-node grids

    // CSR build (deterministic up to intra-node order)
    k_zero<<<(NN + 255) / 256, 256>>>(p_cnt, NN);
    k_hist<<<(ET + 255) / 256, 256>>>(ei);
    k_scan<<<1, 1024>>>();
    k_scatter<<<(ET + 255) / 256, 256>>>(ei);

    // embedding
    k_gemm<true, true><<<dim3(MB, 1), 256>>>(x, W_emb, b_emb, p_h0, NN, FIN, HID);

    // GAT layer 0 (heads=4, concat, relu)
    k_gemm<false, false><<<dim3(MB, 4), 256>>>(p_h0, W0, nullptr, p_hA, NN, HID, 256);
    k_alpha<4><<<WARP_GRID, 256>>>(p_hA, as0, ad0);
    k_agg<4, true><<<WARP_GRID, 256>>>(p_hA, b0, p_hB);

    // GAT layer 1
    k_gemm<false, false><<<dim3(MB, 4), 256>>>(p_hB, W1, nullptr, p_hA, NN, 256, 256);
    k_alpha<4><<<WARP_GRID, 256>>>(p_hA, as1, ad1);
    k_agg<4, true><<<WARP_GRID, 256>>>(p_hA, b1, p_hB);

    // GAT layer 2 (heads=1, mean==identity, no relu)
    k_gemm<false, false><<<dim3(MB, 1), 256>>>(p_hB, W2, nullptr, p_hA, NN, 256, 64);
    k_alpha<1><<<WARP_GRID, 256>>>(p_hA, as2, ad2);
    k_agg<1, false><<<WARP_GRID, 256>>>(p_hA, b2, p_h0);

    // output MLP
    k_mlp<<<WARP_GRID, 256>>>(p_h0, Wo1, bo1, Wo2, bo2, out);
}

// round 2
// speedup vs baseline: 1.0617x; 1.0617x over previous
#include <cuda_runtime.h>

#define NN 50000
#define NE 800000
#define ET 850000            // NE + NN self loops
#define FIN 128
#define HID 64
#define HEADS 4

typedef unsigned long long ull;

// ---------------- device scratch (static allocation only) ----------------
static __device__ float g_h0[NN * HID];            // 12.8 MB
static __device__ float g_hA[NN * HEADS * HID];    // 51.2 MB
static __device__ float g_hB[NN * HEADS * HID];    // 51.2 MB
static __device__ float g_as[NN * HEADS];
static __device__ float g_ad[NN * HEADS];
static __device__ float g_alpha[(size_t)ET * HEADS]; // 13.6 MB (exp numerators)
static __device__ int   g_cnt[NN];
static __device__ int   g_rowptr[NN + 1];
static __device__ int   g_cursor[NN];
static __device__ int   g_csrc[ET];

__device__ __forceinline__ float leaky(float v) { return v > 0.f ? v : 0.2f * v; }

// packed fp32x2 helpers (FFMA2 — only reachable via PTX on sm_103a)
__device__ __forceinline__ ull dupf(float f) {
    ull r; asm("mov.b64 %0, {%1, %1};" : "=l"(r) : "f"(f)); return r;
}
__device__ __forceinline__ void ffma2(ull& d, ull a, ull b) {
    asm("fma.rn.f32x2 %0, %1, %2, %0;" : "+l"(d) : "l"(a), "l"(b));
}
__device__ __forceinline__ float2 unpack2(ull v) {
    float2 r; asm("mov.b64 {%0, %1}, %2;" : "=f"(r.x), "=f"(r.y) : "l"(v)); return r;
}

// ---------------- CSR construction ----------------
__global__ void k_zero(int* p, int n) {
    int i = blockIdx.x * blockDim.x + threadIdx.x;
    if (i < n) p[i] = 0;
}

__global__ void k_hist(const int* __restrict__ ei) {
    int i = blockIdx.x * blockDim.x + threadIdx.x;
    if (i >= ET) return;
    int d = (i < NE) ? ei[NE + i] : (i - NE);
    atomicAdd(&g_cnt[d], 1);
}

__global__ void k_scan() {
    __shared__ int warp_sums[32];
    __shared__ int s_carry;
    const int tid = threadIdx.x, lane = tid & 31, wid = tid >> 5;
    if (tid == 0) s_carry = 0;
    __syncthreads();
    for (int base = 0; base < NN; base += 1024) {
        int i = base + tid;
        int v = (i < NN) ? g_cnt[i] : 0;
        int x = v;
        #pragma unroll
        for (int o = 1; o < 32; o <<= 1) {
            int y = __shfl_up_sync(0xffffffffu, x, o);
            if (lane >= o) x += y;
        }
        if (lane == 31) warp_sums[wid] = x;
        __syncthreads();
        if (wid == 0) {
            int w = warp_sums[lane];
            #pragma unroll
            for (int o = 1; o < 32; o <<= 1) {
                int y = __shfl_up_sync(0xffffffffu, w, o);
                if (lane >= o) w += y;
            }
            warp_sums[lane] = w;
        }
        __syncthreads();
        int offset = s_carry + (wid > 0 ? warp_sums[wid - 1] : 0);
        int excl = offset + x - v;
        if (i < NN) { g_rowptr[i] = excl; g_cursor[i] = excl; }
        __syncthreads();
        if (tid == 1023) s_carry += warp_sums[31];
        __syncthreads();
    }
    if (tid == 0) g_rowptr[NN] = s_carry;
}

__global__ void k_scatter(const int* __restrict__ ei) {
    int i = blockIdx.x * blockDim.x + threadIdx.x;
    if (i >= ET) return;
    int s, d;
    if (i < NE) { s = ei[i]; d = ei[NE + i]; }
    else        { s = i - NE; d = s; }
    int pos = atomicAdd(&g_cursor[d], 1);
    g_csrc[pos] = s;
}

// ---------------- FFMA2 SGEMM: C[M,N] = A[M,K] @ B[K,N] ----------------
// BM=128, BN=64, BK=16, 256 threads, 8x4 microtile (row-paired f32x2 accums).
// Requirements: K%16==0, N%64==0.
// Optional fused epilogue: attention dots ps = h·a_src, pd = h·a_dst per head
// (each 64-col block == one head), written to g_as/g_ad.
template<bool BIAS, bool RELU, bool ALPHA, int AH>
__global__ __launch_bounds__(256)
void k_gemm2(const float* __restrict__ A, const float* __restrict__ B,
             const float* __restrict__ bias,
             const float* __restrict__ a_src, const float* __restrict__ a_dst,
             float* __restrict__ C, int M, int K, int N) {
    __shared__ float As[16][128];   // [k][m]
    __shared__ float Bs[16][64];    // [k][n]
    const int t  = threadIdx.x;
    const int tx = t & 15, ty = t >> 4;
    const int m0 = blockIdx.x * 128;
    const int by = blockIdx.y;
    const int n0 = by * 64;

    ull acc[4][4];
    #pragma unroll
    for (int p = 0; p < 4; p++)
        #pragma unroll
        for (int j = 0; j < 4; j++) acc[p][j] = 0ull;

    const int brow = t >> 4, bcol = (t & 15) << 2;

    for (int k0 = 0; k0 < K; k0 += 16) {
        #pragma unroll
        for (int it = 0; it < 2; it++) {
            int idx = t + it * 256;       // 0..511
            int row = idx & 127;
            int kc  = (idx >> 7) << 2;    // 0,4,8,12
            float4 av = make_float4(0.f, 0.f, 0.f, 0.f);
            if (m0 + row < M)
                av = *(const float4*)(A + (size_t)(m0 + row) * K + k0 + kc);
            As[kc + 0][row] = av.x; As[kc + 1][row] = av.y;
            As[kc + 2][row] = av.z; As[kc + 3][row] = av.w;
        }
        *(float4*)&Bs[brow][bcol] =
            *(const float4*)(B + (size_t)(k0 + brow) * N + n0 + bcol);
        __syncthreads();
        #pragma unroll
        for (int k = 0; k < 16; k++) {
            const ull* ap = (const ull*)&As[k][0];
            ull a0 = ap[(ty << 2) + 0];
            ull a1 = ap[(ty << 2) + 1];
            ull a2 = ap[(ty << 2) + 2];
            ull a3 = ap[(ty << 2) + 3];
            float4 b = *(const float4*)&Bs[k][tx << 2];
            ull b0 = dupf(b.x), b1 = dupf(b.y), b2 = dupf(b.z), b3 = dupf(b.w);
            ffma2(acc[0][0], a0, b0); ffma2(acc[0][1], a0, b1); ffma2(acc[0][2], a0, b2); ffma2(acc[0][3], a0, b3);
            ffma2(acc[1][0], a1, b0); ffma2(acc[1][1], a1, b1); ffma2(acc[1][2], a1, b2); ffma2(acc[1][3], a1, b3);
            ffma2(acc[2][0], a2, b0); ffma2(acc[2][1], a2, b1); ffma2(acc[2][2], a2, b2); ffma2(acc[2][3], a2, b3);
            ffma2(acc[3][0], a3, b0); ffma2(acc[3][1], a3, b1); ffma2(acc[3][2], a3, b2); ffma2(acc[3][3], a3, b3);
        }
        __syncthreads();
    }

    float4 bias4 = make_float4(0.f, 0.f, 0.f, 0.f);
    if (BIAS) bias4 = *(const float4*)(bias + n0 + (tx << 2));
    float4 sa4 = make_float4(0.f, 0.f, 0.f, 0.f);
    float4 sd4 = make_float4(0.f, 0.f, 0.f, 0.f);
    if (ALPHA) {
        sa4 = *(const float4*)(a_src + n0 + (tx << 2));
        sd4 = *(const float4*)(a_dst + n0 + (tx << 2));
    }

    #pragma unroll
    for (int p = 0; p < 4; p++) {
        float2 u0 = unpack2(acc[p][0]);
        float2 u1 = unpack2(acc[p][1]);
        float2 u2 = unpack2(acc[p][2]);
        float2 u3 = unpack2(acc[p][3]);
        int r0 = m0 + (ty << 3) + (p << 1);

        float lo0 = u0.x, lo1 = u1.x, lo2 = u2.x, lo3 = u3.x;
        float hi0 = u0.y, hi1 = u1.y, hi2 = u2.y, hi3 = u3.y;

        if (r0 < M) {
            float4 v = make_float4(lo0 + bias4.x, lo1 + bias4.y, lo2 + bias4.z, lo3 + bias4.w);
            if (RELU) { v.x = fmaxf(v.x, 0.f); v.y = fmaxf(v.y, 0.f); v.z = fmaxf(v.z, 0.f); v.w = fmaxf(v.w, 0.f); }
            *(float4*)(C + (size_t)r0 * N + n0 + (tx << 2)) = v;
        }
        if (r0 + 1 < M) {
            float4 v = make_float4(hi0 + bias4.x, hi1 + bias4.y, hi2 + bias4.z, hi3 + bias4.w);
            if (RELU) { v.x = fmaxf(v.x, 0.f); v.y = fmaxf(v.y, 0.f); v.z = fmaxf(v.z, 0.f); v.w = fmaxf(v.w, 0.f); }
            *(float4*)(C + (size_t)(r0 + 1) * N + n0 + (tx << 2)) = v;
        }
        if (ALPHA) {
            float ps0 = lo0 * sa4.x + lo1 * sa4.y + lo2 * sa4.z + lo3 * sa4.w;
            float pd0 = lo0 * sd4.x + lo1 * sd4.y + lo2 * sd4.z + lo3 * sd4.w;
            float ps1 = hi0 * sa4.x + hi1 * sa4.y + hi2 * sa4.z + hi3 * sa4.w;
            float pd1 = hi0 * sd4.x + hi1 * sd4.y + hi2 * sd4.z + hi3 * sd4.w;
            #pragma unroll
            for (int o = 1; o < 16; o <<= 1) {
                ps0 += __shfl_xor_sync(0xffffffffu, ps0, o);
                pd0 += __shfl_xor_sync(0xffffffffu, pd0, o);
                ps1 += __shfl_xor_sync(0xffffffffu, ps1, o);
                pd1 += __shfl_xor_sync(0xffffffffu, pd1, o);
            }
            if (tx == 0) {
                if (r0 < M)     { g_as[r0 * AH + by] = ps0; g_ad[r0 * AH + by] = pd0; }
                if (r0 + 1 < M) { g_as[(r0 + 1) * AH + by] = ps1; g_ad[(r0 + 1) * AH + by] = pd1; }
            }
        }
    }
}

// ---------------- warp-per-dst-node softmax + aggregation ----------------
template<int H, bool RELU>
__global__ void k_agg(const float* __restrict__ h, const float* __restrict__ bias,
                      float* __restrict__ out) {
    constexpr int HC = H * 64, EPL = HC / 32, LPH = 32 / H;
    int gw = (blockIdx.x * blockDim.x + threadIdx.x) >> 5;
    int lane = threadIdx.x & 31;
    if (gw >= NN) return;
    const int beg = g_rowptr[gw], end = g_rowptr[gw + 1];

    float adv[H], m[H], ssum[H];
    #pragma unroll
    for (int t = 0; t < H; t++) { adv[t] = g_ad[gw * H + t]; m[t] = -1e30f; ssum[t] = 0.f; }

    // pass 1: per-head max over incoming edges (lane-parallel)
    for (int i = beg + lane; i < end; i += 32) {
        int s = g_csrc[i];
        if constexpr (H == 4) {
            float4 av = *(const float4*)&g_as[s * 4];
            m[0] = fmaxf(m[0], leaky(av.x + adv[0]));
            m[1] = fmaxf(m[1], leaky(av.y + adv[1]));
            m[2] = fmaxf(m[2], leaky(av.z + adv[2]));
            m[3] = fmaxf(m[3], leaky(av.w + adv[3]));
        } else {
            m[0] = fmaxf(m[0], leaky(g_as[s] + adv[0]));
        }
    }
    #pragma unroll
    for (int t = 0; t < H; t++)
        #pragma unroll
        for (int o = 1; o < 32; o <<= 1)
            m[t] = fmaxf(m[t], __shfl_xor_sync(0xffffffffu, m[t], o));

    // pass 2: exp numerators (stored) + per-head sum
    for (int i = beg + lane; i < end; i += 32) {
        int s = g_csrc[i];
        if constexpr (H == 4) {
            float4 av = *(const float4*)&g_as[s * 4];
            float e0 = __expf(leaky(av.x + adv[0]) - m[0]);
            float e1 = __expf(leaky(av.y + adv[1]) - m[1]);
            float e2 = __expf(leaky(av.z + adv[2]) - m[2]);
            float e3 = __expf(leaky(av.w + adv[3]) - m[3]);
            *(float4*)&g_alpha[(size_t)i * 4] = make_float4(e0, e1, e2, e3);
            ssum[0] += e0; ssum[1] += e1; ssum[2] += e2; ssum[3] += e3;
        } else {
            float e0 = __expf(leaky(g_as[s] + adv[0]) - m[0]);
            g_alpha[i] = e0;
            ssum[0] += e0;
        }
    }
    #pragma unroll
    for (int t = 0; t < H; t++)
        #pragma unroll
        for (int o = 1; o < 32; o <<= 1)
            ssum[t] += __shfl_xor_sync(0xffffffffu, ssum[t], o);

    float rinv[H];
    #pragma unroll
    for (int t = 0; t < H; t++) rinv[t] = 1.f / (ssum[t] + 1e-16f);
    __syncwarp();  // make pass-2 alpha stores visible to all lanes

    const int head = lane / LPH;
    float ri = rinv[0];
    if constexpr (H == 4)
        ri = (lane < 16) ? ((lane < 8) ? rinv[0] : rinv[1])
                         : ((lane < 24) ? rinv[2] : rinv[3]);

    // pass 3: weighted gather of h[src] (lane owns EPL contiguous channels)
    float acc[EPL];
    #pragma unroll
    for (int k = 0; k < EPL; k++) acc[k] = 0.f;
    const float* hb = h + lane * EPL;
    for (int i = beg; i < end; i++) {
        int s = g_csrc[i];
        float w = g_alpha[(size_t)i * H + head] * ri;
        const float* hp = hb + (size_t)s * HC;
        if constexpr (EPL >= 4) {
            #pragma unroll
            for (int k = 0; k < EPL; k += 4) {
                float4 hv = *(const float4*)(hp + k);
                acc[k] += w * hv.x; acc[k + 1] += w * hv.y;
                acc[k + 2] += w * hv.z; acc[k + 3] += w * hv.w;
            }
        } else {
            float2 hv = *(const float2*)hp;
            acc[0] += w * hv.x; acc[1] += w * hv.y;
        }
    }

    const float* bp = bias + lane * EPL;
    #pragma unroll
    for (int k = 0; k < EPL; k++) {
        float v = acc[k] + bp[k];
        if (RELU) v = fmaxf(v, 0.f);
        acc[k] = v;
    }
    float* op = out + (size_t)gw * HC + lane * EPL;
    if constexpr (EPL >= 4) {
        #pragma unroll
        for (int k = 0; k < EPL; k += 4)
            *(float4*)(op + k) = make_float4(acc[k], acc[k + 1], acc[k + 2], acc[k + 3]);
    } else {
        *(float2*)op = make_float2(acc[0], acc[1]);
    }
}

// ---------------- fused output MLP: relu(h@Wo1+bo1)@Wo2+bo2 ----------------
__global__ void k_mlp(const float* __restrict__ hin, const float* __restrict__ Wo1,
                      const float* __restrict__ bo1, const float* __restrict__ Wo2,
                      const float* __restrict__ bo2, float* __restrict__ out) {
    __shared__ float sW1[64 * 32];
    __shared__ float sW2[32];
    __shared__ float sb1[32];
    const int tid = threadIdx.x;
    for (int i = tid; i < 64 * 32; i += blockDim.x) sW1[i] = Wo1[i];
    if (tid < 32) { sW2[tid] = Wo2[tid]; sb1[tid] = bo1[tid]; }
    __syncthreads();
    int gw = (blockIdx.x * blockDim.x + tid) >> 5;
    int lane = tid & 31;
    if (gw >= NN) return;
    const float* row = hin + (size_t)gw * 64;
    float acc = sb1[lane];
    #pragma unroll 8
    for (int k = 0; k < 64; k++) acc += row[k] * sW1[k * 32 + lane];
    acc = fmaxf(acc, 0.f);
    float v = acc * sW2[lane];
    #pragma unroll
    for (int o = 1; o < 32; o <<= 1) v += __shfl_xor_sync(0xffffffffu, v, o);
    if (lane == 0) out[gw] = v + bo2[0];
}

// ---------------- launch ----------------
extern "C" void kernel_launch(void* const* d_in, const int* in_sizes, int n_in,
                              void* d_out, int out_size) {
    const float* x     = (const float*)d_in[0];
    const float* W_emb = (const float*)d_in[1];
    const float* b_emb = (const float*)d_in[2];
    const float* W0    = (const float*)d_in[3];
    const float* as0   = (const float*)d_in[4];
    const float* ad0   = (const float*)d_in[5];
    const float* b0    = (const float*)d_in[6];
    const float* W1    = (const float*)d_in[7];
    const float* as1   = (const float*)d_in[8];
    const float* ad1   = (const float*)d_in[9];
    const float* b1    = (const float*)d_in[10];
    const float* W2    = (const float*)d_in[11];
    const float* as2   = (const float*)d_in[12];
    const float* ad2   = (const float*)d_in[13];
    const float* b2    = (const float*)d_in[14];
    const float* Wo1   = (const float*)d_in[15];
    const float* bo1   = (const float*)d_in[16];
    const float* Wo2   = (const float*)d_in[17];
    const float* bo2   = (const float*)d_in[18];
    const int*   ei    = (const int*)d_in[19];
    float* out = (float*)d_out;

    float *p_h0, *p_hA, *p_hB;
    int* p_cnt;
    cudaGetSymbolAddress((void**)&p_h0, g_h0);
    cudaGetSymbolAddress((void**)&p_hA, g_hA);
    cudaGetSymbolAddress((void**)&p_hB, g_hB);
    cudaGetSymbolAddress((void**)&p_cnt, g_cnt);

    const int MB = (NN + 127) / 128;               // 391 row tiles
    const int WARP_GRID = (NN * 32 + 255) / 256;   // warp-per-node grids

    // CSR build (deterministic up to intra-node order)
    k_zero<<<(NN + 255) / 256, 256>>>(p_cnt, NN);
    k_hist<<<(ET + 255) / 256, 256>>>(ei);
    k_scan<<<1, 1024>>>();
    k_scatter<<<(ET + 255) / 256, 256>>>(ei);

    // embedding: relu(x @ W_emb + b_emb)
    k_gemm2<true, true, false, 1><<<dim3(MB, 1), 256>>>(
        x, W_emb, b_emb, nullptr, nullptr, p_h0, NN, FIN, HID);

    // GAT layer 0 (heads=4, concat, relu); alpha dots fused into GEMM epilogue
    k_gemm2<false, false, true, 4><<<dim3(MB, 4), 256>>>(
        p_h0, W0, nullptr, as0, ad0, p_hA, NN, HID, 256);
    k_agg<4, true><<<WARP_GRID, 256>>>(p_hA, b0, p_hB);

    // GAT layer 1
    k_gemm2<false, false, true, 4><<<dim3(MB, 4), 256>>>(
        p_hB, W1, nullptr, as1, ad1, p_hA, NN, 256, 256);
    k_agg<4, true><<<WARP_GRID, 256>>>(p_hA, b1, p_hB);

    // GAT layer 2 (heads=1, mean==identity, no relu)
    k_gemm2<false, false, true, 1><<<dim3(MB, 1), 256>>>(
        p_hB, W2, nullptr, as2, ad2, p_hA, NN, 256, 64);
    k_agg<1, false><<<WARP_GRID, 256>>>(p_hA, b2, p_h0);

    // output MLP
    k_mlp<<<WARP_GRID, 256>>>(p_h0, Wo1, bo1, Wo2, bo2, out);
}

// round 3
// speedup vs baseline: 1.1697x; 1.1017x over previous
#include <cuda_runtime.h>

#define NN 50000
#define NE 800000
#define ET 850000            // NE + NN self loops
#define FIN 128
#define HID 64
#define HEADS 4

typedef unsigned long long ull;

// ---------------- device scratch (static allocation only) ----------------
static __device__ float g_h0[NN * HID];            // 12.8 MB
static __device__ float g_hA[NN * HEADS * HID];    // 51.2 MB
static __device__ float g_hB[NN * HEADS * HID];    // 51.2 MB
static __device__ float g_as[NN * HEADS];
static __device__ float g_ad[NN * HEADS];
static __device__ int   g_cnt[NN];
static __device__ int   g_rowptr[NN + 1];
static __device__ int   g_cursor[NN];
static __device__ int   g_csrc[ET];

__device__ __forceinline__ float leaky(float v) { return v > 0.f ? v : 0.2f * v; }

// packed fp32x2 helpers (FFMA2 — only reachable via PTX on sm_103a)
__device__ __forceinline__ ull dupf(float f) {
    ull r; asm("mov.b64 %0, {%1, %1};" : "=l"(r) : "f"(f)); return r;
}
__device__ __forceinline__ void ffma2(ull& d, ull a, ull b) {
    asm("fma.rn.f32x2 %0, %1, %2, %0;" : "+l"(d) : "l"(a), "l"(b));
}
__device__ __forceinline__ float2 unpack2(ull v) {
    float2 r; asm("mov.b64 {%0, %1}, %2;" : "=f"(r.x), "=f"(r.y) : "l"(v)); return r;
}

// ---------------- CSR construction ----------------
__global__ void k_zero(int* p, int n) {
    int i = blockIdx.x * blockDim.x + threadIdx.x;
    if (i < n) p[i] = 0;
}

__global__ void k_hist(const int* __restrict__ ei) {
    int i = blockIdx.x * blockDim.x + threadIdx.x;
    if (i >= ET) return;
    int d = (i < NE) ? ei[NE + i] : (i - NE);
    atomicAdd(&g_cnt[d], 1);
}

__global__ void k_scan() {
    __shared__ int warp_sums[32];
    __shared__ int s_carry;
    const int tid = threadIdx.x, lane = tid & 31, wid = tid >> 5;
    if (tid == 0) s_carry = 0;
    __syncthreads();
    for (int base = 0; base < NN; base += 1024) {
        int i = base + tid;
        int v = (i < NN) ? g_cnt[i] : 0;
        int x = v;
        #pragma unroll
        for (int o = 1; o < 32; o <<= 1) {
            int y = __shfl_up_sync(0xffffffffu, x, o);
            if (lane >= o) x += y;
        }
        if (lane == 31) warp_sums[wid] = x;
        __syncthreads();
        if (wid == 0) {
            int w = warp_sums[lane];
            #pragma unroll
            for (int o = 1; o < 32; o <<= 1) {
                int y = __shfl_up_sync(0xffffffffu, w, o);
                if (lane >= o) w += y;
            }
            warp_sums[lane] = w;
        }
        __syncthreads();
        int offset = s_carry + (wid > 0 ? warp_sums[wid - 1] : 0);
        int excl = offset + x - v;
        if (i < NN) { g_rowptr[i] = excl; g_cursor[i] = excl; }
        __syncthreads();
        if (tid == 1023) s_carry += warp_sums[31];
        __syncthreads();
    }
    if (tid == 0) g_rowptr[NN] = s_carry;
}

__global__ void k_scatter(const int* __restrict__ ei) {
    int i = blockIdx.x * blockDim.x + threadIdx.x;
    if (i >= ET) return;
    int s, d;
    if (i < NE) { s = ei[i]; d = ei[NE + i]; }
    else        { s = i - NE; d = s; }
    int pos = atomicAdd(&g_cursor[d], 1);
    g_csrc[pos] = s;
}

// ---------------- FFMA2 SGEMM, double-buffered ----------------
// BM=128, BN=64, BK=16, 256 threads, 8x4 microtile (row-paired f32x2 accums).
// Requirements: K%16==0, N%64==0.
__device__ __forceinline__ void gemm_compute(const float (*As)[128], const float (*Bs)[64],
                                             ull acc[4][4], int ty, int tx) {
    #pragma unroll
    for (int k = 0; k < 16; k++) {
        const ull* ap = (const ull*)&As[k][0];
        ull a0 = ap[(ty << 2) + 0];
        ull a1 = ap[(ty << 2) + 1];
        ull a2 = ap[(ty << 2) + 2];
        ull a3 = ap[(ty << 2) + 3];
        float4 b = *(const float4*)&Bs[k][tx << 2];
        ull b0 = dupf(b.x), b1 = dupf(b.y), b2 = dupf(b.z), b3 = dupf(b.w);
        ffma2(acc[0][0], a0, b0); ffma2(acc[0][1], a0, b1); ffma2(acc[0][2], a0, b2); ffma2(acc[0][3], a0, b3);
        ffma2(acc[1][0], a1, b0); ffma2(acc[1][1], a1, b1); ffma2(acc[1][2], a1, b2); ffma2(acc[1][3], a1, b3);
        ffma2(acc[2][0], a2, b0); ffma2(acc[2][1], a2, b1); ffma2(acc[2][2], a2, b2); ffma2(acc[2][3], a2, b3);
        ffma2(acc[3][0], a3, b0); ffma2(acc[3][1], a3, b1); ffma2(acc[3][2], a3, b2); ffma2(acc[3][3], a3, b3);
    }
}

template<bool BIAS, bool RELU, bool ALPHA, int AH>
__global__ __launch_bounds__(256)
void k_gemm2(const float* __restrict__ A, const float* __restrict__ B,
             const float* __restrict__ bias,
             const float* __restrict__ a_src, const float* __restrict__ a_dst,
             float* __restrict__ C, int M, int K, int N) {
    __shared__ float As[2][16][128];   // [stage][k][m]
    __shared__ float Bs[2][16][64];    // [stage][k][n]
    const int t  = threadIdx.x;
    const int tx = t & 15, ty = t >> 4;
    const int m0 = blockIdx.x * 128;
    const int by = blockIdx.y;
    const int n0 = by * 64;

    ull acc[4][4];
    #pragma unroll
    for (int p = 0; p < 4; p++)
        #pragma unroll
        for (int j = 0; j < 4; j++) acc[p][j] = 0ull;

    // A load mapping: thread loads 2 float4s of row (t&127): k = akc..akc+3, akc+8..akc+11
    const int arow = t & 127;
    const int akc  = (t >> 7) << 2;     // 0 or 4
    const bool aval = (m0 + arow) < M;
    const float* Ap = A + (size_t)(m0 + arow) * K + akc;
    const int brow = t >> 4, bcol = (t & 15) << 2;
    const float* Bp = B + (size_t)brow * N + n0 + bcol;

    const float4 fz = make_float4(0.f, 0.f, 0.f, 0.f);
    float4 pa0, pa1, pb;

    // prologue: prefetch k0=0, store stage 0
    pa0 = aval ? *(const float4*)(Ap)     : fz;
    pa1 = aval ? *(const float4*)(Ap + 8) : fz;
    pb  = *(const float4*)(Bp);
    As[0][akc + 0][arow] = pa0.x; As[0][akc + 1][arow] = pa0.y;
    As[0][akc + 2][arow] = pa0.z; As[0][akc + 3][arow] = pa0.w;
    As[0][akc + 8][arow] = pa1.x; As[0][akc + 9][arow] = pa1.y;
    As[0][akc + 10][arow] = pa1.z; As[0][akc + 11][arow] = pa1.w;
    *(float4*)&Bs[0][brow][bcol] = pb;
    __syncthreads();

    int buf = 0;
    for (int k0 = 16; k0 < K; k0 += 16) {
        // prefetch next tile into regs (latency hidden by compute below)
        pa0 = aval ? *(const float4*)(Ap + k0)     : fz;
        pa1 = aval ? *(const float4*)(Ap + k0 + 8) : fz;
        pb  = *(const float4*)(Bp + (size_t)k0 * N);
        gemm_compute(As[buf], Bs[buf], acc, ty, tx);
        int nb = buf ^ 1;
        As[nb][akc + 0][arow] = pa0.x; As[nb][akc + 1][arow] = pa0.y;
        As[nb][akc + 2][arow] = pa0.z; As[nb][akc + 3][arow] = pa0.w;
        As[nb][akc + 8][arow] = pa1.x; As[nb][akc + 9][arow] = pa1.y;
        As[nb][akc + 10][arow] = pa1.z; As[nb][akc + 11][arow] = pa1.w;
        *(float4*)&Bs[nb][brow][bcol] = pb;
        __syncthreads();
        buf = nb;
    }
    gemm_compute(As[buf], Bs[buf], acc, ty, tx);

    float4 bias4 = fz;
    if (BIAS) bias4 = *(const float4*)(bias + n0 + (tx << 2));
    float4 sa4 = fz, sd4 = fz;
    if (ALPHA) {
        sa4 = *(const float4*)(a_src + n0 + (tx << 2));
        sd4 = *(const float4*)(a_dst + n0 + (tx << 2));
    }

    #pragma unroll
    for (int p = 0; p < 4; p++) {
        float2 u0 = unpack2(acc[p][0]);
        float2 u1 = unpack2(acc[p][1]);
        float2 u2 = unpack2(acc[p][2]);
        float2 u3 = unpack2(acc[p][3]);
        int r0 = m0 + (ty << 3) + (p << 1);

        float lo0 = u0.x, lo1 = u1.x, lo2 = u2.x, lo3 = u3.x;
        float hi0 = u0.y, hi1 = u1.y, hi2 = u2.y, hi3 = u3.y;

        if (r0 < M) {
            float4 v = make_float4(lo0 + bias4.x, lo1 + bias4.y, lo2 + bias4.z, lo3 + bias4.w);
            if (RELU) { v.x = fmaxf(v.x, 0.f); v.y = fmaxf(v.y, 0.f); v.z = fmaxf(v.z, 0.f); v.w = fmaxf(v.w, 0.f); }
            *(float4*)(C + (size_t)r0 * N + n0 + (tx << 2)) = v;
        }
        if (r0 + 1 < M) {
            float4 v = make_float4(hi0 + bias4.x, hi1 + bias4.y, hi2 + bias4.z, hi3 + bias4.w);
            if (RELU) { v.x = fmaxf(v.x, 0.f); v.y = fmaxf(v.y, 0.f); v.z = fmaxf(v.z, 0.f); v.w = fmaxf(v.w, 0.f); }
            *(float4*)(C + (size_t)(r0 + 1) * N + n0 + (tx << 2)) = v;
        }
        if (ALPHA) {
            float ps0 = lo0 * sa4.x + lo1 * sa4.y + lo2 * sa4.z + lo3 * sa4.w;
            float pd0 = lo0 * sd4.x + lo1 * sd4.y + lo2 * sd4.z + lo3 * sd4.w;
            float ps1 = hi0 * sa4.x + hi1 * sa4.y + hi2 * sa4.z + hi3 * sa4.w;
            float pd1 = hi0 * sd4.x + hi1 * sd4.y + hi2 * sd4.z + hi3 * sd4.w;
            #pragma unroll
            for (int o = 1; o < 16; o <<= 1) {
                ps0 += __shfl_xor_sync(0xffffffffu, ps0, o);
                pd0 += __shfl_xor_sync(0xffffffffu, pd0, o);
                ps1 += __shfl_xor_sync(0xffffffffu, ps1, o);
                pd1 += __shfl_xor_sync(0xffffffffu, pd1, o);
            }
            if (tx == 0) {
                if (r0 < M)     { g_as[r0 * AH + by] = ps0; g_ad[r0 * AH + by] = pd0; }
                if (r0 + 1 < M) { g_as[(r0 + 1) * AH + by] = ps1; g_ad[(r0 + 1) * AH + by] = pd1; }
            }
        }
    }
}

// ---------- single-pass softmax aggregation (no max subtraction) ----------
// out[dst] = (sum_e exp(leaky(as[src]+ad[dst])) * h[src]) / sum_e exp(...) + bias
// Softmax is shift-invariant; |e| is small here (<~20), so exp never overflows.
// Optionally fuses the output MLP (H==1 case): relu(row@Wo1+bo1)@Wo2+bo2.
template<int H, bool RELU, bool FUSE_MLP>
__global__ void k_agg(const float* __restrict__ h, const float* __restrict__ bias,
                      float* __restrict__ out,
                      const float* __restrict__ Wo1, const float* __restrict__ bo1,
                      const float* __restrict__ Wo2, const float* __restrict__ bo2) {
    constexpr int HC = H * 64, EPL = HC / 32, LPH = 32 / H;
    __shared__ float sW1[FUSE_MLP ? 64 * 32 : 1];
    __shared__ float sW2[FUSE_MLP ? 32 : 1];
    __shared__ float sb1[FUSE_MLP ? 32 : 1];
    if (FUSE_MLP) {
        for (int i = threadIdx.x; i < 64 * 32; i += blockDim.x) sW1[i] = Wo1[i];
        if (threadIdx.x < 32) { sW2[threadIdx.x] = Wo2[threadIdx.x]; sb1[threadIdx.x] = bo1[threadIdx.x]; }
        __syncthreads();
    }
    const int gw = (blockIdx.x * blockDim.x + threadIdx.x) >> 5;
    const int lane = threadIdx.x & 31;
    if (gw >= NN) return;
    const int beg = g_rowptr[gw], end = g_rowptr[gw + 1];
    const int head = lane / LPH;
    const float adv = g_ad[gw * H + head];

    float ws = 0.f;
    float acc[EPL];
    #pragma unroll
    for (int k = 0; k < EPL; k++) acc[k] = 0.f;
    const float* hb = h + lane * EPL;

    for (int i = beg; i < end; i++) {
        int s = g_csrc[i];
        float e = __expf(leaky(g_as[s * H + head] + adv));
        ws += e;
        const float* hp = hb + (size_t)s * HC;
        if constexpr (EPL >= 4) {
            #pragma unroll
            for (int k = 0; k < EPL; k += 4) {
                float4 hv = *(const float4*)(hp + k);
                acc[k] += e * hv.x; acc[k + 1] += e * hv.y;
                acc[k + 2] += e * hv.z; acc[k + 3] += e * hv.w;
            }
        } else {
            float2 hv = *(const float2*)hp;
            acc[0] += e * hv.x; acc[1] += e * hv.y;
        }
    }

    const float rinv = 1.f / ws;   // deg >= 1 always (self loop)
    const float* bp = bias + lane * EPL;
    #pragma unroll
    for (int k = 0; k < EPL; k++) {
        float v = acc[k] * rinv + bp[k];
        if (RELU) v = fmaxf(v, 0.f);
        acc[k] = v;
    }

    if constexpr (FUSE_MLP) {
        // row lives across lanes: channel c on lane c>>1, component c&1 (EPL==2)
        float v0 = acc[0], v1 = acc[1];
        float hid = sb1[lane];
        #pragma unroll
        for (int k = 0; k < 32; k++) {
            float r0 = __shfl_sync(0xffffffffu, v0, k);
            float r1 = __shfl_sync(0xffffffffu, v1, k);
            hid = fmaf(r0, sW1[(2 * k) * 32 + lane], hid);
            hid = fmaf(r1, sW1[(2 * k + 1) * 32 + lane], hid);
        }
        hid = fmaxf(hid, 0.f);
        float o = hid * sW2[lane];
        #pragma unroll
        for (int w = 1; w < 32; w <<= 1) o += __shfl_xor_sync(0xffffffffu, o, w);
        if (lane == 0) out[gw] = o + bo2[0];
    } else {
        float* op = out + (size_t)gw * HC + lane * EPL;
        #pragma unroll
        for (int k = 0; k < EPL; k += 4)
            *(float4*)(op + k) = make_float4(acc[k], acc[k + 1], acc[k + 2], acc[k + 3]);
    }
}

// ---------------- launch ----------------
extern "C" void kernel_launch(void* const* d_in, const int* in_sizes, int n_in,
                              void* d_out, int out_size) {
    const float* x     = (const float*)d_in[0];
    const float* W_emb = (const float*)d_in[1];
    const float* b_emb = (const float*)d_in[2];
    const float* W0    = (const float*)d_in[3];
    const float* as0   = (const float*)d_in[4];
    const float* ad0   = (const float*)d_in[5];
    const float* b0    = (const float*)d_in[6];
    const float* W1    = (const float*)d_in[7];
    const float* as1   = (const float*)d_in[8];
    const float* ad1   = (const float*)d_in[9];
    const float* b1    = (const float*)d_in[10];
    const float* W2    = (const float*)d_in[11];
    const float* as2   = (const float*)d_in[12];
    const float* ad2   = (const float*)d_in[13];
    const float* b2    = (const float*)d_in[14];
    const float* Wo1   = (const float*)d_in[15];
    const float* bo1   = (const float*)d_in[16];
    const float* Wo2   = (const float*)d_in[17];
    const float* bo2   = (const float*)d_in[18];
    const int*   ei    = (const int*)d_in[19];
    float* out = (float*)d_out;

    float *p_h0, *p_hA, *p_hB;
    int* p_cnt;
    cudaGetSymbolAddress((void**)&p_h0, g_h0);
    cudaGetSymbolAddress((void**)&p_hA, g_hA);
    cudaGetSymbolAddress((void**)&p_hB, g_hB);
    cudaGetSymbolAddress((void**)&p_cnt, g_cnt);

    const int MB = (NN + 127) / 128;               // 391 row tiles
    const int WARP_GRID = (NN * 32 + 255) / 256;   // warp-per-node, 256-thread blocks
    const int WARP_GRID512 = (NN * 32 + 511) / 512;

    // CSR build (deterministic up to intra-node order)
    k_zero<<<(NN + 255) / 256, 256>>>(p_cnt, NN);
    k_hist<<<(ET + 255) / 256, 256>>>(ei);
    k_scan<<<1, 1024>>>();
    k_scatter<<<(ET + 255) / 256, 256>>>(ei);

    // embedding: relu(x @ W_emb + b_emb)
    k_gemm2<true, true, false, 1><<<dim3(MB, 1), 256>>>(
        x, W_emb, b_emb, nullptr, nullptr, p_h0, NN, FIN, HID);

    // GAT layer 0 (heads=4, concat, relu); alpha dots fused into GEMM epilogue
    k_gemm2<false, false, true, 4><<<dim3(MB, 4), 256>>>(
        p_h0, W0, nullptr, as0, ad0, p_hA, NN, HID, 256);
    k_agg<4, true, false><<<WARP_GRID, 256>>>(p_hA, b0, p_hB,
        nullptr, nullptr, nullptr, nullptr);

    // GAT layer 1
    k_gemm2<false, false, true, 4><<<dim3(MB, 4), 256>>>(
        p_hB, W1, nullptr, as1, ad1, p_hA, NN, 256, 256);
    k_agg<4, true, false><<<WARP_GRID, 256>>>(p_hA, b1, p_hB,
        nullptr, nullptr, nullptr, nullptr);

    // GAT layer 2 (heads=1, mean==identity, no relu) + fused output MLP
    k_gemm2<false, false, true, 1><<<dim3(MB, 1), 256>>>(
        p_hB, W2, nullptr, as2, ad2, p_hA, NN, 256, 64);
    k_agg<1, false, true><<<WARP_GRID512, 512>>>(p_hA, b2, out,
        Wo1, bo1, Wo2, bo2);
}

// round 5
// speedup vs baseline: 1.2106x; 1.0350x over previous
#include <cuda_runtime.h>

#define NN 50000
#define NE 800000
#define ET 850000            // NE + NN self loops
#define FIN 128
#define HID 64
#define HEADS 4

typedef unsigned long long ull;

// ---------------- device scratch (static allocation only) ----------------
static __device__ float g_h0[NN * HID];            // 12.8 MB
static __device__ float g_hA[NN * HEADS * HID];    // 51.2 MB
static __device__ float g_hB[NN * HEADS * HID];    // 51.2 MB
static __device__ float g_as[NN * HEADS];
static __device__ float g_ad[NN * HEADS];
static __device__ int   g_cnt[NN];
static __device__ int   g_rowptr[NN + 1];
static __device__ int   g_cursor[NN];
static __device__ int   g_csrc[ET];
static __device__ int   g_bsum[256];
static __device__ int   g_boff[256];

__device__ __forceinline__ float leaky(float v) { return v > 0.f ? v : 0.2f * v; }

// packed fp32x2 helpers (FFMA2 — only reachable via PTX on sm_103a)
__device__ __forceinline__ ull dupf(float f) {
    ull r; asm("mov.b64 %0, {%1, %1};" : "=l"(r) : "f"(f)); return r;
}
__device__ __forceinline__ void ffma2(ull& d, ull a, ull b) {
    asm("fma.rn.f32x2 %0, %1, %2, %0;" : "+l"(d) : "l"(a), "l"(b));
}
__device__ __forceinline__ float2 unpack2(ull v) {
    float2 r; asm("mov.b64 {%0, %1}, %2;" : "=f"(r.x), "=f"(r.y) : "l"(v)); return r;
}

// ---------------- CSR construction ----------------
__global__ void k_zero(int* p, int n) {
    int i = blockIdx.x * blockDim.x + threadIdx.x;
    if (i < n) p[i] = 0;
}

__global__ void k_hist(const int* __restrict__ ei) {
    int i = blockIdx.x * blockDim.x + threadIdx.x;
    if (i >= ET) return;
    int d = (i < NE) ? ei[NE + i] : (i - NE);
    atomicAdd(&g_cnt[d], 1);
}

// 3-phase parallel exclusive scan of g_cnt -> g_rowptr/g_cursor
__device__ __forceinline__ int blk_scan_excl(int v, int* total, int lane, int wid, int nw) {
    __shared__ int wsum[32];
    int x = v;
    #pragma unroll
    for (int o = 1; o < 32; o <<= 1) {
        int y = __shfl_up_sync(0xffffffffu, x, o);
        if (lane >= o) x += y;
    }
    if (lane == 31) wsum[wid] = x;
    __syncthreads();
    if (wid == 0) {
        int w = (lane < nw) ? wsum[lane] : 0;
        #pragma unroll
        for (int o = 1; o < 32; o <<= 1) {
            int y = __shfl_up_sync(0xffffffffu, w, o);
            if (lane >= o) w += y;
        }
        wsum[lane] = w;
    }
    __syncthreads();
    int base = (wid > 0) ? wsum[wid - 1] : 0;
    *total = wsum[nw - 1];
    return base + x - v;
}

__global__ void k_scan1() {  // 196 blocks x 256: per-block exclusive scan
    int tid = threadIdx.x, i = blockIdx.x * 256 + tid;
    int v = (i < NN) ? g_cnt[i] : 0;
    int total;
    int excl = blk_scan_excl(v, &total, tid & 31, tid >> 5, 8);
    if (i < NN) g_rowptr[i] = excl;
    if (tid == 0) g_bsum[blockIdx.x] = total;
}

__global__ void k_scan2(int nblk) {  // 1 block x 256: scan block sums
    int tid = threadIdx.x;
    int v = (tid < nblk) ? g_bsum[tid] : 0;
    int total;
    int excl = blk_scan_excl(v, &total, tid & 31, tid >> 5, 8);
    g_boff[tid] = excl;
    if (tid == 0) g_rowptr[NN] = total;
}

__global__ void k_scan3() {  // add block offsets
    int i = blockIdx.x * blockDim.x + threadIdx.x;
    if (i >= NN) return;
    int r = g_rowptr[i] + g_boff[i >> 8];
    g_rowptr[i] = r;
    g_cursor[i] = r;
}

__global__ void k_scatter(const int* __restrict__ ei) {
    int i = blockIdx.x * blockDim.x + threadIdx.x;
    if (i >= ET) return;
    int s, d;
    if (i < NE) { s = ei[i]; d = ei[NE + i]; }
    else        { s = i - NE; d = s; }
    int pos = atomicAdd(&g_cursor[d], 1);
    g_csrc[pos] = s;
}

// ---------------- FFMA2 SGEMM BM=128 BN=64 (8x4 microtile) ----------------
__device__ __forceinline__ void gemm_compute(const float (*As)[128], const float (*Bs)[64],
                                             ull acc[4][4], int ty, int tx) {
    #pragma unroll
    for (int k = 0; k < 16; k++) {
        const ull* ap = (const ull*)&As[k][0];
        ull a0 = ap[(ty << 2) + 0];
        ull a1 = ap[(ty << 2) + 1];
        ull a2 = ap[(ty << 2) + 2];
        ull a3 = ap[(ty << 2) + 3];
        float4 b = *(const float4*)&Bs[k][tx << 2];
        ull b0 = dupf(b.x), b1 = dupf(b.y), b2 = dupf(b.z), b3 = dupf(b.w);
        ffma2(acc[0][0], a0, b0); ffma2(acc[0][1], a0, b1); ffma2(acc[0][2], a0, b2); ffma2(acc[0][3], a0, b3);
        ffma2(acc[1][0], a1, b0); ffma2(acc[1][1], a1, b1); ffma2(acc[1][2], a1, b2); ffma2(acc[1][3], a1, b3);
        ffma2(acc[2][0], a2, b0); ffma2(acc[2][1], a2, b1); ffma2(acc[2][2], a2, b2); ffma2(acc[2][3], a2, b3);
        ffma2(acc[3][0], a3, b0); ffma2(acc[3][1], a3, b1); ffma2(acc[3][2], a3, b2); ffma2(acc[3][3], a3, b3);
    }
}

template<bool BIAS, bool RELU, bool ALPHA, int AH>
__global__ __launch_bounds__(256)
void k_gemm2(const float* __restrict__ A, const float* __restrict__ B,
             const float* __restrict__ bias,
             const float* __restrict__ a_src, const float* __restrict__ a_dst,
             float* __restrict__ C, int M, int K, int N) {
    __shared__ float As[2][16][128];
    __shared__ float Bs[2][16][64];
    const int t  = threadIdx.x;
    const int tx = t & 15, ty = t >> 4;
    const int m0 = blockIdx.x * 128;
    const int by = blockIdx.y;
    const int n0 = by * 64;

    ull acc[4][4];
    #pragma unroll
    for (int p = 0; p < 4; p++)
        #pragma unroll
        for (int j = 0; j < 4; j++) acc[p][j] = 0ull;

    const int arow = t & 127;
    const int akc  = (t >> 7) << 2;
    const bool aval = (m0 + arow) < M;
    const float* Ap = A + (size_t)(m0 + arow) * K + akc;
    const int brow = t >> 4, bcol = (t & 15) << 2;
    const float* Bp = B + (size_t)brow * N + n0 + bcol;

    const float4 fz = make_float4(0.f, 0.f, 0.f, 0.f);
    float4 pa0, pa1, pb;

    pa0 = aval ? *(const float4*)(Ap)     : fz;
    pa1 = aval ? *(const float4*)(Ap + 8) : fz;
    pb  = *(const float4*)(Bp);
    As[0][akc + 0][arow] = pa0.x; As[0][akc + 1][arow] = pa0.y;
    As[0][akc + 2][arow] = pa0.z; As[0][akc + 3][arow] = pa0.w;
    As[0][akc + 8][arow] = pa1.x; As[0][akc + 9][arow] = pa1.y;
    As[0][akc + 10][arow] = pa1.z; As[0][akc + 11][arow] = pa1.w;
    *(float4*)&Bs[0][brow][bcol] = pb;
    __syncthreads();

    int buf = 0;
    for (int k0 = 16; k0 < K; k0 += 16) {
        pa0 = aval ? *(const float4*)(Ap + k0)     : fz;
        pa1 = aval ? *(const float4*)(Ap + k0 + 8) : fz;
        pb  = *(const float4*)(Bp + (size_t)k0 * N);
        gemm_compute(As[buf], Bs[buf], acc, ty, tx);
        int nb = buf ^ 1;
        As[nb][akc + 0][arow] = pa0.x; As[nb][akc + 1][arow] = pa0.y;
        As[nb][akc + 2][arow] = pa0.z; As[nb][akc + 3][arow] = pa0.w;
        As[nb][akc + 8][arow] = pa1.x; As[nb][akc + 9][arow] = pa1.y;
        As[nb][akc + 10][arow] = pa1.z; As[nb][akc + 11][arow] = pa1.w;
        *(float4*)&Bs[nb][brow][bcol] = pb;
        __syncthreads();
        buf = nb;
    }
    gemm_compute(As[buf], Bs[buf], acc, ty, tx);

    float4 bias4 = fz;
    if (BIAS) bias4 = *(const float4*)(bias + n0 + (tx << 2));
    float4 sa4 = fz, sd4 = fz;
    if (ALPHA) {
        sa4 = *(const float4*)(a_src + n0 + (tx << 2));
        sd4 = *(const float4*)(a_dst + n0 + (tx << 2));
    }

    #pragma unroll
    for (int p = 0; p < 4; p++) {
        float2 u0 = unpack2(acc[p][0]);
        float2 u1 = unpack2(acc[p][1]);
        float2 u2 = unpack2(acc[p][2]);
        float2 u3 = unpack2(acc[p][3]);
        int r0 = m0 + (ty << 3) + (p << 1);
        float lo0 = u0.x, lo1 = u1.x, lo2 = u2.x, lo3 = u3.x;
        float hi0 = u0.y, hi1 = u1.y, hi2 = u2.y, hi3 = u3.y;

        if (r0 < M) {
            float4 v = make_float4(lo0 + bias4.x, lo1 + bias4.y, lo2 + bias4.z, lo3 + bias4.w);
            if (RELU) { v.x = fmaxf(v.x, 0.f); v.y = fmaxf(v.y, 0.f); v.z = fmaxf(v.z, 0.f); v.w = fmaxf(v.w, 0.f); }
            *(float4*)(C + (size_t)r0 * N + n0 + (tx << 2)) = v;
        }
        if (r0 + 1 < M) {
            float4 v = make_float4(hi0 + bias4.x, hi1 + bias4.y, hi2 + bias4.z, hi3 + bias4.w);
            if (RELU) { v.x = fmaxf(v.x, 0.f); v.y = fmaxf(v.y, 0.f); v.z = fmaxf(v.z, 0.f); v.w = fmaxf(v.w, 0.f); }
            *(float4*)(C + (size_t)(r0 + 1) * N + n0 + (tx << 2)) = v;
        }
        if (ALPHA) {
            float ps0 = lo0 * sa4.x + lo1 * sa4.y + lo2 * sa4.z + lo3 * sa4.w;
            float pd0 = lo0 * sd4.x + lo1 * sd4.y + lo2 * sd4.z + lo3 * sd4.w;
            float ps1 = hi0 * sa4.x + hi1 * sa4.y + hi2 * sa4.z + hi3 * sa4.w;
            float pd1 = hi0 * sd4.x + hi1 * sd4.y + hi2 * sd4.z + hi3 * sd4.w;
            #pragma unroll
            for (int o = 1; o < 16; o <<= 1) {
                ps0 += __shfl_xor_sync(0xffffffffu, ps0, o);
                pd0 += __shfl_xor_sync(0xffffffffu, pd0, o);
                ps1 += __shfl_xor_sync(0xffffffffu, ps1, o);
                pd1 += __shfl_xor_sync(0xffffffffu, pd1, o);
            }
            if (tx == 0) {
                if (r0 < M)     { g_as[r0 * AH + by] = ps0; g_ad[r0 * AH + by] = pd0; }
                if (r0 + 1 < M) { g_as[(r0 + 1) * AH + by] = ps1; g_ad[(r0 + 1) * AH + by] = pd1; }
            }
        }
    }
}

// ---------------- FFMA2 SGEMM BM=128 BN=128 (8x8 microtile) ----------------
// For N multiple of 128. ALPHA fused (AH heads, 64 cols per head -> head = by*2 + (tx>=8)).
template<int AH>
__global__ __launch_bounds__(256, 2)
void k_gemm8(const float* __restrict__ A, const float* __restrict__ B,
             const float* __restrict__ a_src, const float* __restrict__ a_dst,
             float* __restrict__ C, int M, int K, int N) {
    __shared__ float As[2][16][128];
    __shared__ float Bs[2][16][128];
    const int t  = threadIdx.x;
    const int tx = t & 15, ty = t >> 4;
    const int m0 = blockIdx.x * 128;
    const int by = blockIdx.y;
    const int n0 = by * 128;

    ull acc[4][8];
    #pragma unroll
    for (int p = 0; p < 4; p++)
        #pragma unroll
        for (int j = 0; j < 8; j++) acc[p][j] = 0ull;

    const int arow = t & 127;
    const int akc  = (t >> 7) << 3;      // 0 or 8
    const bool aval = (m0 + arow) < M;
    const float* Ap = A + (size_t)(m0 + arow) * K + akc;
    const int brow = t >> 4, bcol = (t & 15) << 3;
    const float* Bp = B + (size_t)brow * N + n0 + bcol;

    const float4 fz = make_float4(0.f, 0.f, 0.f, 0.f);
    float4 pa0, pa1, pb0, pb1;

    pa0 = aval ? *(const float4*)(Ap)     : fz;
    pa1 = aval ? *(const float4*)(Ap + 4) : fz;
    pb0 = *(const float4*)(Bp);
    pb1 = *(const float4*)(Bp + 4);
    As[0][akc + 0][arow] = pa0.x; As[0][akc + 1][arow] = pa0.y;
    As[0][akc + 2][arow] = pa0.z; As[0][akc + 3][arow] = pa0.w;
    As[0][akc + 4][arow] = pa1.x; As[0][akc + 5][arow] = pa1.y;
    As[0][akc + 6][arow] = pa1.z; As[0][akc + 7][arow] = pa1.w;
    *(float4*)&Bs[0][brow][bcol] = pb0;
    *(float4*)&Bs[0][brow][bcol + 4] = pb1;
    __syncthreads();

    int buf = 0;
    for (int k0 = 16; k0 < K; k0 += 16) {
        pa0 = aval ? *(const float4*)(Ap + k0)     : fz;
        pa1 = aval ? *(const float4*)(Ap + k0 + 4) : fz;
        pb0 = *(const float4*)(Bp + (size_t)k0 * N);
        pb1 = *(const float4*)(Bp + (size_t)k0 * N + 4);
        #pragma unroll
        for (int k = 0; k < 16; k++) {
            const ull* ap = (const ull*)&As[buf][k][0];
            ull a0 = ap[(ty << 2) + 0];
            ull a1 = ap[(ty << 2) + 1];
            ull a2 = ap[(ty << 2) + 2];
            ull a3 = ap[(ty << 2) + 3];
            float4 bv0 = *(const float4*)&Bs[buf][k][tx << 3];
            float4 bv1 = *(const float4*)&Bs[buf][k][(tx << 3) + 4];
            ull b0 = dupf(bv0.x), b1 = dupf(bv0.y), b2 = dupf(bv0.z), b3 = dupf(bv0.w);
            ull b4 = dupf(bv1.x), b5 = dupf(bv1.y), b6 = dupf(bv1.z), b7 = dupf(bv1.w);
            ffma2(acc[0][0], a0, b0); ffma2(acc[0][1], a0, b1); ffma2(acc[0][2], a0, b2); ffma2(acc[0][3], a0, b3);
            ffma2(acc[0][4], a0, b4); ffma2(acc[0][5], a0, b5); ffma2(acc[0][6], a0, b6); ffma2(acc[0][7], a0, b7);
            ffma2(acc[1][0], a1, b0); ffma2(acc[1][1], a1, b1); ffma2(acc[1][2], a1, b2); ffma2(acc[1][3], a1, b3);
            ffma2(acc[1][4], a1, b4); ffma2(acc[1][5], a1, b5); ffma2(acc[1][6], a1, b6); ffma2(acc[1][7], a1, b7);
            ffma2(acc[2][0], a2, b0); ffma2(acc[2][1], a2, b1); ffma2(acc[2][2], a2, b2); ffma2(acc[2][3], a2, b3);
            ffma2(acc[2][4], a2, b4); ffma2(acc[2][5], a2, b5); ffma2(acc[2][6], a2, b6); ffma2(acc[2][7], a2, b7);
            ffma2(acc[3][0], a3, b0); ffma2(acc[3][1], a3, b1); ffma2(acc[3][2], a3, b2); ffma2(acc[3][3], a3, b3);
            ffma2(acc[3][4], a3, b4); ffma2(acc[3][5], a3, b5); ffma2(acc[3][6], a3, b6); ffma2(acc[3][7], a3, b7);
        }
        int nb = buf ^ 1;
        As[nb][akc + 0][arow] = pa0.x; As[nb][akc + 1][arow] = pa0.y;
        As[nb][akc + 2][arow] = pa0.z; As[nb][akc + 3][arow] = pa0.w;
        As[nb][akc + 4][arow] = pa1.x; As[nb][akc + 5][arow] = pa1.y;
        As[nb][akc + 6][arow] = pa1.z; As[nb][akc + 7][arow] = pa1.w;
        *(float4*)&Bs[nb][brow][bcol] = pb0;
        *(float4*)&Bs[nb][brow][bcol + 4] = pb1;
        __syncthreads();
        buf = nb;
    }
    #pragma unroll
    for (int k = 0; k < 16; k++) {
        const ull* ap = (const ull*)&As[buf][k][0];
        ull a0 = ap[(ty << 2) + 0];
        ull a1 = ap[(ty << 2) + 1];
        ull a2 = ap[(ty << 2) + 2];
        ull a3 = ap[(ty << 2) + 3];
        float4 bv0 = *(const float4*)&Bs[buf][k][tx << 3];
        float4 bv1 = *(const float4*)&Bs[buf][k][(tx << 3) + 4];
        ull b0 = dupf(bv0.x), b1 = dupf(bv0.y), b2 = dupf(bv0.z), b3 = dupf(bv0.w);
        ull b4 = dupf(bv1.x), b5 = dupf(bv1.y), b6 = dupf(bv1.z), b7 = dupf(bv1.w);
        ffma2(acc[0][0], a0, b0); ffma2(acc[0][1], a0, b1); ffma2(acc[0][2], a0, b2); ffma2(acc[0][3], a0, b3);
        ffma2(acc[0][4], a0, b4); ffma2(acc[0][5], a0, b5); ffma2(acc[0][6], a0, b6); ffma2(acc[0][7], a0, b7);
        ffma2(acc[1][0], a1, b0); ffma2(acc[1][1], a1, b1); ffma2(acc[1][2], a1, b2); ffma2(acc[1][3], a1, b3);
        ffma2(acc[1][4], a1, b4); ffma2(acc[1][5], a1, b5); ffma2(acc[1][6], a1, b6); ffma2(acc[1][7], a1, b7);
        ffma2(acc[2][0], a2, b0); ffma2(acc[2][1], a2, b1); ffma2(acc[2][2], a2, b2); ffma2(acc[2][3], a2, b3);
        ffma2(acc[2][4], a2, b4); ffma2(acc[2][5], a2, b5); ffma2(acc[2][6], a2, b6); ffma2(acc[2][7], a2, b7);
        ffma2(acc[3][0], a3, b0); ffma2(acc[3][1], a3, b1); ffma2(acc[3][2], a3, b2); ffma2(acc[3][3], a3, b3);
        ffma2(acc[3][4], a3, b4); ffma2(acc[3][5], a3, b5); ffma2(acc[3][6], a3, b6); ffma2(acc[3][7], a3, b7);
    }

    float4 sa0 = *(const float4*)(a_src + n0 + (tx << 3));
    float4 sa1 = *(const float4*)(a_src + n0 + (tx << 3) + 4);
    float4 sd0 = *(const float4*)(a_dst + n0 + (tx << 3));
    float4 sd1 = *(const float4*)(a_dst + n0 + (tx << 3) + 4);
    const int head = by * 2 + (tx >> 3);

    #pragma unroll
    for (int p = 0; p < 4; p++) {
        float lo[8], hi[8];
        #pragma unroll
        for (int j = 0; j < 8; j++) {
            float2 u = unpack2(acc[p][j]);
            lo[j] = u.x; hi[j] = u.y;
        }
        int r0 = m0 + (ty << 3) + (p << 1);
        if (r0 < M) {
            *(float4*)(C + (size_t)r0 * N + n0 + (tx << 3))     = make_float4(lo[0], lo[1], lo[2], lo[3]);
            *(float4*)(C + (size_t)r0 * N + n0 + (tx << 3) + 4) = make_float4(lo[4], lo[5], lo[6], lo[7]);
        }
        if (r0 + 1 < M) {
            *(float4*)(C + (size_t)(r0 + 1) * N + n0 + (tx << 3))     = make_float4(hi[0], hi[1], hi[2], hi[3]);
            *(float4*)(C + (size_t)(r0 + 1) * N + n0 + (tx << 3) + 4) = make_float4(hi[4], hi[5], hi[6], hi[7]);
        }
        float ps0 = lo[0]*sa0.x + lo[1]*sa0.y + lo[2]*sa0.z + lo[3]*sa0.w
                  + lo[4]*sa1.x + lo[5]*sa1.y + lo[6]*sa1.z + lo[7]*sa1.w;
        float pd0 = lo[0]*sd0.x + lo[1]*sd0.y + lo[2]*sd0.z + lo[3]*sd0.w
                  + lo[4]*sd1.x + lo[5]*sd1.y + lo[6]*sd1.z + lo[7]*sd1.w;
        float ps1 = hi[0]*sa0.x + hi[1]*sa0.y + hi[2]*sa0.z + hi[3]*sa0.w
                  + hi[4]*sa1.x + hi[5]*sa1.y + hi[6]*sa1.z + hi[7]*sa1.w;
        float pd1 = hi[0]*sd0.x + hi[1]*sd0.y + hi[2]*sd0.z + hi[3]*sd0.w
                  + hi[4]*sd1.x + hi[5]*sd1.y + hi[6]*sd1.z + hi[7]*sd1.w;
        #pragma unroll
        for (int o = 1; o < 8; o <<= 1) {
            ps0 += __shfl_xor_sync(0xffffffffu, ps0, o);
            pd0 += __shfl_xor_sync(0xffffffffu, pd0, o);
            ps1 += __shfl_xor_sync(0xffffffffu, ps1, o);
            pd1 += __shfl_xor_sync(0xffffffffu, pd1, o);
        }
        if ((tx & 7) == 0) {
            if (r0 < M)     { g_as[r0 * AH + head] = ps0; g_ad[r0 * AH + head] = pd0; }
            if (r0 + 1 < M) { g_as[(r0 + 1) * AH + head] = ps1; g_ad[(r0 + 1) * AH + head] = pd1; }
        }
    }
}

// ---------- single-pass softmax aggregation (no max subtraction) ----------
template<int H, bool RELU, bool FUSE_MLP>
__global__ void k_agg(const float* __restrict__ h, const float* __restrict__ bias,
                      float* __restrict__ out,
                      const float* __restrict__ Wo1, const float* __restrict__ bo1,
                      const float* __restrict__ Wo2, const float* __restrict__ bo2) {
    constexpr int HC = H * 64, EPL = HC / 32, LPH = 32 / H;
    __shared__ float sW1[FUSE_MLP ? 64 * 32 : 1];
    __shared__ float sW2[FUSE_MLP ? 32 : 1];
    __shared__ float sb1[FUSE_MLP ? 32 : 1];
    if (FUSE_MLP) {
        for (int i = threadIdx.x; i < 64 * 32; i += blockDim.x) sW1[i] = Wo1[i];
        if (threadIdx.x < 32) { sW2[threadIdx.x] = Wo2[threadIdx.x]; sb1[threadIdx.x] = bo1[threadIdx.x]; }
        __syncthreads();
    }
    const int gw = (blockIdx.x * blockDim.x + threadIdx.x) >> 5;
    const int lane = threadIdx.x & 31;
    if (gw >= NN) return;
    const int beg = g_rowptr[gw], end = g_rowptr[gw + 1];
    const int head = lane / LPH;
    const float adv = g_ad[gw * H + head];

    float ws = 0.f;
    float acc[EPL];
    #pragma unroll
    for (int k = 0; k < EPL; k++) acc[k] = 0.f;
    const float* hb = h + lane * EPL;

    int i = beg;
    for (; i + 2 <= end; i += 2) {
        int s0 = g_csrc[i], s1 = g_csrc[i + 1];
        float a0 = g_as[s0 * H + head];
        float a1 = g_as[s1 * H + head];
        const float* hp0 = hb + (size_t)s0 * HC;
        const float* hp1 = hb + (size_t)s1 * HC;
        float e0 = __expf(leaky(a0 + adv));
        float e1 = __expf(leaky(a1 + adv));
        ws += e0 + e1;
        if constexpr (EPL >= 4) {
            #pragma unroll
            for (int k = 0; k < EPL; k += 4) {
                float4 v0 = *(const float4*)(hp0 + k);
                float4 v1 = *(const float4*)(hp1 + k);
                acc[k]     += e0 * v0.x + e1 * v1.x;
                acc[k + 1] += e0 * v0.y + e1 * v1.y;
                acc[k + 2] += e0 * v0.z + e1 * v1.z;
                acc[k + 3] += e0 * v0.w + e1 * v1.w;
            }
        } else {
            float2 v0 = *(const float2*)hp0;
            float2 v1 = *(const float2*)hp1;
            acc[0] += e0 * v0.x + e1 * v1.x;
            acc[1] += e0 * v0.y + e1 * v1.y;
        }
    }
    if (i < end) {
        int s = g_csrc[i];
        float e = __expf(leaky(g_as[s * H + head] + adv));
        ws += e;
        const float* hp = hb + (size_t)s * HC;
        if constexpr (EPL >= 4) {
            #pragma unroll
            for (int k = 0; k < EPL; k += 4) {
                float4 hv = *(const float4*)(hp + k);
                acc[k] += e * hv.x; acc[k + 1] += e * hv.y;
                acc[k + 2] += e * hv.z; acc[k + 3] += e * hv.w;
            }
        } else {
            float2 hv = *(const float2*)hp;
            acc[0] += e * hv.x; acc[1] += e * hv.y;
        }
    }

    const float rinv = 1.f / ws;
    const float* bp = bias + lane * EPL;
    #pragma unroll
    for (int k = 0; k < EPL; k++) {
        float v = acc[k] * rinv + bp[k];
        if (RELU) v = fmaxf(v, 0.f);
        acc[k] = v;
    }

    if constexpr (FUSE_MLP) {
        float v0 = acc[0], v1 = acc[1];
        float hid = sb1[lane];
        #pragma unroll
        for (int k = 0; k < 32; k++) {
            float r0 = __shfl_sync(0xffffffffu, v0, k);
            float r1 = __shfl_sync(0xffffffffu, v1, k);
            hid = fmaf(r0, sW1[(2 * k) * 32 + lane], hid);
            hid = fmaf(r1, sW1[(2 * k + 1) * 32 + lane], hid);
        }
        hid = fmaxf(hid, 0.f);
        float o = hid * sW2[lane];
        #pragma unroll
        for (int w = 1; w < 32; w <<= 1) o += __shfl_xor_sync(0xffffffffu, o, w);
        if (lane == 0) out[gw] = o + bo2[0];
    } else {
        float* op = out + (size_t)gw * HC + lane * EPL;
        #pragma unroll
        for (int k = 0; k < EPL; k += 4)
            *(float4*)(op + k) = make_float4(acc[k], acc[k + 1], acc[k + 2], acc[k + 3]);
    }
}

// ---------------- launch ----------------
extern "C" void kernel_launch(void* const* d_in, const int* in_sizes, int n_in,
                              void* d_out, int out_size) {
    const float* x     = (const float*)d_in[0];
    const float* W_emb = (const float*)d_in[1];
    const float* b_emb = (const float*)d_in[2];
    const float* W0    = (const float*)d_in[3];
    const float* as0   = (const float*)d_in[4];
    const float* ad0   = (const float*)d_in[5];
    const float* b0    = (const float*)d_in[6];
    const float* W1    = (const float*)d_in[7];
    const float* as1   = (const float*)d_in[8];
    const float* ad1   = (const float*)d_in[9];
    const float* b1    = (const float*)d_in[10];
    const float* W2    = (const float*)d_in[11];
    const float* as2   = (const float*)d_in[12];
    const float* ad2   = (const float*)d_in[13];
    const float* b2    = (const float*)d_in[14];
    const float* Wo1   = (const float*)d_in[15];
    const float* bo1   = (const float*)d_in[16];
    const float* Wo2   = (const float*)d_in[17];
    const float* bo2   = (const float*)d_in[18];
    const int*   ei    = (const int*)d_in[19];
    float* out = (float*)d_out;

    float *p_h0, *p_hA, *p_hB;
    int* p_cnt;
    cudaGetSymbolAddress((void**)&p_h0, g_h0);
    cudaGetSymbolAddress((void**)&p_hA, g_hA);
    cudaGetSymbolAddress((void**)&p_hB, g_hB);
    cudaGetSymbolAddress((void**)&p_cnt, g_cnt);

    const int MB = (NN + 127) / 128;               // 391 row tiles
    const int SCAN_BLK = (NN + 255) / 256;         // 196
    const int WARP_GRID = (NN * 32 + 255) / 256;
    const int WARP_GRID512 = (NN * 32 + 511) / 512;

    // CSR build (parallel scan)
    k_zero<<<(NN + 255) / 256, 256>>>(p_cnt, NN);
    k_hist<<<(ET + 255) / 256, 256>>>(ei);
    k_scan1<<<SCAN_BLK, 256>>>();
    k_scan2<<<1, 256>>>(SCAN_BLK);
    k_scan3<<<SCAN_BLK, 256>>>();
    k_scatter<<<(ET + 255) / 256, 256>>>(ei);

    // embedding: relu(x @ W_emb + b_emb)
    k_gemm2<true, true, false, 1><<<dim3(MB, 1), 256>>>(
        x, W_emb, b_emb, nullptr, nullptr, p_h0, NN, FIN, HID);

    // GAT layer 0 (heads=4, concat, relu); alpha dots fused into GEMM epilogue
    k_gemm8<4><<<dim3(MB, 2), 256>>>(p_h0, W0, as0, ad0, p_hA, NN, HID, 256);
    k_agg<4, true, false><<<WARP_GRID, 256>>>(p_hA, b0, p_hB,
        nullptr, nullptr, nullptr, nullptr);

    // GAT layer 1
    k_gemm8<4><<<dim3(MB, 2), 256>>>(p_hB, W1, as1, ad1, p_hA, NN, 256, 256);
    k_agg<4, true, false><<<WARP_GRID, 256>>>(p_hA, b1, p_hB,
        nullptr, nullptr, nullptr, nullptr);

    // GAT layer 2 (heads=1, mean==identity, no relu) + fused output MLP
    k_gemm2<false, false, true, 1><<<dim3(MB, 1), 256>>>(
        p_hB, W2, nullptr, as2, ad2, p_hA, NN, 256, 64);
    k_agg<1, false, true><<<WARP_GRID512, 512>>>(p_hA, b2, out,
        Wo1, bo1, Wo2, bo2);
}

// round 7
// speedup vs baseline: 1.5163x; 1.2525x over previous
#include <cuda_runtime.h>
#include <cstdint>

#define NN 50000
#define NE 800000
#define ET 850000            // NE + NN self loops
#define FIN 128
#define HID 64
#define HEADS 4

typedef unsigned long long ull;

// ---------------- device scratch (static allocation only) ----------------
static __device__ float g_h0[NN * HID];            // 12.8 MB
static __device__ float g_hA[NN * HEADS * HID];    // 51.2 MB
static __device__ float g_hB[NN * HEADS * HID];    // 51.2 MB
static __device__ float g_as[NN * HEADS];
static __device__ float g_ad[NN * HEADS];
static __device__ int   g_cnt[NN];
static __device__ int   g_rowptr[NN + 1];
static __device__ int   g_cursor[NN];
static __device__ int   g_csrc[ET];
static __device__ int   g_bsum[256];
static __device__ int   g_boff[256];

__device__ __forceinline__ float leaky(float v) { return v > 0.f ? v : 0.2f * v; }

// packed fp32x2 helpers (FFMA2 — only reachable via PTX on sm_103a)
__device__ __forceinline__ ull dupf(float f) {
    ull r; asm("mov.b64 %0, {%1, %1};" : "=l"(r) : "f"(f)); return r;
}
__device__ __forceinline__ void ffma2(ull& d, ull a, ull b) {
    asm("fma.rn.f32x2 %0, %1, %2, %0;" : "+l"(d) : "l"(a), "l"(b));
}
__device__ __forceinline__ float2 unpack2(ull v) {
    float2 r; asm("mov.b64 {%0, %1}, %2;" : "=f"(r.x), "=f"(r.y) : "l"(v)); return r;
}
__device__ __forceinline__ uint32_t cvt_tf32(float f) {
    uint32_t r; asm("cvt.rna.tf32.f32 %0, %1;" : "=r"(r) : "f"(f)); return r;
}

// ---------------- CSR construction ----------------
__global__ void k_zero(int* p, int n) {
    int i = blockIdx.x * blockDim.x + threadIdx.x;
    if (i < n) p[i] = 0;
}

__global__ void k_hist(const int* __restrict__ ei) {
    int i = blockIdx.x * blockDim.x + threadIdx.x;
    if (i >= ET) return;
    int d = (i < NE) ? ei[NE + i] : (i - NE);
    atomicAdd(&g_cnt[d], 1);
}

__device__ __forceinline__ int blk_scan_excl(int v, int* total, int lane, int wid, int nw) {
    __shared__ int wsum[32];
    int x = v;
    #pragma unroll
    for (int o = 1; o < 32; o <<= 1) {
        int y = __shfl_up_sync(0xffffffffu, x, o);
        if (lane >= o) x += y;
    }
    if (lane == 31) wsum[wid] = x;
    __syncthreads();
    if (wid == 0) {
        int w = (lane < nw) ? wsum[lane] : 0;
        #pragma unroll
        for (int o = 1; o < 32; o <<= 1) {
            int y = __shfl_up_sync(0xffffffffu, w, o);
            if (lane >= o) w += y;
        }
        wsum[lane] = w;
    }
    __syncthreads();
    int base = (wid > 0) ? wsum[wid - 1] : 0;
    *total = wsum[nw - 1];
    return base + x - v;
}

__global__ void k_scan1() {
    int tid = threadIdx.x, i = blockIdx.x * 256 + tid;
    int v = (i < NN) ? g_cnt[i] : 0;
    int total;
    int excl = blk_scan_excl(v, &total, tid & 31, tid >> 5, 8);
    if (i < NN) g_rowptr[i] = excl;
    if (tid == 0) g_bsum[blockIdx.x] = total;
}

__global__ void k_scan2(int nblk) {
    int tid = threadIdx.x;
    int v = (tid < nblk) ? g_bsum[tid] : 0;
    int total;
    int excl = blk_scan_excl(v, &total, tid & 31, tid >> 5, 8);
    g_boff[tid] = excl;
    if (tid == 0) g_rowptr[NN] = total;
}

__global__ void k_scan3() {
    int i = blockIdx.x * blockDim.x + threadIdx.x;
    if (i >= NN) return;
    int r = g_rowptr[i] + g_boff[i >> 8];
    g_rowptr[i] = r;
    g_cursor[i] = r;
}

__global__ void k_scatter(const int* __restrict__ ei) {
    int i = blockIdx.x * blockDim.x + threadIdx.x;
    if (i >= ET) return;
    int s, d;
    if (i < NE) { s = ei[i]; d = ei[NE + i]; }
    else        { s = i - NE; d = s; }
    int pos = atomicAdd(&g_cursor[d], 1);
    g_csrc[pos] = s;
}

// ============ tf32 mma.sync GEMM: C[M,256] = A[M,K] @ W[K,256] =============
// 128x128 block, 8 warps (2x4), warp tile 64x32 via 4x4 m16n8k8 MMAs,
// BK=16 double-buffered static smem. Strides chosen conflict-free:
//   As[m][20] (a-frag banks: g*4+tig distinct), Bs[k][136] (tig*8+g distinct).
#define AST 20
#define BST 136

__device__ __forceinline__ void mma_tf32(float c[4], const uint32_t a[4], const uint32_t b[2]) {
    asm volatile(
        "mma.sync.aligned.m16n8k8.row.col.f32.tf32.tf32.f32 "
        "{%0,%1,%2,%3}, {%4,%5,%6,%7}, {%8,%9}, {%0,%1,%2,%3};"
        : "+f"(c[0]), "+f"(c[1]), "+f"(c[2]), "+f"(c[3])
        : "r"(a[0]), "r"(a[1]), "r"(a[2]), "r"(a[3]), "r"(b[0]), "r"(b[1]));
}

__global__ __launch_bounds__(256)
void k_gemm_mma(const float* __restrict__ A, const float* __restrict__ W,
                float* __restrict__ C, int M, int K) {
    __shared__ uint32_t As[2][128 * AST];
    __shared__ uint32_t Bs[2][16 * BST];
    const int tid = threadIdx.x;
    const int wid = tid >> 5, lane = tid & 31;
    const int g = lane >> 2, tig = lane & 3;
    const int warp_m = (wid >> 2) << 6;     // 0 or 64
    const int warp_n = (wid & 3) << 5;      // 0,32,64,96
    const int m0 = blockIdx.x * 128;
    const int n0 = blockIdx.y * 128;
    const int N = 256;

    float acc[4][4][4];
    #pragma unroll
    for (int mt = 0; mt < 4; mt++)
        #pragma unroll
        for (int nt = 0; nt < 4; nt++)
            #pragma unroll
            for (int q = 0; q < 4; q++) acc[mt][nt][q] = 0.f;

    // global load mapping
    const int ar = tid >> 1, akh = (tid & 1) << 3;        // row, k-half (0/8)
    const bool av = (m0 + ar) < M;
    const float* Ap = A + (size_t)(m0 + ar) * K + akh;
    const int bk = tid >> 4, bn = (tid & 15) << 3;        // k-row, n-base
    const float* Wp = W + (size_t)bk * N + n0 + bn;

    const float4 fz = make_float4(0.f, 0.f, 0.f, 0.f);
    float4 ra0, ra1, rb0, rb1;

    // prologue: chunk 0 -> buf 0
    ra0 = av ? *(const float4*)(Ap)     : fz;
    ra1 = av ? *(const float4*)(Ap + 4) : fz;
    rb0 = *(const float4*)(Wp);
    rb1 = *(const float4*)(Wp + 4);
    *(uint4*)&As[0][ar * AST + akh]     = make_uint4(cvt_tf32(ra0.x), cvt_tf32(ra0.y), cvt_tf32(ra0.z), cvt_tf32(ra0.w));
    *(uint4*)&As[0][ar * AST + akh + 4] = make_uint4(cvt_tf32(ra1.x), cvt_tf32(ra1.y), cvt_tf32(ra1.z), cvt_tf32(ra1.w));
    *(uint4*)&Bs[0][bk * BST + bn]      = make_uint4(cvt_tf32(rb0.x), cvt_tf32(rb0.y), cvt_tf32(rb0.z), cvt_tf32(rb0.w));
    *(uint4*)&Bs[0][bk * BST + bn + 4]  = make_uint4(cvt_tf32(rb1.x), cvt_tf32(rb1.y), cvt_tf32(rb1.z), cvt_tf32(rb1.w));
    __syncthreads();

    const int nch = K >> 4;
    int buf = 0;
    for (int c = 1; c <= nch; c++) {
        if (c < nch) {
            const int k0 = c << 4;
            ra0 = av ? *(const float4*)(Ap + k0)     : fz;
            ra1 = av ? *(const float4*)(Ap + k0 + 4) : fz;
            rb0 = *(const float4*)(Wp + (size_t)k0 * N);
            rb1 = *(const float4*)(Wp + (size_t)k0 * N + 4);
        }
        // compute current buffer: 2 k-steps of 8
        #pragma unroll
        for (int ks = 0; ks < 2; ks++) {
            const int kc = ks << 3;
            uint32_t a[4][4], b[4][2];
            #pragma unroll
            for (int mt = 0; mt < 4; mt++) {
                int mr = warp_m + (mt << 4) + g;
                a[mt][0] = As[buf][mr * AST + kc + tig];
                a[mt][1] = As[buf][(mr + 8) * AST + kc + tig];
                a[mt][2] = As[buf][mr * AST + kc + tig + 4];
                a[mt][3] = As[buf][(mr + 8) * AST + kc + tig + 4];
            }
            #pragma unroll
            for (int nt = 0; nt < 4; nt++) {
                int nc = warp_n + (nt << 3) + g;
                b[nt][0] = Bs[buf][(kc + tig) * BST + nc];
                b[nt][1] = Bs[buf][(kc + tig + 4) * BST + nc];
            }
            #pragma unroll
            for (int mt = 0; mt < 4; mt++)
                #pragma unroll
                for (int nt = 0; nt < 4; nt++)
                    mma_tf32(acc[mt][nt], a[mt], b[nt]);
        }
        if (c < nch) {
            int nb = buf ^ 1;
            *(uint4*)&As[nb][ar * AST + akh]     = make_uint4(cvt_tf32(ra0.x), cvt_tf32(ra0.y), cvt_tf32(ra0.z), cvt_tf32(ra0.w));
            *(uint4*)&As[nb][ar * AST + akh + 4] = make_uint4(cvt_tf32(ra1.x), cvt_tf32(ra1.y), cvt_tf32(ra1.z), cvt_tf32(ra1.w));
            *(uint4*)&Bs[nb][bk * BST + bn]      = make_uint4(cvt_tf32(rb0.x), cvt_tf32(rb0.y), cvt_tf32(rb0.z), cvt_tf32(rb0.w));
            *(uint4*)&Bs[nb][bk * BST + bn + 4]  = make_uint4(cvt_tf32(rb1.x), cvt_tf32(rb1.y), cvt_tf32(rb1.z), cvt_tf32(rb1.w));
            __syncthreads();
            buf = nb;
        }
    }

    // epilogue: c0,c1 -> (row g, cols tig*2,+1); c2,c3 -> (row g+8)
    #pragma unroll
    for (int mt = 0; mt < 4; mt++) {
        int r0 = m0 + warp_m + (mt << 4) + g;
        int r1 = r0 + 8;
        #pragma unroll
        for (int nt = 0; nt < 4; nt++) {
            int col = n0 + warp_n + (nt << 3) + (tig << 1);
            if (r0 < M) *(float2*)(C + (size_t)r0 * N + col) = make_float2(acc[mt][nt][0], acc[mt][nt][1]);
            if (r1 < M) *(float2*)(C + (size_t)r1 * N + col) = make_float2(acc[mt][nt][2], acc[mt][nt][3]);
        }
    }
}

// ---------------- per-node attention dots (H=4) ----------------
// warp per node; lane owns channels [lane*8, lane*8+8), all same head.
__global__ void k_alpha4(const float* __restrict__ h, const float* __restrict__ a_s,
                         const float* __restrict__ a_d) {
    int gw = (blockIdx.x * blockDim.x + threadIdx.x) >> 5;
    int lane = threadIdx.x & 31;
    if (gw >= NN) return;
    const float* row = h + (size_t)gw * 256 + lane * 8;
    const float* asp = a_s + lane * 8;
    const float* adp = a_d + lane * 8;
    float ps = 0.f, pd = 0.f;
    #pragma unroll
    for (int k = 0; k < 8; k += 4) {
        float4 hv = *(const float4*)(row + k);
        float4 sv = *(const float4*)(asp + k);
        float4 dv = *(const float4*)(adp + k);
        ps += hv.x * sv.x + hv.y * sv.y + hv.z * sv.z + hv.w * sv.w;
        pd += hv.x * dv.x + hv.y * dv.y + hv.z * dv.z + hv.w * dv.w;
    }
    #pragma unroll
    for (int o = 1; o < 8; o <<= 1) {
        ps += __shfl_xor_sync(0xffffffffu, ps, o);
        pd += __shfl_xor_sync(0xffffffffu, pd, o);
    }
    if ((lane & 7) == 0) {
        int head = lane >> 3;
        g_as[gw * 4 + head] = ps;
        g_ad[gw * 4 + head] = pd;
    }
}

// ---------------- FFMA2 SGEMM BM=128 BN=64 (emb + layer-2) -----------------
__device__ __forceinline__ void gemm_compute(const float (*As)[128], const float (*Bs)[64],
                                             ull acc[4][4], int ty, int tx) {
    #pragma unroll
    for (int k = 0; k < 16; k++) {
        const ull* ap = (const ull*)&As[k][0];
        ull a0 = ap[(ty << 2) + 0];
        ull a1 = ap[(ty << 2) + 1];
        ull a2 = ap[(ty << 2) + 2];
        ull a3 = ap[(ty << 2) + 3];
        float4 b = *(const float4*)&Bs[k][tx << 2];
        ull b0 = dupf(b.x), b1 = dupf(b.y), b2 = dupf(b.z), b3 = dupf(b.w);
        ffma2(acc[0][0], a0, b0); ffma2(acc[0][1], a0, b1); ffma2(acc[0][2], a0, b2); ffma2(acc[0][3], a0, b3);
        ffma2(acc[1][0], a1, b0); ffma2(acc[1][1], a1, b1); ffma2(acc[1][2], a1, b2); ffma2(acc[1][3], a1, b3);
        ffma2(acc[2][0], a2, b0); ffma2(acc[2][1], a2, b1); ffma2(acc[2][2], a2, b2); ffma2(acc[2][3], a2, b3);
        ffma2(acc[3][0], a3, b0); ffma2(acc[3][1], a3, b1); ffma2(acc[3][2], a3, b2); ffma2(acc[3][3], a3, b3);
    }
}

template<bool BIAS, bool RELU, bool ALPHA, int AH>
__global__ __launch_bounds__(256)
void k_gemm2(const float* __restrict__ A, const float* __restrict__ B,
             const float* __restrict__ bias,
             const float* __restrict__ a_src, const float* __restrict__ a_dst,
             float* __restrict__ C, int M, int K, int N) {
    __shared__ float As[2][16][128];
    __shared__ float Bs[2][16][64];
    const int t  = threadIdx.x;
    const int tx = t & 15, ty = t >> 4;
    const int m0 = blockIdx.x * 128;
    const int by = blockIdx.y;
    const int n0 = by * 64;

    ull acc[4][4];
    #pragma unroll
    for (int p = 0; p < 4; p++)
        #pragma unroll
        for (int j = 0; j < 4; j++) acc[p][j] = 0ull;

    const int arow = t & 127;
    const int akc  = (t >> 7) << 2;
    const bool aval = (m0 + arow) < M;
    const float* Ap = A + (size_t)(m0 + arow) * K + akc;
    const int brow = t >> 4, bcol = (t & 15) << 2;
    const float* Bp = B + (size_t)brow * N + n0 + bcol;

    const float4 fz = make_float4(0.f, 0.f, 0.f, 0.f);
    float4 pa0, pa1, pb;

    pa0 = aval ? *(const float4*)(Ap)     : fz;
    pa1 = aval ? *(const float4*)(Ap + 8) : fz;
    pb  = *(const float4*)(Bp);
    As[0][akc + 0][arow] = pa0.x; As[0][akc + 1][arow] = pa0.y;
    As[0][akc + 2][arow] = pa0.z; As[0][akc + 3][arow] = pa0.w;
    As[0][akc + 8][arow] = pa1.x; As[0][akc + 9][arow] = pa1.y;
    As[0][akc + 10][arow] = pa1.z; As[0][akc + 11][arow] = pa1.w;
    *(float4*)&Bs[0][brow][bcol] = pb;
    __syncthreads();

    int buf = 0;
    for (int k0 = 16; k0 < K; k0 += 16) {
        pa0 = aval ? *(const float4*)(Ap + k0)     : fz;
        pa1 = aval ? *(const float4*)(Ap + k0 + 8) : fz;
        pb  = *(const float4*)(Bp + (size_t)k0 * N);
        gemm_compute(As[buf], Bs[buf], acc, ty, tx);
        int nb = buf ^ 1;
        As[nb][akc + 0][arow] = pa0.x; As[nb][akc + 1][arow] = pa0.y;
        As[nb][akc + 2][arow] = pa0.z; As[nb][akc + 3][arow] = pa0.w;
        As[nb][akc + 8][arow] = pa1.x; As[nb][akc + 9][arow] = pa1.y;
        As[nb][akc + 10][arow] = pa1.z; As[nb][akc + 11][arow] = pa1.w;
        *(float4*)&Bs[nb][brow][bcol] = pb;
        __syncthreads();
        buf = nb;
    }
    gemm_compute(As[buf], Bs[buf], acc, ty, tx);

    float4 bias4 = fz;
    if (BIAS) bias4 = *(const float4*)(bias + n0 + (tx << 2));
    float4 sa4 = fz, sd4 = fz;
    if (ALPHA) {
        sa4 = *(const float4*)(a_src + n0 + (tx << 2));
        sd4 = *(const float4*)(a_dst + n0 + (tx << 2));
    }

    #pragma unroll
    for (int p = 0; p < 4; p++) {
        float2 u0 = unpack2(acc[p][0]);
        float2 u1 = unpack2(acc[p][1]);
        float2 u2 = unpack2(acc[p][2]);
        float2 u3 = unpack2(acc[p][3]);
        int r0 = m0 + (ty << 3) + (p << 1);
        float lo0 = u0.x, lo1 = u1.x, lo2 = u2.x, lo3 = u3.x;
        float hi0 = u0.y, hi1 = u1.y, hi2 = u2.y, hi3 = u3.y;

        if (r0 < M) {
            float4 v = make_float4(lo0 + bias4.x, lo1 + bias4.y, lo2 + bias4.z, lo3 + bias4.w);
            if (RELU) { v.x = fmaxf(v.x, 0.f); v.y = fmaxf(v.y, 0.f); v.z = fmaxf(v.z, 0.f); v.w = fmaxf(v.w, 0.f); }
            *(float4*)(C + (size_t)r0 * N + n0 + (tx << 2)) = v;
        }
        if (r0 + 1 < M) {
            float4 v = make_float4(hi0 + bias4.x, hi1 + bias4.y, hi2 + bias4.z, hi3 + bias4.w);
            if (RELU) { v.x = fmaxf(v.x, 0.f); v.y = fmaxf(v.y, 0.f); v.z = fmaxf(v.z, 0.f); v.w = fmaxf(v.w, 0.f); }
            *(float4*)(C + (size_t)(r0 + 1) * N + n0 + (tx << 2)) = v;
        }
        if (ALPHA) {
            float ps0 = lo0 * sa4.x + lo1 * sa4.y + lo2 * sa4.z + lo3 * sa4.w;
            float pd0 = lo0 * sd4.x + lo1 * sd4.y + lo2 * sd4.z + lo3 * sd4.w;
            float ps1 = hi0 * sa4.x + hi1 * sa4.y + hi2 * sa4.z + hi3 * sa4.w;
            float pd1 = hi0 * sd4.x + hi1 * sd4.y + hi2 * sd4.z + hi3 * sd4.w;
            #pragma unroll
            for (int o = 1; o < 16; o <<= 1) {
                ps0 += __shfl_xor_sync(0xffffffffu, ps0, o);
                pd0 += __shfl_xor_sync(0xffffffffu, pd0, o);
                ps1 += __shfl_xor_sync(0xffffffffu, ps1, o);
                pd1 += __shfl_xor_sync(0xffffffffu, pd1, o);
            }
            if (tx == 0) {
                if (r0 < M)     { g_as[r0 * AH + by] = ps0; g_ad[r0 * AH + by] = pd0; }
                if (r0 + 1 < M) { g_as[(r0 + 1) * AH + by] = ps1; g_ad[(r0 + 1) * AH + by] = pd1; }
            }
        }
    }
}

// ---------- single-pass softmax aggregation (no max subtraction) ----------
template<int H, bool RELU, bool FUSE_MLP>
__global__ void k_agg(const float* __restrict__ h, const float* __restrict__ bias,
                      float* __restrict__ out,
                      const float* __restrict__ Wo1, const float* __restrict__ bo1,
                      const float* __restrict__ Wo2, const float* __restrict__ bo2) {
    constexpr int HC = H * 64, EPL = HC / 32, LPH = 32 / H;
    __shared__ float sW1[FUSE_MLP ? 64 * 32 : 1];
    __shared__ float sW2[FUSE_MLP ? 32 : 1];
    __shared__ float sb1[FUSE_MLP ? 32 : 1];
    if (FUSE_MLP) {
        for (int i = threadIdx.x; i < 64 * 32; i += blockDim.x) sW1[i] = Wo1[i];
        if (threadIdx.x < 32) { sW2[threadIdx.x] = Wo2[threadIdx.x]; sb1[threadIdx.x] = bo1[threadIdx.x]; }
        __syncthreads();
    }
    const int gw = (blockIdx.x * blockDim.x + threadIdx.x) >> 5;
    const int lane = threadIdx.x & 31;
    if (gw >= NN) return;
    const int beg = g_rowptr[gw], end = g_rowptr[gw + 1];
    const int head = lane / LPH;
    const float adv = g_ad[gw * H + head];

    float ws = 0.f;
    float acc[EPL];
    #pragma unroll
    for (int k = 0; k < EPL; k++) acc[k] = 0.f;
    const float* hb = h + lane * EPL;

    int i = beg;
    for (; i + 2 <= end; i += 2) {
        int s0 = g_csrc[i], s1 = g_csrc[i + 1];
        float a0 = g_as[s0 * H + head];
        float a1 = g_as[s1 * H + head];
        const float* hp0 = hb + (size_t)s0 * HC;
        const float* hp1 = hb + (size_t)s1 * HC;
        float e0 = __expf(leaky(a0 + adv));
        float e1 = __expf(leaky(a1 + adv));
        ws += e0 + e1;
        if constexpr (EPL >= 4) {
            #pragma unroll
            for (int k = 0; k < EPL; k += 4) {
                float4 v0 = *(const float4*)(hp0 + k);
                float4 v1 = *(const float4*)(hp1 + k);
                acc[k]     += e0 * v0.x + e1 * v1.x;
                acc[k + 1] += e0 * v0.y + e1 * v1.y;
                acc[k + 2] += e0 * v0.z + e1 * v1.z;
                acc[k + 3] += e0 * v0.w + e1 * v1.w;
            }
        } else {
            float2 v0 = *(const float2*)hp0;
            float2 v1 = *(const float2*)hp1;
            acc[0] += e0 * v0.x + e1 * v1.x;
            acc[1] += e0 * v0.y + e1 * v1.y;
        }
    }
    if (i < end) {
        int s = g_csrc[i];
        float e = __expf(leaky(g_as[s * H + head] + adv));
        ws += e;
        const float* hp = hb + (size_t)s * HC;
        if constexpr (EPL >= 4) {
            #pragma unroll
            for (int k = 0; k < EPL; k += 4) {
                float4 hv = *(const float4*)(hp + k);
                acc[k] += e * hv.x; acc[k + 1] += e * hv.y;
                acc[k + 2] += e * hv.z; acc[k + 3] += e * hv.w;
            }
        } else {
            float2 hv = *(const float2*)hp;
            acc[0] += e * hv.x; acc[1] += e * hv.y;
        }
    }

    const float rinv = 1.f / ws;
    const float* bp = bias + lane * EPL;
    #pragma unroll
    for (int k = 0; k < EPL; k++) {
        float v = acc[k] * rinv + bp[k];
        if (RELU) v = fmaxf(v, 0.f);
        acc[k] = v;
    }

    if constexpr (FUSE_MLP) {
        float v0 = acc[0], v1 = acc[1];
        float hid = sb1[lane];
        #pragma unroll
        for (int k = 0; k < 32; k++) {
            float r0 = __shfl_sync(0xffffffffu, v0, k);
            float r1 = __shfl_sync(0xffffffffu, v1, k);
            hid = fmaf(r0, sW1[(2 * k) * 32 + lane], hid);
            hid = fmaf(r1, sW1[(2 * k + 1) * 32 + lane], hid);
        }
        hid = fmaxf(hid, 0.f);
        float o = hid * sW2[lane];
        #pragma unroll
        for (int w = 1; w < 32; w <<= 1) o += __shfl_xor_sync(0xffffffffu, o, w);
        if (lane == 0) out[gw] = o + bo2[0];
    } else {
        float* op = out + (size_t)gw * HC + lane * EPL;
        #pragma unroll
        for (int k = 0; k < EPL; k += 4)
            *(float4*)(op + k) = make_float4(acc[k], acc[k + 1], acc[k + 2], acc[k + 3]);
    }
}

// ---------------- launch ----------------
extern "C" void kernel_launch(void* const* d_in, const int* in_sizes, int n_in,
                              void* d_out, int out_size) {
    const float* x     = (const float*)d_in[0];
    const float* W_emb = (const float*)d_in[1];
    const float* b_emb = (const float*)d_in[2];
    const float* W0    = (const float*)d_in[3];
    const float* as0   = (const float*)d_in[4];
    const float* ad0   = (const float*)d_in[5];
    const float* b0    = (const float*)d_in[6];
    const float* W1    = (const float*)d_in[7];
    const float* as1   = (const float*)d_in[8];
    const float* ad1   = (const float*)d_in[9];
    const float* b1    = (const float*)d_in[10];
    const float* W2    = (const float*)d_in[11];
    const float* as2   = (const float*)d_in[12];
    const float* ad2   = (const float*)d_in[13];
    const float* b2    = (const float*)d_in[14];
    const float* Wo1   = (const float*)d_in[15];
    const float* bo1   = (const float*)d_in[16];
    const float* Wo2   = (const float*)d_in[17];
    const float* bo2   = (const float*)d_in[18];
    const int*   ei    = (const int*)d_in[19];
    float* out = (float*)d_out;

    float *p_h0, *p_hA, *p_hB;
    int* p_cnt;
    cudaGetSymbolAddress((void**)&p_h0, g_h0);
    cudaGetSymbolAddress((void**)&p_hA, g_hA);
    cudaGetSymbolAddress((void**)&p_hB, g_hB);
    cudaGetSymbolAddress((void**)&p_cnt, g_cnt);

    const int MB = (NN + 127) / 128;               // 391 row tiles
    const int SCAN_BLK = (NN + 255) / 256;         // 196
    const int WARP_GRID = (NN * 32 + 255) / 256;
    const int WARP_GRID512 = (NN * 32 + 511) / 512;

    // [0] embedding: relu(x @ W_emb + b_emb)
    k_gemm2<true, true, false, 1><<<dim3(MB, 1), 256>>>(
        x, W_emb, b_emb, nullptr, nullptr, p_h0, NN, FIN, HID);

    // CSR build ordered so launch #5 (the profiled one) is the mma GEMM
    k_zero<<<(NN + 255) / 256, 256>>>(p_cnt, NN);                 // [1]
    k_hist<<<(ET + 255) / 256, 256>>>(ei);                        // [2]
    k_scan1<<<SCAN_BLK, 256>>>();                                 // [3]
    k_scan2<<<1, 256>>>(SCAN_BLK);                                // [4]

    // [5] GAT layer 0 GEMM (mma.sync tf32): hA = h0 @ W0
    k_gemm_mma<<<dim3(MB, 2), 256>>>(p_h0, W0, p_hA, NN, HID);
    // [6] layer 0 attention dots
    k_alpha4<<<WARP_GRID, 256>>>(p_hA, as0, ad0);

    k_scan3<<<SCAN_BLK, 256>>>();                                 // [7]
    k_scatter<<<(ET + 255) / 256, 256>>>(ei);                     // [8]

    // [9] layer-0 aggregation
    k_agg<4, true, false><<<WARP_GRID, 256>>>(p_hA, b0, p_hB,
        nullptr, nullptr, nullptr, nullptr);

    // [10] GAT layer 1 GEMM (mma.sync tf32) + [11] dots
    k_gemm_mma<<<dim3(MB, 2), 256>>>(p_hB, W1, p_hA, NN, HEADS * HID);
    k_alpha4<<<WARP_GRID, 256>>>(p_hA, as1, ad1);
    // [12] layer-1 aggregation
    k_agg<4, true, false><<<WARP_GRID, 256>>>(p_hA, b1, p_hB,
        nullptr, nullptr, nullptr, nullptr);

    // [13] GAT layer 2 GEMM (FFMA2, N=64) + alpha fused
    k_gemm2<false, false, true, 1><<<dim3(MB, 1), 256>>>(
        p_hB, W2, nullptr, as2, ad2, p_hA, NN, 256, 64);
    // [14] layer-2 aggregation + fused output MLP
    k_agg<1, false, true><<<WARP_GRID512, 512>>>(p_hA, b2, out,
        Wo1, bo1, Wo2, bo2);
}

// round 8
// speedup vs baseline: 1.6431x; 1.0837x over previous
#include <cuda_runtime.h>
#include <cuda_fp16.h>
#include <cstdint>

#define NN 50000
#define NE 800000
#define ET 850000            // NE + NN self loops
#define FIN 128
#define HID 64
#define HEADS 4

typedef unsigned long long ull;

// ---------------- device scratch (static allocation only) ----------------
static __device__ float g_h0[NN * HID];            // 12.8 MB
static __device__ float g_hA[NN * HEADS * HID];    // 51.2 MB (aliased as half)
static __device__ float g_hB[NN * HEADS * HID];    // 51.2 MB
static __device__ float g_as[NN * HEADS];
static __device__ float g_ad[NN * HEADS];
static __device__ int   g_cnt[NN];
static __device__ int   g_rowptr[NN + 1];
static __device__ int   g_cursor[NN];
static __device__ int   g_csrc[ET];
static __device__ int   g_bsum[256];
static __device__ int   g_boff[256];

__device__ __forceinline__ float leaky(float v) { return v > 0.f ? v : 0.2f * v; }

// packed fp32x2 helpers (FFMA2 — only reachable via PTX on sm_103a)
__device__ __forceinline__ ull dupf(float f) {
    ull r; asm("mov.b64 %0, {%1, %1};" : "=l"(r) : "f"(f)); return r;
}
__device__ __forceinline__ void ffma2(ull& d, ull a, ull b) {
    asm("fma.rn.f32x2 %0, %1, %2, %0;" : "+l"(d) : "l"(a), "l"(b));
}
__device__ __forceinline__ float2 unpack2(ull v) {
    float2 r; asm("mov.b64 {%0, %1}, %2;" : "=f"(r.x), "=f"(r.y) : "l"(v)); return r;
}
__device__ __forceinline__ uint32_t cvt_tf32(float f) {
    uint32_t r; asm("cvt.rna.tf32.f32 %0, %1;" : "=r"(r) : "f"(f)); return r;
}

// ---------------- CSR construction ----------------
__global__ void k_zero(int* p, int n) {
    int i = blockIdx.x * blockDim.x + threadIdx.x;
    if (i < n) p[i] = 0;
}

__global__ void k_hist(const int* __restrict__ ei) {
    int i = blockIdx.x * blockDim.x + threadIdx.x;
    if (i >= ET) return;
    int d = (i < NE) ? ei[NE + i] : (i - NE);
    atomicAdd(&g_cnt[d], 1);
}

__device__ __forceinline__ int blk_scan_excl(int v, int* total, int lane, int wid, int nw) {
    __shared__ int wsum[32];
    int x = v;
    #pragma unroll
    for (int o = 1; o < 32; o <<= 1) {
        int y = __shfl_up_sync(0xffffffffu, x, o);
        if (lane >= o) x += y;
    }
    if (lane == 31) wsum[wid] = x;
    __syncthreads();
    if (wid == 0) {
        int w = (lane < nw) ? wsum[lane] : 0;
        #pragma unroll
        for (int o = 1; o < 32; o <<= 1) {
            int y = __shfl_up_sync(0xffffffffu, w, o);
            if (lane >= o) w += y;
        }
        wsum[lane] = w;
    }
    __syncthreads();
    int base = (wid > 0) ? wsum[wid - 1] : 0;
    *total = wsum[nw - 1];
    return base + x - v;
}

__global__ void k_scan1() {
    int tid = threadIdx.x, i = blockIdx.x * 256 + tid;
    int v = (i < NN) ? g_cnt[i] : 0;
    int total;
    int excl = blk_scan_excl(v, &total, tid & 31, tid >> 5, 8);
    if (i < NN) g_rowptr[i] = excl;
    if (tid == 0) g_bsum[blockIdx.x] = total;
}

__global__ void k_scan2(int nblk) {
    int tid = threadIdx.x;
    int v = (tid < nblk) ? g_bsum[tid] : 0;
    int total;
    int excl = blk_scan_excl(v, &total, tid & 31, tid >> 5, 8);
    g_boff[tid] = excl;
    if (tid == 0) g_rowptr[NN] = total;
}

__global__ void k_scan3() {
    int i = blockIdx.x * blockDim.x + threadIdx.x;
    if (i >= NN) return;
    int r = g_rowptr[i] + g_boff[i >> 8];
    g_rowptr[i] = r;
    g_cursor[i] = r;
}

__global__ void k_scatter(const int* __restrict__ ei) {
    int i = blockIdx.x * blockDim.x + threadIdx.x;
    if (i >= ET) return;
    int s, d;
    if (i < NE) { s = ei[i]; d = ei[NE + i]; }
    else        { s = i - NE; d = s; }
    int pos = atomicAdd(&g_cursor[d], 1);
    g_csrc[pos] = s;
}

// ============ tf32 mma.sync GEMM: Ch[M,256] = A[M,K] @ W[K,256] ============
// Output stored as fp16 (consumed only by alpha/agg gathers).
#define AST 20
#define BST 136

__device__ __forceinline__ void mma_tf32(float c[4], const uint32_t a[4], const uint32_t b[2]) {
    asm volatile(
        "mma.sync.aligned.m16n8k8.row.col.f32.tf32.tf32.f32 "
        "{%0,%1,%2,%3}, {%4,%5,%6,%7}, {%8,%9}, {%0,%1,%2,%3};"
        : "+f"(c[0]), "+f"(c[1]), "+f"(c[2]), "+f"(c[3])
        : "r"(a[0]), "r"(a[1]), "r"(a[2]), "r"(a[3]), "r"(b[0]), "r"(b[1]));
}

__global__ __launch_bounds__(256)
void k_gemm_mma(const float* __restrict__ A, const float* __restrict__ W,
                __half* __restrict__ Ch, int M, int K) {
    __shared__ uint32_t As[2][128 * AST];
    __shared__ uint32_t Bs[2][16 * BST];
    const int tid = threadIdx.x;
    const int wid = tid >> 5, lane = tid & 31;
    const int g = lane >> 2, tig = lane & 3;
    const int warp_m = (wid >> 2) << 6;     // 0 or 64
    const int warp_n = (wid & 3) << 5;      // 0,32,64,96
    const int m0 = blockIdx.x * 128;
    const int n0 = blockIdx.y * 128;
    const int N = 256;

    float acc[4][4][4];
    #pragma unroll
    for (int mt = 0; mt < 4; mt++)
        #pragma unroll
        for (int nt = 0; nt < 4; nt++)
            #pragma unroll
            for (int q = 0; q < 4; q++) acc[mt][nt][q] = 0.f;

    const int ar = tid >> 1, akh = (tid & 1) << 3;
    const bool av = (m0 + ar) < M;
    const float* Ap = A + (size_t)(m0 + ar) * K + akh;
    const int bk = tid >> 4, bn = (tid & 15) << 3;
    const float* Wp = W + (size_t)bk * N + n0 + bn;

    const float4 fz = make_float4(0.f, 0.f, 0.f, 0.f);
    float4 ra0, ra1, rb0, rb1;

    ra0 = av ? *(const float4*)(Ap)     : fz;
    ra1 = av ? *(const float4*)(Ap + 4) : fz;
    rb0 = *(const float4*)(Wp);
    rb1 = *(const float4*)(Wp + 4);
    *(uint4*)&As[0][ar * AST + akh]     = make_uint4(cvt_tf32(ra0.x), cvt_tf32(ra0.y), cvt_tf32(ra0.z), cvt_tf32(ra0.w));
    *(uint4*)&As[0][ar * AST + akh + 4] = make_uint4(cvt_tf32(ra1.x), cvt_tf32(ra1.y), cvt_tf32(ra1.z), cvt_tf32(ra1.w));
    *(uint4*)&Bs[0][bk * BST + bn]      = make_uint4(cvt_tf32(rb0.x), cvt_tf32(rb0.y), cvt_tf32(rb0.z), cvt_tf32(rb0.w));
    *(uint4*)&Bs[0][bk * BST + bn + 4]  = make_uint4(cvt_tf32(rb1.x), cvt_tf32(rb1.y), cvt_tf32(rb1.z), cvt_tf32(rb1.w));
    __syncthreads();

    const int nch = K >> 4;
    int buf = 0;
    for (int c = 1; c <= nch; c++) {
        if (c < nch) {
            const int k0 = c << 4;
            ra0 = av ? *(const float4*)(Ap + k0)     : fz;
            ra1 = av ? *(const float4*)(Ap + k0 + 4) : fz;
            rb0 = *(const float4*)(Wp + (size_t)k0 * N);
            rb1 = *(const float4*)(Wp + (size_t)k0 * N + 4);
        }
        #pragma unroll
        for (int ks = 0; ks < 2; ks++) {
            const int kc = ks << 3;
            uint32_t a[4][4], b[4][2];
            #pragma unroll
            for (int mt = 0; mt < 4; mt++) {
                int mr = warp_m + (mt << 4) + g;
                a[mt][0] = As[buf][mr * AST + kc + tig];
                a[mt][1] = As[buf][(mr + 8) * AST + kc + tig];
                a[mt][2] = As[buf][mr * AST + kc + tig + 4];
                a[mt][3] = As[buf][(mr + 8) * AST + kc + tig + 4];
            }
            #pragma unroll
            for (int nt = 0; nt < 4; nt++) {
                int nc = warp_n + (nt << 3) + g;
                b[nt][0] = Bs[buf][(kc + tig) * BST + nc];
                b[nt][1] = Bs[buf][(kc + tig + 4) * BST + nc];
            }
            #pragma unroll
            for (int mt = 0; mt < 4; mt++)
                #pragma unroll
                for (int nt = 0; nt < 4; nt++)
                    mma_tf32(acc[mt][nt], a[mt], b[nt]);
        }
        if (c < nch) {
            int nb = buf ^ 1;
            *(uint4*)&As[nb][ar * AST + akh]     = make_uint4(cvt_tf32(ra0.x), cvt_tf32(ra0.y), cvt_tf32(ra0.z), cvt_tf32(ra0.w));
            *(uint4*)&As[nb][ar * AST + akh + 4] = make_uint4(cvt_tf32(ra1.x), cvt_tf32(ra1.y), cvt_tf32(ra1.z), cvt_tf32(ra1.w));
            *(uint4*)&Bs[nb][bk * BST + bn]      = make_uint4(cvt_tf32(rb0.x), cvt_tf32(rb0.y), cvt_tf32(rb0.z), cvt_tf32(rb0.w));
            *(uint4*)&Bs[nb][bk * BST + bn + 4]  = make_uint4(cvt_tf32(rb1.x), cvt_tf32(rb1.y), cvt_tf32(rb1.z), cvt_tf32(rb1.w));
            __syncthreads();
            buf = nb;
        }
    }

    // epilogue: half2 stores
    #pragma unroll
    for (int mt = 0; mt < 4; mt++) {
        int r0 = m0 + warp_m + (mt << 4) + g;
        int r1 = r0 + 8;
        #pragma unroll
        for (int nt = 0; nt < 4; nt++) {
            int col = n0 + warp_n + (nt << 3) + (tig << 1);
            if (r0 < M)
                *(__half2*)(Ch + (size_t)r0 * N + col) = __floats2half2_rn(acc[mt][nt][0], acc[mt][nt][1]);
            if (r1 < M)
                *(__half2*)(Ch + (size_t)r1 * N + col) = __floats2half2_rn(acc[mt][nt][2], acc[mt][nt][3]);
        }
    }
}

// ---------------- per-node attention dots (H=4, fp16 h) ----------------
__global__ void k_alpha4(const __half* __restrict__ h, const float* __restrict__ a_s,
                         const float* __restrict__ a_d) {
    int gw = (blockIdx.x * blockDim.x + threadIdx.x) >> 5;
    int lane = threadIdx.x & 31;
    if (gw >= NN) return;
    const __half* row = h + (size_t)gw * 256 + lane * 8;
    const float* asp = a_s + lane * 8;
    const float* adp = a_d + lane * 8;
    uint4 u = *(const uint4*)row;
    float2 f0 = __half22float2(*(__half2*)&u.x);
    float2 f1 = __half22float2(*(__half2*)&u.y);
    float2 f2 = __half22float2(*(__half2*)&u.z);
    float2 f3 = __half22float2(*(__half2*)&u.w);
    float hv[8] = {f0.x, f0.y, f1.x, f1.y, f2.x, f2.y, f3.x, f3.y};
    float ps = 0.f, pd = 0.f;
    #pragma unroll
    for (int k = 0; k < 8; k++) {
        ps += hv[k] * asp[k];
        pd += hv[k] * adp[k];
    }
    #pragma unroll
    for (int o = 1; o < 8; o <<= 1) {
        ps += __shfl_xor_sync(0xffffffffu, ps, o);
        pd += __shfl_xor_sync(0xffffffffu, pd, o);
    }
    if ((lane & 7) == 0) {
        int head = lane >> 3;
        g_as[gw * 4 + head] = ps;
        g_ad[gw * 4 + head] = pd;
    }
}

// ---------------- FFMA2 SGEMM BM=128 BN=64 (emb fp32 out, layer-2 half out) --
__device__ __forceinline__ void gemm_compute(const float (*As)[128], const float (*Bs)[64],
                                             ull acc[4][4], int ty, int tx) {
    #pragma unroll
    for (int k = 0; k < 16; k++) {
        const ull* ap = (const ull*)&As[k][0];
        ull a0 = ap[(ty << 2) + 0];
        ull a1 = ap[(ty << 2) + 1];
        ull a2 = ap[(ty << 2) + 2];
        ull a3 = ap[(ty << 2) + 3];
        float4 b = *(const float4*)&Bs[k][tx << 2];
        ull b0 = dupf(b.x), b1 = dupf(b.y), b2 = dupf(b.z), b3 = dupf(b.w);
        ffma2(acc[0][0], a0, b0); ffma2(acc[0][1], a0, b1); ffma2(acc[0][2], a0, b2); ffma2(acc[0][3], a0, b3);
        ffma2(acc[1][0], a1, b0); ffma2(acc[1][1], a1, b1); ffma2(acc[1][2], a1, b2); ffma2(acc[1][3], a1, b3);
        ffma2(acc[2][0], a2, b0); ffma2(acc[2][1], a2, b1); ffma2(acc[2][2], a2, b2); ffma2(acc[2][3], a2, b3);
        ffma2(acc[3][0], a3, b0); ffma2(acc[3][1], a3, b1); ffma2(acc[3][2], a3, b2); ffma2(acc[3][3], a3, b3);
    }
}

template<bool BIAS, bool RELU, bool ALPHA, bool STORE_HALF, int AH>
__global__ __launch_bounds__(256)
void k_gemm2(const float* __restrict__ A, const float* __restrict__ B,
             const float* __restrict__ bias,
             const float* __restrict__ a_src, const float* __restrict__ a_dst,
             void* __restrict__ Cv, int M, int K, int N) {
    __shared__ float As[2][16][128];
    __shared__ float Bs[2][16][64];
    const int t  = threadIdx.x;
    const int tx = t & 15, ty = t >> 4;
    const int m0 = blockIdx.x * 128;
    const int by = blockIdx.y;
    const int n0 = by * 64;

    ull acc[4][4];
    #pragma unroll
    for (int p = 0; p < 4; p++)
        #pragma unroll
        for (int j = 0; j < 4; j++) acc[p][j] = 0ull;

    const int arow = t & 127;
    const int akc  = (t >> 7) << 2;
    const bool aval = (m0 + arow) < M;
    const float* Ap = A + (size_t)(m0 + arow) * K + akc;
    const int brow = t >> 4, bcol = (t & 15) << 2;
    const float* Bp = B + (size_t)brow * N + n0 + bcol;

    const float4 fz = make_float4(0.f, 0.f, 0.f, 0.f);
    float4 pa0, pa1, pb;

    pa0 = aval ? *(const float4*)(Ap)     : fz;
    pa1 = aval ? *(const float4*)(Ap + 8) : fz;
    pb  = *(const float4*)(Bp);
    As[0][akc + 0][arow] = pa0.x; As[0][akc + 1][arow] = pa0.y;
    As[0][akc + 2][arow] = pa0.z; As[0][akc + 3][arow] = pa0.w;
    As[0][akc + 8][arow] = pa1.x; As[0][akc + 9][arow] = pa1.y;
    As[0][akc + 10][arow] = pa1.z; As[0][akc + 11][arow] = pa1.w;
    *(float4*)&Bs[0][brow][bcol] = pb;
    __syncthreads();

    int buf = 0;
    for (int k0 = 16; k0 < K; k0 += 16) {
        pa0 = aval ? *(const float4*)(Ap + k0)     : fz;
        pa1 = aval ? *(const float4*)(Ap + k0 + 8) : fz;
        pb  = *(const float4*)(Bp + (size_t)k0 * N);
        gemm_compute(As[buf], Bs[buf], acc, ty, tx);
        int nb = buf ^ 1;
        As[nb][akc + 0][arow] = pa0.x; As[nb][akc + 1][arow] = pa0.y;
        As[nb][akc + 2][arow] = pa0.z; As[nb][akc + 3][arow] = pa0.w;
        As[nb][akc + 8][arow] = pa1.x; As[nb][akc + 9][arow] = pa1.y;
        As[nb][akc + 10][arow] = pa1.z; As[nb][akc + 11][arow] = pa1.w;
        *(float4*)&Bs[nb][brow][bcol] = pb;
        __syncthreads();
        buf = nb;
    }
    gemm_compute(As[buf], Bs[buf], acc, ty, tx);

    float4 bias4 = fz;
    if (BIAS) bias4 = *(const float4*)(bias + n0 + (tx << 2));
    float4 sa4 = fz, sd4 = fz;
    if (ALPHA) {
        sa4 = *(const float4*)(a_src + n0 + (tx << 2));
        sd4 = *(const float4*)(a_dst + n0 + (tx << 2));
    }

    float* Cf = (float*)Cv;
    __half* Ch = (__half*)Cv;

    #pragma unroll
    for (int p = 0; p < 4; p++) {
        float2 u0 = unpack2(acc[p][0]);
        float2 u1 = unpack2(acc[p][1]);
        float2 u2 = unpack2(acc[p][2]);
        float2 u3 = unpack2(acc[p][3]);
        int r0 = m0 + (ty << 3) + (p << 1);
        float lo0 = u0.x, lo1 = u1.x, lo2 = u2.x, lo3 = u3.x;
        float hi0 = u0.y, hi1 = u1.y, hi2 = u2.y, hi3 = u3.y;

        if (r0 < M) {
            float4 v = make_float4(lo0 + bias4.x, lo1 + bias4.y, lo2 + bias4.z, lo3 + bias4.w);
            if (RELU) { v.x = fmaxf(v.x, 0.f); v.y = fmaxf(v.y, 0.f); v.z = fmaxf(v.z, 0.f); v.w = fmaxf(v.w, 0.f); }
            if (STORE_HALF) {
                __half2 h0 = __floats2half2_rn(v.x, v.y);
                __half2 h1 = __floats2half2_rn(v.z, v.w);
                *(uint2*)(Ch + (size_t)r0 * N + n0 + (tx << 2)) =
                    make_uint2(*(uint32_t*)&h0, *(uint32_t*)&h1);
            } else {
                *(float4*)(Cf + (size_t)r0 * N + n0 + (tx << 2)) = v;
            }
        }
        if (r0 + 1 < M) {
            float4 v = make_float4(hi0 + bias4.x, hi1 + bias4.y, hi2 + bias4.z, hi3 + bias4.w);
            if (RELU) { v.x = fmaxf(v.x, 0.f); v.y = fmaxf(v.y, 0.f); v.z = fmaxf(v.z, 0.f); v.w = fmaxf(v.w, 0.f); }
            if (STORE_HALF) {
                __half2 h0 = __floats2half2_rn(v.x, v.y);
                __half2 h1 = __floats2half2_rn(v.z, v.w);
                *(uint2*)(Ch + (size_t)(r0 + 1) * N + n0 + (tx << 2)) =
                    make_uint2(*(uint32_t*)&h0, *(uint32_t*)&h1);
            } else {
                *(float4*)(Cf + (size_t)(r0 + 1) * N + n0 + (tx << 2)) = v;
            }
        }
        if (ALPHA) {
            float ps0 = lo0 * sa4.x + lo1 * sa4.y + lo2 * sa4.z + lo3 * sa4.w;
            float pd0 = lo0 * sd4.x + lo1 * sd4.y + lo2 * sd4.z + lo3 * sd4.w;
            float ps1 = hi0 * sa4.x + hi1 * sa4.y + hi2 * sa4.z + hi3 * sa4.w;
            float pd1 = hi0 * sd4.x + hi1 * sd4.y + hi2 * sd4.z + hi3 * sd4.w;
            #pragma unroll
            for (int o = 1; o < 16; o <<= 1) {
                ps0 += __shfl_xor_sync(0xffffffffu, ps0, o);
                pd0 += __shfl_xor_sync(0xffffffffu, pd0, o);
                ps1 += __shfl_xor_sync(0xffffffffu, ps1, o);
                pd1 += __shfl_xor_sync(0xffffffffu, pd1, o);
            }
            if (tx == 0) {
                if (r0 < M)     { g_as[r0 * AH + by] = ps0; g_ad[r0 * AH + by] = pd0; }
                if (r0 + 1 < M) { g_as[(r0 + 1) * AH + by] = ps1; g_ad[(r0 + 1) * AH + by] = pd1; }
            }
        }
    }
}

// ---------- single-pass softmax aggregation over fp16 h ----------
template<int H, bool RELU, bool FUSE_MLP>
__global__ void k_agg(const __half* __restrict__ h, const float* __restrict__ bias,
                      float* __restrict__ out,
                      const float* __restrict__ Wo1, const float* __restrict__ bo1,
                      const float* __restrict__ Wo2, const float* __restrict__ bo2) {
    constexpr int HC = H * 64, EPL = HC / 32, LPH = 32 / H;
    __shared__ float sW1[FUSE_MLP ? 64 * 32 : 1];
    __shared__ float sW2[FUSE_MLP ? 32 : 1];
    __shared__ float sb1[FUSE_MLP ? 32 : 1];
    if (FUSE_MLP) {
        for (int i = threadIdx.x; i < 64 * 32; i += blockDim.x) sW1[i] = Wo1[i];
        if (threadIdx.x < 32) { sW2[threadIdx.x] = Wo2[threadIdx.x]; sb1[threadIdx.x] = bo1[threadIdx.x]; }
        __syncthreads();
    }
    const int gw = (blockIdx.x * blockDim.x + threadIdx.x) >> 5;
    const int lane = threadIdx.x & 31;
    if (gw >= NN) return;
    const int beg = g_rowptr[gw], end = g_rowptr[gw + 1];
    const int head = lane / LPH;
    const float adv = g_ad[gw * H + head];

    float ws = 0.f;
    float acc[EPL];
    #pragma unroll
    for (int k = 0; k < EPL; k++) acc[k] = 0.f;
    const __half* hb = h + lane * EPL;

    int i = beg;
    for (; i + 2 <= end; i += 2) {
        int s0 = g_csrc[i], s1 = g_csrc[i + 1];
        float a0 = g_as[s0 * H + head];
        float a1 = g_as[s1 * H + head];
        const __half* hp0 = hb + (size_t)s0 * HC;
        const __half* hp1 = hb + (size_t)s1 * HC;
        float e0 = __expf(leaky(a0 + adv));
        float e1 = __expf(leaky(a1 + adv));
        ws += e0 + e1;
        if constexpr (EPL == 8) {
            uint4 u0 = *(const uint4*)hp0;
            uint4 u1 = *(const uint4*)hp1;
            float2 p;
            p = __half22float2(*(__half2*)&u0.x); acc[0] += e0 * p.x; acc[1] += e0 * p.y;
            p = __half22float2(*(__half2*)&u0.y); acc[2] += e0 * p.x; acc[3] += e0 * p.y;
            p = __half22float2(*(__half2*)&u0.z); acc[4] += e0 * p.x; acc[5] += e0 * p.y;
            p = __half22float2(*(__half2*)&u0.w); acc[6] += e0 * p.x; acc[7] += e0 * p.y;
            p = __half22float2(*(__half2*)&u1.x); acc[0] += e1 * p.x; acc[1] += e1 * p.y;
            p = __half22float2(*(__half2*)&u1.y); acc[2] += e1 * p.x; acc[3] += e1 * p.y;
            p = __half22float2(*(__half2*)&u1.z); acc[4] += e1 * p.x; acc[5] += e1 * p.y;
            p = __half22float2(*(__half2*)&u1.w); acc[6] += e1 * p.x; acc[7] += e1 * p.y;
        } else {
            float2 v0 = __half22float2(*(const __half2*)hp0);
            float2 v1 = __half22float2(*(const __half2*)hp1);
            acc[0] += e0 * v0.x + e1 * v1.x;
            acc[1] += e0 * v0.y + e1 * v1.y;
        }
    }
    if (i < end) {
        int s = g_csrc[i];
        float e = __expf(leaky(g_as[s * H + head] + adv));
        ws += e;
        const __half* hp = hb + (size_t)s * HC;
        if constexpr (EPL == 8) {
            uint4 u0 = *(const uint4*)hp;
            float2 p;
            p = __half22float2(*(__half2*)&u0.x); acc[0] += e * p.x; acc[1] += e * p.y;
            p = __half22float2(*(__half2*)&u0.y); acc[2] += e * p.x; acc[3] += e * p.y;
            p = __half22float2(*(__half2*)&u0.z); acc[4] += e * p.x; acc[5] += e * p.y;
            p = __half22float2(*(__half2*)&u0.w); acc[6] += e * p.x; acc[7] += e * p.y;
        } else {
            float2 v0 = __half22float2(*(const __half2*)hp);
            acc[0] += e * v0.x; acc[1] += e * v0.y;
        }
    }

    const float rinv = 1.f / ws;
    const float* bp = bias + lane * EPL;
    #pragma unroll
    for (int k = 0; k < EPL; k++) {
        float v = acc[k] * rinv + bp[k];
        if (RELU) v = fmaxf(v, 0.f);
        acc[k] = v;
    }

    if constexpr (FUSE_MLP) {
        float v0 = acc[0], v1 = acc[1];
        float hid = sb1[lane];
        #pragma unroll
        for (int k = 0; k < 32; k++) {
            float r0 = __shfl_sync(0xffffffffu, v0, k);
            float r1 = __shfl_sync(0xffffffffu, v1, k);
            hid = fmaf(r0, sW1[(2 * k) * 32 + lane], hid);
            hid = fmaf(r1, sW1[(2 * k + 1) * 32 + lane], hid);
        }
        hid = fmaxf(hid, 0.f);
        float o = hid * sW2[lane];
        #pragma unroll
        for (int w = 1; w < 32; w <<= 1) o += __shfl_xor_sync(0xffffffffu, o, w);
        if (lane == 0) out[gw] = o + bo2[0];
    } else {
        float* op = out + (size_t)gw * HC + lane * EPL;
        #pragma unroll
        for (int k = 0; k < EPL; k += 4)
            *(float4*)(op + k) = make_float4(acc[k], acc[k + 1], acc[k + 2], acc[k + 3]);
    }
}

// ---------------- launch ----------------
extern "C" void kernel_launch(void* const* d_in, const int* in_sizes, int n_in,
                              void* d_out, int out_size) {
    const float* x     = (const float*)d_in[0];
    const float* W_emb = (const float*)d_in[1];
    const float* b_emb = (const float*)d_in[2];
    const float* W0    = (const float*)d_in[3];
    const float* as0   = (const float*)d_in[4];
    const float* ad0   = (const float*)d_in[5];
    const float* b0    = (const float*)d_in[6];
    const float* W1    = (const float*)d_in[7];
    const float* as1   = (const float*)d_in[8];
    const float* ad1   = (const float*)d_in[9];
    const float* b1    = (const float*)d_in[10];
    const float* W2    = (const float*)d_in[11];
    const float* as2   = (const float*)d_in[12];
    const float* ad2   = (const float*)d_in[13];
    const float* b2    = (const float*)d_in[14];
    const float* Wo1   = (const float*)d_in[15];
    const float* bo1   = (const float*)d_in[16];
    const float* Wo2   = (const float*)d_in[17];
    const float* bo2   = (const float*)d_in[18];
    const int*   ei    = (const int*)d_in[19];
    float* out = (float*)d_out;

    float *p_h0, *p_hA, *p_hB;
    int* p_cnt;
    cudaGetSymbolAddress((void**)&p_h0, g_h0);
    cudaGetSymbolAddress((void**)&p_hA, g_hA);
    cudaGetSymbolAddress((void**)&p_hB, g_hB);
    cudaGetSymbolAddress((void**)&p_cnt, g_cnt);
    __half* p_hAh = (__half*)p_hA;    // fp16 view of the hA scratch

    const int MB = (NN + 127) / 128;               // 391 row tiles
    const int SCAN_BLK = (NN + 255) / 256;         // 196
    const int WARP_GRID = (NN * 32 + 255) / 256;
    const int WARP_GRID512 = (NN * 32 + 511) / 512;

    // embedding: relu(x @ W_emb + b_emb)  (fp32 out, feeds mma A)
    k_gemm2<true, true, false, false, 1><<<dim3(MB, 1), 256>>>(
        x, W_emb, b_emb, nullptr, nullptr, p_h0, NN, FIN, HID);

    // CSR build
    k_zero<<<(NN + 255) / 256, 256>>>(p_cnt, NN);
    k_hist<<<(ET + 255) / 256, 256>>>(ei);
    k_scan1<<<SCAN_BLK, 256>>>();
    k_scan2<<<1, 256>>>(SCAN_BLK);

    // GAT layer 0 GEMM (mma.sync tf32, fp16 out) + dots
    k_gemm_mma<<<dim3(MB, 2), 256>>>(p_h0, W0, p_hAh, NN, HID);
    k_alpha4<<<WARP_GRID, 256>>>(p_hAh, as0, ad0);

    k_scan3<<<SCAN_BLK, 256>>>();
    k_scatter<<<(ET + 255) / 256, 256>>>(ei);

    // layer-0 aggregation (fp16 gather, fp32 out)
    k_agg<4, true, false><<<WARP_GRID, 256>>>(p_hAh, b0, p_hB,
        nullptr, nullptr, nullptr, nullptr);

    // GAT layer 1
    k_gemm_mma<<<dim3(MB, 2), 256>>>(p_hB, W1, p_hAh, NN, HEADS * HID);
    k_alpha4<<<WARP_GRID, 256>>>(p_hAh, as1, ad1);
    k_agg<4, true, false><<<WARP_GRID, 256>>>(p_hAh, b1, p_hB,
        nullptr, nullptr, nullptr, nullptr);

    // GAT layer 2 (FFMA2, N=64, fp16 out + fp32 alpha dots)
    k_gemm2<false, false, true, true, 1><<<dim3(MB, 1), 256>>>(
        p_hB, W2, nullptr, as2, ad2, p_hAh, NN, 256, 64);
    // layer-2 aggregation + fused output MLP
    k_agg<1, false, true><<<WARP_GRID512, 512>>>(p_hAh, b2, out,
        Wo1, bo1, Wo2, bo2);
}

// round 10
// speedup vs baseline: 2.1275x; 1.2948x over previous
#include <cuda_runtime.h>
#include <cuda_fp16.h>
#include <cstdint>

#define NN 50000
#define NE 800000
#define ET 850000            // NE + NN self loops
#define FIN 128
#define HID 64
#define HEADS 4

// ---------------- device scratch (static allocation only) ----------------
static __device__ float g_h0[NN * HID];            // used as half [NN][64]
static __device__ float g_hA[NN * HEADS * HID];    // used as half [NN][256]
static __device__ float g_hB[NN * HEADS * HID];    // used as half [NN][256]
static __device__ float g_as[NN * HEADS];
static __device__ float g_ad[NN * HEADS];
static __device__ int   g_cnt[NN];
static __device__ int   g_rowptr[NN + 1];
static __device__ int   g_cursor[NN];
static __device__ int   g_csrc[ET];
static __device__ int   g_bsum[256];
static __device__ int   g_boff[256];

__device__ __forceinline__ float leaky(float v) { return v > 0.f ? v : 0.2f * v; }
__device__ __forceinline__ uint32_t cvt_tf32(float f) {
    uint32_t r; asm("cvt.rna.tf32.f32 %0, %1;" : "=r"(r) : "f"(f)); return r;
}

// ---------------- CSR construction ----------------
__global__ void k_zero(int* p, int n) {
    int i = blockIdx.x * blockDim.x + threadIdx.x;
    if (i < n) p[i] = 0;
}

__global__ void k_hist(const int* __restrict__ ei) {
    int i = blockIdx.x * blockDim.x + threadIdx.x;
    if (i >= ET) return;
    int d = (i < NE) ? ei[NE + i] : (i - NE);
    atomicAdd(&g_cnt[d], 1);
}

__device__ __forceinline__ int blk_scan_excl(int v, int* total, int lane, int wid, int nw) {
    __shared__ int wsum[32];
    int x = v;
    #pragma unroll
    for (int o = 1; o < 32; o <<= 1) {
        int y = __shfl_up_sync(0xffffffffu, x, o);
        if (lane >= o) x += y;
    }
    if (lane == 31) wsum[wid] = x;
    __syncthreads();
    if (wid == 0) {
        int w = (lane < nw) ? wsum[lane] : 0;
        #pragma unroll
        for (int o = 1; o < 32; o <<= 1) {
            int y = __shfl_up_sync(0xffffffffu, w, o);
            if (lane >= o) w += y;
        }
        wsum[lane] = w;
    }
    __syncthreads();
    int base = (wid > 0) ? wsum[wid - 1] : 0;
    *total = wsum[nw - 1];
    return base + x - v;
}

__global__ void k_scan1() {
    int tid = threadIdx.x, i = blockIdx.x * 256 + tid;
    int v = (i < NN) ? g_cnt[i] : 0;
    int total;
    int excl = blk_scan_excl(v, &total, tid & 31, tid >> 5, 8);
    if (i < NN) g_rowptr[i] = excl;
    if (tid == 0) g_bsum[blockIdx.x] = total;
}

__global__ void k_scan2(int nblk) {
    int tid = threadIdx.x;
    int v = (tid < nblk) ? g_bsum[tid] : 0;
    int total;
    int excl = blk_scan_excl(v, &total, tid & 31, tid >> 5, 8);
    g_boff[tid] = excl;
    if (tid == 0) g_rowptr[NN] = total;
}

__global__ void k_scan3() {
    int i = blockIdx.x * blockDim.x + threadIdx.x;
    if (i >= NN) return;
    int r = g_rowptr[i] + g_boff[i >> 8];
    g_rowptr[i] = r;
    g_cursor[i] = r;
}

__global__ void k_scatter(const int* __restrict__ ei) {
    int i = blockIdx.x * blockDim.x + threadIdx.x;
    if (i >= ET) return;
    int s, d;
    if (i < NE) { s = ei[i]; d = ei[NE + i]; }
    else        { s = i - NE; d = s; }
    int pos = atomicAdd(&g_cursor[d], 1);
    g_csrc[pos] = s;
}

// ========== unified tf32 mma.sync GEMM: Ch[M,N] = A[M,K] @ W[K,N] ==========
// BM=128, BK=16, 256 threads. BN=128: 8 warps 4m x 2n, warp tile 32x64.
// BN=64: 8 warps 8m x 1n, warp tile 16x64. Each warp owns a FULL 64-col head
// -> fused alpha dots reduce in-warp (deterministic, no atomics).
// Output always fp16. Optional bias+relu (emb). A operand fp32 or fp16.
#define AST 20

__device__ __forceinline__ void mma_tf32(float c[4], const uint32_t a[4], const uint32_t b[2]) {
    asm volatile(
        "mma.sync.aligned.m16n8k8.row.col.f32.tf32.tf32.f32 "
        "{%0,%1,%2,%3}, {%4,%5,%6,%7}, {%8,%9}, {%0,%1,%2,%3};"
        : "+f"(c[0]), "+f"(c[1]), "+f"(c[2]), "+f"(c[3])
        : "r"(a[0]), "r"(a[1]), "r"(a[2]), "r"(a[3]), "r"(b[0]), "r"(b[1]));
}

template<int BN, bool A_HALF, bool BIAS, bool RELU, int ALPHA_H>
__global__ __launch_bounds__(256)
void k_mma(const void* __restrict__ Av, const float* __restrict__ W,
           const float* __restrict__ bias,
           const float* __restrict__ a_src, const float* __restrict__ a_dst,
           __half* __restrict__ Ch, int M, int K, int N) {
    constexpr int BST = BN + 8;
    constexpr int NWN = BN / 64;                 // warps along n: 2 or 1
    constexpr int MT  = (BN == 128) ? 2 : 1;     // 16-row m-tiles per warp
    __shared__ uint32_t As[2][128 * AST];
    __shared__ uint32_t Bs[2][16 * BST];

    const int tid = threadIdx.x;
    const int wid = tid >> 5, lane = tid & 31;
    const int g = lane >> 2, tig = lane & 3;
    const int warp_m = (wid / NWN) * (MT * 16);
    const int warp_n = (wid % NWN) * 64;
    const int m0 = blockIdx.x * 128;
    const int n0 = blockIdx.y * BN;

    float acc[MT][8][4];
    #pragma unroll
    for (int mt = 0; mt < MT; mt++)
        #pragma unroll
        for (int nt = 0; nt < 8; nt++)
            #pragma unroll
            for (int q = 0; q < 4; q++) acc[mt][nt][q] = 0.f;

    // global load mappings
    const int ar = tid >> 1, akh = (tid & 1) << 3;       // A: row, k-offset
    const bool av = (m0 + ar) < M;
    const float*  Apf = (const float*)Av  + (size_t)(m0 + ar) * K + akh;
    const __half* Aph = (const __half*)Av + (size_t)(m0 + ar) * K + akh;
    const int bk = tid >> 4;                              // B: k-row 0..15
    const int bn = (tid & 15) << (BN == 128 ? 3 : 2);     // n-offset
    const float* Wp = W + (size_t)bk * N + n0 + bn;

    const float4 fz = make_float4(0.f, 0.f, 0.f, 0.f);
    float4 fa0, fa1, fb0, fb1;
    uint4  ua = make_uint4(0, 0, 0, 0);

    // ---- prefetch + store helpers (macros keep reg use tight) ----
    #define LOAD_A(k0_) do { \
        if (A_HALF) { ua = av ? *(const uint4*)(Aph + (k0_)) : make_uint4(0,0,0,0); } \
        else { fa0 = av ? *(const float4*)(Apf + (k0_)) : fz; \
               fa1 = av ? *(const float4*)(Apf + (k0_) + 4) : fz; } \
    } while (0)
    #define LOAD_B(k0_) do { \
        fb0 = *(const float4*)(Wp + (size_t)(k0_) * N); \
        if (BN == 128) fb1 = *(const float4*)(Wp + (size_t)(k0_) * N + 4); \
    } while (0)
    #define STORE_AB(bf_) do { \
        float x0,x1,x2,x3,x4,x5,x6,x7; \
        if (A_HALF) { \
            float2 p0 = __half22float2(*(__half2*)&ua.x); \
            float2 p1 = __half22float2(*(__half2*)&ua.y); \
            float2 p2 = __half22float2(*(__half2*)&ua.z); \
            float2 p3 = __half22float2(*(__half2*)&ua.w); \
            x0=p0.x; x1=p0.y; x2=p1.x; x3=p1.y; x4=p2.x; x5=p2.y; x6=p3.x; x7=p3.y; \
        } else { x0=fa0.x; x1=fa0.y; x2=fa0.z; x3=fa0.w; x4=fa1.x; x5=fa1.y; x6=fa1.z; x7=fa1.w; } \
        *(uint4*)&As[bf_][ar * AST + akh]     = make_uint4(cvt_tf32(x0), cvt_tf32(x1), cvt_tf32(x2), cvt_tf32(x3)); \
        *(uint4*)&As[bf_][ar * AST + akh + 4] = make_uint4(cvt_tf32(x4), cvt_tf32(x5), cvt_tf32(x6), cvt_tf32(x7)); \
        *(uint4*)&Bs[bf_][bk * BST + bn] = make_uint4(cvt_tf32(fb0.x), cvt_tf32(fb0.y), cvt_tf32(fb0.z), cvt_tf32(fb0.w)); \
        if (BN == 128) \
            *(uint4*)&Bs[bf_][bk * BST + bn + 4] = make_uint4(cvt_tf32(fb1.x), cvt_tf32(fb1.y), cvt_tf32(fb1.z), cvt_tf32(fb1.w)); \
    } while (0)

    LOAD_A(0); LOAD_B(0);
    STORE_AB(0);
    __syncthreads();

    const int nch = K >> 4;
    int buf = 0;
    for (int c = 1; c <= nch; c++) {
        if (c < nch) { LOAD_A(c << 4); LOAD_B(c << 4); }
        #pragma unroll
        for (int ks = 0; ks < 2; ks++) {
            const int kc = ks << 3;
            uint32_t a[MT][4], b[8][2];
            #pragma unroll
            for (int mt = 0; mt < MT; mt++) {
                int mr = warp_m + (mt << 4) + g;
                a[mt][0] = As[buf][mr * AST + kc + tig];
                a[mt][1] = As[buf][(mr + 8) * AST + kc + tig];
                a[mt][2] = As[buf][mr * AST + kc + tig + 4];
                a[mt][3] = As[buf][(mr + 8) * AST + kc + tig + 4];
            }
            #pragma unroll
            for (int nt = 0; nt < 8; nt++) {
                int nc = warp_n + (nt << 3) + g;
                b[nt][0] = Bs[buf][(kc + tig) * BST + nc];
                b[nt][1] = Bs[buf][(kc + tig + 4) * BST + nc];
            }
            #pragma unroll
            for (int mt = 0; mt < MT; mt++)
                #pragma unroll
                for (int nt = 0; nt < 8; nt++)
                    mma_tf32(acc[mt][nt], a[mt], b[nt]);
        }
        if (c < nch) {
            int nb = buf ^ 1;
            STORE_AB(nb);
            __syncthreads();
            buf = nb;
        }
    }
    #undef LOAD_A
    #undef LOAD_B
    #undef STORE_AB

    // ---- epilogue: bias/relu, fp16 store, fused in-warp alpha dots ----
    #pragma unroll
    for (int mt = 0; mt < MT; mt++) {
        int r0 = m0 + warp_m + (mt << 4) + g;
        int r1 = r0 + 8;
        float ps0 = 0.f, pd0 = 0.f, ps1 = 0.f, pd1 = 0.f;
        #pragma unroll
        for (int nt = 0; nt < 8; nt++) {
            int col = n0 + warp_n + (nt << 3) + (tig << 1);
            float c0 = acc[mt][nt][0], c1 = acc[mt][nt][1];
            float c2 = acc[mt][nt][2], c3 = acc[mt][nt][3];
            if (BIAS) {
                float b0v = __ldg(bias + col), b1v = __ldg(bias + col + 1);
                c0 += b0v; c1 += b1v; c2 += b0v; c3 += b1v;
            }
            if (RELU) {
                c0 = fmaxf(c0, 0.f); c1 = fmaxf(c1, 0.f);
                c2 = fmaxf(c2, 0.f); c3 = fmaxf(c3, 0.f);
            }
            if (r0 < M) *(__half2*)(Ch + (size_t)r0 * N + col) = __floats2half2_rn(c0, c1);
            if (r1 < M) *(__half2*)(Ch + (size_t)r1 * N + col) = __floats2half2_rn(c2, c3);
            if (ALPHA_H > 0) {
                float sa0 = __ldg(a_src + col), sa1 = __ldg(a_src + col + 1);
                float sd0 = __ldg(a_dst + col), sd1 = __ldg(a_dst + col + 1);
                ps0 += c0 * sa0 + c1 * sa1; pd0 += c0 * sd0 + c1 * sd1;
                ps1 += c2 * sa0 + c3 * sa1; pd1 += c2 * sd0 + c3 * sd1;
            }
        }
        if (ALPHA_H > 0) {
            #pragma unroll
            for (int o = 1; o < 4; o <<= 1) {
                ps0 += __shfl_xor_sync(0xffffffffu, ps0, o);
                pd0 += __shfl_xor_sync(0xffffffffu, pd0, o);
                ps1 += __shfl_xor_sync(0xffffffffu, ps1, o);
                pd1 += __shfl_xor_sync(0xffffffffu, pd1, o);
            }
            if (tig == 0) {
                int head = (n0 + warp_n) >> 6;
                if (r0 < M) { g_as[r0 * ALPHA_H + head] = ps0; g_ad[r0 * ALPHA_H + head] = pd0; }
                if (r1 < M) { g_as[r1 * ALPHA_H + head] = ps1; g_ad[r1 * ALPHA_H + head] = pd1; }
            }
        }
    }
}

// ---------- single-pass softmax aggregation over fp16 h ----------
template<int H, bool RELU, bool OUT_HALF, bool FUSE_MLP>
__global__ void k_agg(const __half* __restrict__ h, const float* __restrict__ bias,
                      void* __restrict__ outv,
                      const float* __restrict__ Wo1, const float* __restrict__ bo1,
                      const float* __restrict__ Wo2, const float* __restrict__ bo2) {
    constexpr int HC = H * 64, EPL = HC / 32, LPH = 32 / H;
    __shared__ float sW1[FUSE_MLP ? 64 * 32 : 1];
    __shared__ float sW2[FUSE_MLP ? 32 : 1];
    __shared__ float sb1[FUSE_MLP ? 32 : 1];
    if (FUSE_MLP) {
        for (int i = threadIdx.x; i < 64 * 32; i += blockDim.x) sW1[i] = Wo1[i];
        if (threadIdx.x < 32) { sW2[threadIdx.x] = Wo2[threadIdx.x]; sb1[threadIdx.x] = bo1[threadIdx.x]; }
        __syncthreads();
    }
    const int gw = (blockIdx.x * blockDim.x + threadIdx.x) >> 5;
    const int lane = threadIdx.x & 31;
    if (gw >= NN) return;
    const int beg = g_rowptr[gw], end = g_rowptr[gw + 1];
    const int head = lane / LPH;
    const float adv = g_ad[gw * H + head];

    float ws = 0.f;
    float acc[EPL];
    #pragma unroll
    for (int k = 0; k < EPL; k++) acc[k] = 0.f;
    const __half* hb = h + lane * EPL;

    int i = beg;
    if constexpr (EPL == 8) {
        // 4-edge unroll for MLP
        for (; i + 4 <= end; i += 4) {
            int s0 = g_csrc[i],     s1 = g_csrc[i + 1];
            int s2 = g_csrc[i + 2], s3 = g_csrc[i + 3];
            float a0 = g_as[s0 * H + head], a1 = g_as[s1 * H + head];
            float a2 = g_as[s2 * H + head], a3 = g_as[s3 * H + head];
            uint4 u0 = *(const uint4*)(hb + (size_t)s0 * HC);
            uint4 u1 = *(const uint4*)(hb + (size_t)s1 * HC);
            uint4 u2 = *(const uint4*)(hb + (size_t)s2 * HC);
            uint4 u3 = *(const uint4*)(hb + (size_t)s3 * HC);
            float e0 = __expf(leaky(a0 + adv));
            float e1 = __expf(leaky(a1 + adv));
            float e2 = __expf(leaky(a2 + adv));
            float e3 = __expf(leaky(a3 + adv));
            ws += e0 + e1 + e2 + e3;
            float2 p;
            p = __half22float2(*(__half2*)&u0.x); acc[0] += e0 * p.x; acc[1] += e0 * p.y;
            p = __half22float2(*(__half2*)&u0.y); acc[2] += e0 * p.x; acc[3] += e0 * p.y;
            p = __half22float2(*(__half2*)&u0.z); acc[4] += e0 * p.x; acc[5] += e0 * p.y;
            p = __half22float2(*(__half2*)&u0.w); acc[6] += e0 * p.x; acc[7] += e0 * p.y;
            p = __half22float2(*(__half2*)&u1.x); acc[0] += e1 * p.x; acc[1] += e1 * p.y;
            p = __half22float2(*(__half2*)&u1.y); acc[2] += e1 * p.x; acc[3] += e1 * p.y;
            p = __half22float2(*(__half2*)&u1.z); acc[4] += e1 * p.x; acc[5] += e1 * p.y;
            p = __half22float2(*(__half2*)&u1.w); acc[6] += e1 * p.x; acc[7] += e1 * p.y;
            p = __half22float2(*(__half2*)&u2.x); acc[0] += e2 * p.x; acc[1] += e2 * p.y;
            p = __half22float2(*(__half2*)&u2.y); acc[2] += e2 * p.x; acc[3] += e2 * p.y;
            p = __half22float2(*(__half2*)&u2.z); acc[4] += e2 * p.x; acc[5] += e2 * p.y;
            p = __half22float2(*(__half2*)&u2.w); acc[6] += e2 * p.x; acc[7] += e2 * p.y;
            p = __half22float2(*(__half2*)&u3.x); acc[0] += e3 * p.x; acc[1] += e3 * p.y;
            p = __half22float2(*(__half2*)&u3.y); acc[2] += e3 * p.x; acc[3] += e3 * p.y;
            p = __half22float2(*(__half2*)&u3.z); acc[4] += e3 * p.x; acc[5] += e3 * p.y;
            p = __half22float2(*(__half2*)&u3.w); acc[6] += e3 * p.x; acc[7] += e3 * p.y;
        }
        for (; i < end; i++) {
            int s = g_csrc[i];
            float e = __expf(leaky(g_as[s * H + head] + adv));
            ws += e;
            uint4 u0 = *(const uint4*)(hb + (size_t)s * HC);
            float2 p;
            p = __half22float2(*(__half2*)&u0.x); acc[0] += e * p.x; acc[1] += e * p.y;
            p = __half22float2(*(__half2*)&u0.y); acc[2] += e * p.x; acc[3] += e * p.y;
            p = __half22float2(*(__half2*)&u0.z); acc[4] += e * p.x; acc[5] += e * p.y;
            p = __half22float2(*(__half2*)&u0.w); acc[6] += e * p.x; acc[7] += e * p.y;
        }
    } else {
        for (; i + 2 <= end; i += 2) {
            int s0 = g_csrc[i], s1 = g_csrc[i + 1];
            float a0 = g_as[s0 * H + head];
            float a1 = g_as[s1 * H + head];
            float2 v0 = __half22float2(*(const __half2*)(hb + (size_t)s0 * HC));
            float2 v1 = __half22float2(*(const __half2*)(hb + (size_t)s1 * HC));
            float e0 = __expf(leaky(a0 + adv));
            float e1 = __expf(leaky(a1 + adv));
            ws += e0 + e1;
            acc[0] += e0 * v0.x + e1 * v1.x;
            acc[1] += e0 * v0.y + e1 * v1.y;
        }
        if (i < end) {
            int s = g_csrc[i];
            float e = __expf(leaky(g_as[s * H + head] + adv));
            ws += e;
            float2 v0 = __half22float2(*(const __half2*)(hb + (size_t)s * HC));
            acc[0] += e * v0.x; acc[1] += e * v0.y;
        }
    }

    const float rinv = 1.f / ws;
    const float* bp = bias + lane * EPL;
    #pragma unroll
    for (int k = 0; k < EPL; k++) {
        float v = acc[k] * rinv + bp[k];
        if (RELU) v = fmaxf(v, 0.f);
        acc[k] = v;
    }

    if constexpr (FUSE_MLP) {
        float v0 = acc[0], v1 = acc[1];
        float hid = sb1[lane];
        #pragma unroll
        for (int k = 0; k < 32; k++) {
            float r0 = __shfl_sync(0xffffffffu, v0, k);
            float r1 = __shfl_sync(0xffffffffu, v1, k);
            hid = fmaf(r0, sW1[(2 * k) * 32 + lane], hid);
            hid = fmaf(r1, sW1[(2 * k + 1) * 32 + lane], hid);
        }
        hid = fmaxf(hid, 0.f);
        float o = hid * sW2[lane];
        #pragma unroll
        for (int w = 1; w < 32; w <<= 1) o += __shfl_xor_sync(0xffffffffu, o, w);
        if (lane == 0) ((float*)outv)[gw] = o + bo2[0];
    } else if constexpr (OUT_HALF) {
        __half* op = (__half*)outv + (size_t)gw * HC + lane * EPL;
        __half2 h0 = __floats2half2_rn(acc[0], acc[1]);
        __half2 h1 = __floats2half2_rn(acc[2], acc[3]);
        __half2 h2 = __floats2half2_rn(acc[4], acc[5]);
        __half2 h3 = __floats2half2_rn(acc[6], acc[7]);
        *(uint4*)op = make_uint4(*(uint32_t*)&h0, *(uint32_t*)&h1,
                                 *(uint32_t*)&h2, *(uint32_t*)&h3);
    } else {
        float* op = (float*)outv + (size_t)gw * HC + lane * EPL;
        #pragma unroll
        for (int k = 0; k < EPL; k += 4)
            *(float4*)(op + k) = make_float4(acc[k], acc[k + 1], acc[k + 2], acc[k + 3]);
    }
}

// ---------------- launch ----------------
extern "C" void kernel_launch(void* const* d_in, const int* in_sizes, int n_in,
                              void* d_out, int out_size) {
    const float* x     = (const float*)d_in[0];
    const float* W_emb = (const float*)d_in[1];
    const float* b_emb = (const float*)d_in[2];
    const float* W0    = (const float*)d_in[3];
    const float* as0   = (const float*)d_in[4];
    const float* ad0   = (const float*)d_in[5];
    const float* b0    = (const float*)d_in[6];
    const float* W1    = (const float*)d_in[7];
    const float* as1   = (const float*)d_in[8];
    const float* ad1   = (const float*)d_in[9];
    const float* b1    = (const float*)d_in[10];
    const float* W2    = (const float*)d_in[11];
    const float* as2   = (const float*)d_in[12];
    const float* ad2   = (const float*)d_in[13];
    const float* b2    = (const float*)d_in[14];
    const float* Wo1   = (const float*)d_in[15];
    const float* bo1   = (const float*)d_in[16];
    const float* Wo2   = (const float*)d_in[17];
    const float* bo2   = (const float*)d_in[18];
    const int*   ei    = (const int*)d_in[19];
    float* out = (float*)d_out;

    float *p_h0, *p_hA, *p_hB;
    int* p_cnt;
    cudaGetSymbolAddress((void**)&p_h0, g_h0);
    cudaGetSymbolAddress((void**)&p_hA, g_hA);
    cudaGetSymbolAddress((void**)&p_hB, g_hB);
    cudaGetSymbolAddress((void**)&p_cnt, g_cnt);
    __half* p_h0h = (__half*)p_h0;
    __half* p_hAh = (__half*)p_hA;
    __half* p_hBh = (__half*)p_hB;

    const int MB = (NN + 127) / 128;               // 391 row tiles
    const int SCAN_BLK = (NN + 255) / 256;         // 196
    const int WARP_GRID = (NN * 32 + 255) / 256;
    const int WARP_GRID512 = (NN * 32 + 511) / 512;

    // [0] embedding: relu(x @ W_emb + b_emb) -> fp16 h0
    k_mma<64, false, true, true, 0><<<dim3(MB, 1), 256>>>(
        x, W_emb, b_emb, nullptr, nullptr, p_h0h, NN, FIN, HID);

    k_zero<<<(NN + 255) / 256, 256>>>(p_cnt, NN);                 // [1]
    k_hist<<<(ET + 255) / 256, 256>>>(ei);                        // [2]

    // [3] (profiled) GAT layer 0 GEMM + fused alpha: hA = h0 @ W0
    k_mma<128, true, false, false, 4><<<dim3(MB, 2), 256>>>(
        p_h0h, W0, nullptr, as0, ad0, p_hAh, NN, HID, 256);

    k_scan1<<<SCAN_BLK, 256>>>();                                 // [4]
    k_scan2<<<1, 256>>>(SCAN_BLK);                                // [5]
    k_scan3<<<SCAN_BLK, 256>>>();                                 // [6]
    k_scatter<<<(ET + 255) / 256, 256>>>(ei);                     // [7]

    // [8] layer-0 aggregation (fp16 gather -> fp16 hB)
    k_agg<4, true, true, false><<<WARP_GRID, 256>>>(p_hAh, b0, p_hBh,
        nullptr, nullptr, nullptr, nullptr);

    // [9] GAT layer 1 GEMM + fused alpha
    k_mma<128, true, false, false, 4><<<dim3(MB, 2), 256>>>(
        p_hBh, W1, nullptr, as1, ad1, p_hAh, NN, HEADS * HID, 256);
    // [10] layer-1 aggregation
    k_agg<4, true, true, false><<<WARP_GRID, 256>>>(p_hAh, b1, p_hBh,
        nullptr, nullptr, nullptr, nullptr);

    // [11] GAT layer 2 GEMM (N=64) + fused alpha (H=1)
    k_mma<64, true, false, false, 1><<<dim3(MB, 1), 256>>>(
        p_hBh, W2, nullptr, as2, ad2, p_hAh, NN, HEADS * HID, HID);
    // [12] layer-2 aggregation + fused output MLP
    k_agg<1, false, false, true><<<WARP_GRID512, 512>>>(p_hAh, b2, out,
        Wo1, bo1, Wo2, bo2);
}

// round 12
// speedup vs baseline: 2.1976x; 1.0330x over previous
#include <cuda_runtime.h>
#include <cuda_fp16.h>
#include <cstdint>

#define NN 50000
#define NE 800000
#define ET 850000            // NE + NN self loops
#define FIN 128
#define HID 64
#define HEADS 4
#define MBX 391              // (NN+127)/128
#define SCAN_BLK 196         // (NN+255)/256
#define HB 416               // ceil(ET/2048) hist blocks

// ---------------- device scratch (static allocation only) ----------------
// All zero-initialized at module load; g_cnt / g_cur2 / g_tk are
// SELF-RESTORING each launch (scan zeroes cnt, agg0 zeroes cur2, last scan
// block zeroes the ticket), so every graph replay starts from the same state.
static __device__ float g_h0[NN * HID];            // used as half [NN][64]
static __device__ float g_hA[NN * HEADS * HID];    // used as half [NN][256]
static __device__ float g_hB[NN * HEADS * HID];    // used as half [NN][256]
static __device__ float g_as[NN * HEADS];
static __device__ float g_ad[NN * HEADS];
static __device__ int   g_cnt[NN];
static __device__ int   g_rowptr[NN + 1];          // block-local exclusive scan
static __device__ int   g_cur2[NN];                // scatter cursors
static __device__ int   g_csrc[ET];
static __device__ int   g_bsum[256];
static __device__ int   g_boff[256];
static __device__ int   g_tk;                      // scan ticket

__device__ __forceinline__ float leaky(float v) { return v > 0.f ? v : 0.2f * v; }
__device__ __forceinline__ uint32_t cvt_tf32(float f) {
    uint32_t r; asm("cvt.rna.tf32.f32 %0, %1;" : "=r"(r) : "f"(f)); return r;
}

// ---------------- block scan helper ----------------
__device__ __forceinline__ int blk_scan_excl(int v, int* total, int lane, int wid, int nw) {
    __shared__ int wsum[32];
    int x = v;
    #pragma unroll
    for (int o = 1; o < 32; o <<= 1) {
        int y = __shfl_up_sync(0xffffffffu, x, o);
        if (lane >= o) x += y;
    }
    if (lane == 31) wsum[wid] = x;
    __syncthreads();
    if (wid == 0) {
        int w = (lane < nw) ? wsum[lane] : 0;
        #pragma unroll
        for (int o = 1; o < 32; o <<= 1) {
            int y = __shfl_up_sync(0xffffffffu, w, o);
            if (lane >= o) w += y;
        }
        wsum[lane] = w;
    }
    __syncthreads();
    int base = (wid > 0) ? wsum[wid - 1] : 0;
    *total = wsum[nw - 1];
    return base + x - v;
}

// scan1 body + inline scan2 in the last-arriving block (ticket pattern)
__device__ void scan_body(int b) {
    int tid = threadIdx.x;
    int i = b * 256 + tid;
    int v = (i < NN) ? g_cnt[i] : 0;
    int total;
    int excl = blk_scan_excl(v, &total, tid & 31, tid >> 5, 8);
    if (i < NN) { g_rowptr[i] = excl; g_cnt[i] = 0; }   // restore cnt for next replay
    __shared__ int s_last;
    if (tid == 0) {
        g_bsum[b] = total;
        __threadfence();
        int t = atomicAdd(&g_tk, 1);
        s_last = (t == SCAN_BLK - 1) ? 1 : 0;
    }
    __syncthreads();
    if (s_last) {
        int v2 = (tid < SCAN_BLK) ? g_bsum[tid] : 0;
        int tot2;
        int e2 = blk_scan_excl(v2, &tot2, tid & 31, tid >> 5, 8);
        g_boff[tid] = e2;
        if (tid == 0) g_tk = 0;                         // restore ticket
    }
}

// ========== unified tf32 mma.sync body: Ch[M,N] = A[M,K] @ W[K,N] ==========
// BM=128, BK=16, 256 threads. BN=128: 8 warps 4m x 2n (warp 32x64).
// BN=64: 8 warps 8m x 1n (warp 16x64). Warp owns a full 64-col head ->
// fused alpha dots reduce in-warp. fp16 output. A operand fp32 or fp16.
// A smem uses paired-k layout (k%8 order 0,4,1,5,2,6,3,7) so each a-fragment
// pair (tig,tig+4) is one LDS.64; AST=24 keeps phases conflict-free.
#define AST 24

__device__ __forceinline__ void mma_tf32(float c[4], const uint32_t a[4], const uint32_t b[2]) {
    asm volatile(
        "mma.sync.aligned.m16n8k8.row.col.f32.tf32.tf32.f32 "
        "{%0,%1,%2,%3}, {%4,%5,%6,%7}, {%8,%9}, {%0,%1,%2,%3};"
        : "+f"(c[0]), "+f"(c[1]), "+f"(c[2]), "+f"(c[3])
        : "r"(a[0]), "r"(a[1]), "r"(a[2]), "r"(a[3]), "r"(b[0]), "r"(b[1]));
}

template<int BN, bool A_HALF, bool BIAS, bool RELU, int ALPHA_H>
__device__ __forceinline__ void mma_body(
    int bx, int by,
    const void* __restrict__ Av, const float* __restrict__ W,
    const float* __restrict__ bias,
    const float* __restrict__ a_src, const float* __restrict__ a_dst,
    __half* __restrict__ Ch, int M, int K, int N)
{
    constexpr int BST = BN + 8;
    constexpr int NWN = BN / 64;
    constexpr int MT  = (BN == 128) ? 2 : 1;
    __shared__ __align__(16) uint32_t As[2][128 * AST];
    __shared__ __align__(16) uint32_t Bs[2][16 * BST];

    const int tid = threadIdx.x;
    const int wid = tid >> 5, lane = tid & 31;
    const int g = lane >> 2, tig = lane & 3;
    const int warp_m = (wid / NWN) * (MT * 16);
    const int warp_n = (wid % NWN) * 64;
    const int m0 = bx * 128;
    const int n0 = by * BN;

    float acc[MT][8][4];
    #pragma unroll
    for (int mt = 0; mt < MT; mt++)
        #pragma unroll
        for (int nt = 0; nt < 8; nt++)
            #pragma unroll
            for (int q = 0; q < 4; q++) acc[mt][nt][q] = 0.f;

    const int ar = tid >> 1, akh = (tid & 1) << 3;
    const bool av = (m0 + ar) < M;
    const float*  Apf = (const float*)Av  + (size_t)(m0 + ar) * K + akh;
    const __half* Aph = (const __half*)Av + (size_t)(m0 + ar) * K + akh;
    const int bk = tid >> 4;
    const int bn = (tid & 15) << (BN == 128 ? 3 : 2);
    const float* Wp = W + (size_t)bk * N + n0 + bn;

    const float4 fz = make_float4(0.f, 0.f, 0.f, 0.f);
    float4 fa0, fa1, fb0, fb1;
    uint4  ua = make_uint4(0, 0, 0, 0);

    #define LOAD_A(k0_) do { \
        if (A_HALF) { ua = av ? *(const uint4*)(Aph + (k0_)) : make_uint4(0,0,0,0); } \
        else { fa0 = av ? *(const float4*)(Apf + (k0_)) : fz; \
               fa1 = av ? *(const float4*)(Apf + (k0_) + 4) : fz; } \
    } while (0)
    #define LOAD_B(k0_) do { \
        fb0 = *(const float4*)(Wp + (size_t)(k0_) * N); \
        if (BN == 128) fb1 = *(const float4*)(Wp + (size_t)(k0_) * N + 4); \
    } while (0)
    // paired-k A store: positions get k order 0,4,1,5 | 2,6,3,7
    #define STORE_AB(bf_) do { \
        float x0,x1,x2,x3,x4,x5,x6,x7; \
        if (A_HALF) { \
            float2 p0 = __half22float2(*(__half2*)&ua.x); \
            float2 p1 = __half22float2(*(__half2*)&ua.y); \
            float2 p2 = __half22float2(*(__half2*)&ua.z); \
            float2 p3 = __half22float2(*(__half2*)&ua.w); \
            x0=p0.x; x1=p0.y; x2=p1.x; x3=p1.y; x4=p2.x; x5=p2.y; x6=p3.x; x7=p3.y; \
        } else { x0=fa0.x; x1=fa0.y; x2=fa0.z; x3=fa0.w; x4=fa1.x; x5=fa1.y; x6=fa1.z; x7=fa1.w; } \
        *(uint4*)&As[bf_][ar * AST + akh]     = make_uint4(cvt_tf32(x0), cvt_tf32(x4), cvt_tf32(x1), cvt_tf32(x5)); \
        *(uint4*)&As[bf_][ar * AST + akh + 4] = make_uint4(cvt_tf32(x2), cvt_tf32(x6), cvt_tf32(x3), cvt_tf32(x7)); \
        *(uint4*)&Bs[bf_][bk * BST + bn] = make_uint4(cvt_tf32(fb0.x), cvt_tf32(fb0.y), cvt_tf32(fb0.z), cvt_tf32(fb0.w)); \
        if (BN == 128) \
            *(uint4*)&Bs[bf_][bk * BST + bn + 4] = make_uint4(cvt_tf32(fb1.x), cvt_tf32(fb1.y), cvt_tf32(fb1.z), cvt_tf32(fb1.w)); \
    } while (0)

    LOAD_A(0); LOAD_B(0);
    STORE_AB(0);
    __syncthreads();

    const int nch = K >> 4;
    int buf = 0;
    for (int c = 1; c <= nch; c++) {
        if (c < nch) { LOAD_A(c << 4); LOAD_B(c << 4); }
        #pragma unroll
        for (int ks = 0; ks < 2; ks++) {
            const int kc = ks << 3;
            uint32_t a[MT][4], b[8][2];
            #pragma unroll
            for (int mt = 0; mt < MT; mt++) {
                int mr = warp_m + (mt << 4) + g;
                uint2 pa0 = *(const uint2*)&As[buf][mr * AST + kc + (tig << 1)];
                uint2 pa1 = *(const uint2*)&As[buf][(mr + 8) * AST + kc + (tig << 1)];
                a[mt][0] = pa0.x; a[mt][2] = pa0.y;
                a[mt][1] = pa1.x; a[mt][3] = pa1.y;
            }
            #pragma unroll
            for (int nt = 0; nt < 8; nt++) {
                int nc = warp_n + (nt << 3) + g;
                b[nt][0] = Bs[buf][(kc + tig) * BST + nc];
                b[nt][1] = Bs[buf][(kc + tig + 4) * BST + nc];
            }
            #pragma unroll
            for (int mt = 0; mt < MT; mt++)
                #pragma unroll
                for (int nt = 0; nt < 8; nt++)
                    mma_tf32(acc[mt][nt], a[mt], b[nt]);
        }
        if (c < nch) {
            int nb = buf ^ 1;
            STORE_AB(nb);
            __syncthreads();
            buf = nb;
        }
    }
    #undef LOAD_A
    #undef LOAD_B
    #undef STORE_AB

    // ---- epilogue: bias/relu, fp16 store, fused in-warp alpha dots ----
    #pragma unroll
    for (int mt = 0; mt < MT; mt++) {
        int r0 = m0 + warp_m + (mt << 4) + g;
        int r1 = r0 + 8;
        float ps0 = 0.f, pd0 = 0.f, ps1 = 0.f, pd1 = 0.f;
        #pragma unroll
        for (int nt = 0; nt < 8; nt++) {
            int col = n0 + warp_n + (nt << 3) + (tig << 1);
            float c0 = acc[mt][nt][0], c1 = acc[mt][nt][1];
            float c2 = acc[mt][nt][2], c3 = acc[mt][nt][3];
            if (BIAS) {
                float b0v = __ldg(bias + col), b1v = __ldg(bias + col + 1);
                c0 += b0v; c1 += b1v; c2 += b0v; c3 += b1v;
            }
            if (RELU) {
                c0 = fmaxf(c0, 0.f); c1 = fmaxf(c1, 0.f);
                c2 = fmaxf(c2, 0.f); c3 = fmaxf(c3, 0.f);
            }
            if (r0 < M) *(__half2*)(Ch + (size_t)r0 * N + col) = __floats2half2_rn(c0, c1);
            if (r1 < M) *(__half2*)(Ch + (size_t)r1 * N + col) = __floats2half2_rn(c2, c3);
            if (ALPHA_H > 0) {
                float sa0 = __ldg(a_src + col), sa1 = __ldg(a_src + col + 1);
                float sd0 = __ldg(a_dst + col), sd1 = __ldg(a_dst + col + 1);
                ps0 += c0 * sa0 + c1 * sa1; pd0 += c0 * sd0 + c1 * sd1;
                ps1 += c2 * sa0 + c3 * sa1; pd1 += c2 * sd0 + c3 * sd1;
            }
        }
        if (ALPHA_H > 0) {
            #pragma unroll
            for (int o = 1; o < 4; o <<= 1) {
                ps0 += __shfl_xor_sync(0xffffffffu, ps0, o);
                pd0 += __shfl_xor_sync(0xffffffffu, pd0, o);
                ps1 += __shfl_xor_sync(0xffffffffu, ps1, o);
                pd1 += __shfl_xor_sync(0xffffffffu, pd1, o);
            }
            if (tig == 0) {
                int head = (n0 + warp_n) >> 6;
                if (r0 < M) { g_as[r0 * ALPHA_H + head] = ps0; g_ad[r0 * ALPHA_H + head] = pd0; }
                if (r1 < M) { g_as[r1 * ALPHA_H + head] = ps1; g_ad[r1 * ALPHA_H + head] = pd1; }
            }
        }
    }
}

// ---------------- combined kernels ----------------
// [0] embedding GEMM + edge histogram riding as extra blocks
__global__ __launch_bounds__(256)
void k_emb_hist(const float* __restrict__ x, const float* __restrict__ W_emb,
                const float* __restrict__ b_emb, __half* __restrict__ h0,
                const int* __restrict__ ei) {
    if ((int)blockIdx.x < MBX) {
        mma_body<64, false, true, true, 0>(blockIdx.x, 0, x, W_emb, b_emb,
                                           nullptr, nullptr, h0, NN, FIN, HID);
    } else {
        int base = (blockIdx.x - MBX) * 2048 + threadIdx.x;
        #pragma unroll
        for (int j = 0; j < 8; j++) {
            int i = base + j * 256;
            if (i < ET) {
                int d = (i < NE) ? ei[NE + i] : (i - NE);
                atomicAdd(&g_cnt[d], 1);
            }
        }
    }
}

// [1] L0 GEMM + scan blocks riding (scan2 inline in last block)
__global__ __launch_bounds__(256)
void k_l0_scan(const __half* __restrict__ h0, const float* __restrict__ W0,
               const float* __restrict__ as0, const float* __restrict__ ad0,
               __half* __restrict__ hA) {
    if ((int)blockIdx.x < 2 * MBX) {
        mma_body<128, true, false, false, 4>(blockIdx.x >> 1, blockIdx.x & 1,
                                             h0, W0, nullptr, as0, ad0, hA, NN, HID, 256);
    } else {
        scan_body(blockIdx.x - 2 * MBX);
    }
}

// standalone GEMM wrapper (L1, L2)
template<int BN, bool A_HALF, int ALPHA_H>
__global__ __launch_bounds__(256)
void k_mma(const void* __restrict__ Av, const float* __restrict__ W,
           const float* __restrict__ a_src, const float* __restrict__ a_dst,
           __half* __restrict__ Ch, int M, int K, int N) {
    mma_body<BN, A_HALF, false, false, ALPHA_H>(blockIdx.x, blockIdx.y, Av, W,
                                                nullptr, a_src, a_dst, Ch, M, K, N);
}

// [2] scatter: final rowptr computed on the fly (scan3 folded in)
__global__ void k_scatter(const int* __restrict__ ei) {
    int i = blockIdx.x * blockDim.x + threadIdx.x;
    if (i >= ET) return;
    int s, d;
    if (i < NE) { s = ei[i]; d = ei[NE + i]; }
    else        { s = i - NE; d = s; }
    int pos = g_rowptr[d] + g_boff[d >> 8] + atomicAdd(&g_cur2[d], 1);
    g_csrc[pos] = s;
}

// ---------- single-pass softmax aggregation over fp16 h ----------
template<int H, bool RELU, bool OUT_HALF, bool FUSE_MLP, bool RESTORE>
__global__ void k_agg(const __half* __restrict__ h, const float* __restrict__ bias,
                      void* __restrict__ outv,
                      const float* __restrict__ Wo1, const float* __restrict__ bo1,
                      const float* __restrict__ Wo2, const float* __restrict__ bo2) {
    constexpr int HC = H * 64, EPL = HC / 32, LPH = 32 / H;
    __shared__ float sW1[FUSE_MLP ? 64 * 32 : 1];
    __shared__ float sW2[FUSE_MLP ? 32 : 1];
    __shared__ float sb1[FUSE_MLP ? 32 : 1];
    if (FUSE_MLP) {
        for (int i = threadIdx.x; i < 64 * 32; i += blockDim.x) sW1[i] = Wo1[i];
        if (threadIdx.x < 32) { sW2[threadIdx.x] = Wo2[threadIdx.x]; sb1[threadIdx.x] = bo1[threadIdx.x]; }
        __syncthreads();
    }
    const int gw = (blockIdx.x * blockDim.x + threadIdx.x) >> 5;
    const int lane = threadIdx.x & 31;
    if (gw >= NN) return;
    const int beg = g_rowptr[gw] + g_boff[gw >> 8];
    const int end = (gw == NN - 1) ? ET : (g_rowptr[gw + 1] + g_boff[(gw + 1) >> 8]);
    if (RESTORE && lane == 0) g_cur2[gw] = 0;   // restore scatter cursor for next replay
    const int head = lane / LPH;
    const float adv = g_ad[gw * H + head];

    float ws = 0.f;
    float acc[EPL];
    #pragma unroll
    for (int k = 0; k < EPL; k++) acc[k] = 0.f;
    const __half* hb = h + lane * EPL;

    int i = beg;
    if constexpr (EPL == 8) {
        for (; i + 4 <= end; i += 4) {
            int s0 = g_csrc[i],     s1 = g_csrc[i + 1];
            int s2 = g_csrc[i + 2], s3 = g_csrc[i + 3];
            float a0 = g_as[s0 * H + head], a1 = g_as[s1 * H + head];
            float a2 = g_as[s2 * H + head], a3 = g_as[s3 * H + head];
            uint4 u0 = *(const uint4*)(hb + (size_t)s0 * HC);
            uint4 u1 = *(const uint4*)(hb + (size_t)s1 * HC);
            uint4 u2 = *(const uint4*)(hb + (size_t)s2 * HC);
            uint4 u3 = *(const uint4*)(hb + (size_t)s3 * HC);
            float e0 = __expf(leaky(a0 + adv));
            float e1 = __expf(leaky(a1 + adv));
            float e2 = __expf(leaky(a2 + adv));
            float e3 = __expf(leaky(a3 + adv));
            ws += e0 + e1 + e2 + e3;
            float2 p;
            p = __half22float2(*(__half2*)&u0.x); acc[0] += e0 * p.x; acc[1] += e0 * p.y;
            p = __half22float2(*(__half2*)&u0.y); acc[2] += e0 * p.x; acc[3] += e0 * p.y;
            p = __half22float2(*(__half2*)&u0.z); acc[4] += e0 * p.x; acc[5] += e0 * p.y;
            p = __half22float2(*(__half2*)&u0.w); acc[6] += e0 * p.x; acc[7] += e0 * p.y;
            p = __half22float2(*(__half2*)&u1.x); acc[0] += e1 * p.x; acc[1] += e1 * p.y;
            p = __half22float2(*(__half2*)&u1.y); acc[2] += e1 * p.x; acc[3] += e1 * p.y;
            p = __half22float2(*(__half2*)&u1.z); acc[4] += e1 * p.x; acc[5] += e1 * p.y;
            p = __half22float2(*(__half2*)&u1.w); acc[6] += e1 * p.x; acc[7] += e1 * p.y;
            p = __half22float2(*(__half2*)&u2.x); acc[0] += e2 * p.x; acc[1] += e2 * p.y;
            p = __half22float2(*(__half2*)&u2.y); acc[2] += e2 * p.x; acc[3] += e2 * p.y;
            p = __half22float2(*(__half2*)&u2.z); acc[4] += e2 * p.x; acc[5] += e2 * p.y;
            p = __half22float2(*(__half2*)&u2.w); acc[6] += e2 * p.x; acc[7] += e2 * p.y;
            p = __half22float2(*(__half2*)&u3.x); acc[0] += e3 * p.x; acc[1] += e3 * p.y;
            p = __half22float2(*(__half2*)&u3.y); acc[2] += e3 * p.x; acc[3] += e3 * p.y;
            p = __half22float2(*(__half2*)&u3.z); acc[4] += e3 * p.x; acc[5] += e3 * p.y;
            p = __half22float2(*(__half2*)&u3.w); acc[6] += e3 * p.x; acc[7] += e3 * p.y;
        }
        for (; i < end; i++) {
            int s = g_csrc[i];
            float e = __expf(leaky(g_as[s * H + head] + adv));
            ws += e;
            uint4 u0 = *(const uint4*)(hb + (size_t)s * HC);
            float2 p;
            p = __half22float2(*(__half2*)&u0.x); acc[0] += e * p.x; acc[1] += e * p.y;
            p = __half22float2(*(__half2*)&u0.y); acc[2] += e * p.x; acc[3] += e * p.y;
            p = __half22float2(*(__half2*)&u0.z); acc[4] += e * p.x; acc[5] += e * p.y;
            p = __half22float2(*(__half2*)&u0.w); acc[6] += e * p.x; acc[7] += e * p.y;
        }
    } else {
        for (; i + 2 <= end; i += 2) {
            int s0 = g_csrc[i], s1 = g_csrc[i + 1];
            float a0 = g_as[s0 * H + head];
            float a1 = g_as[s1 * H + head];
            float2 v0 = __half22float2(*(const __half2*)(hb + (size_t)s0 * HC));
            float2 v1 = __half22float2(*(const __half2*)(hb + (size_t)s1 * HC));
            float e0 = __expf(leaky(a0 + adv));
            float e1 = __expf(leaky(a1 + adv));
            ws += e0 + e1;
            acc[0] += e0 * v0.x + e1 * v1.x;
            acc[1] += e0 * v0.y + e1 * v1.y;
        }
        if (i < end) {
            int s = g_csrc[i];
            float e = __expf(leaky(g_as[s * H + head] + adv));
            ws += e;
            float2 v0 = __half22float2(*(const __half2*)(hb + (size_t)s * HC));
            acc[0] += e * v0.x; acc[1] += e * v0.y;
        }
    }

    const float rinv = 1.f / ws;
    const float* bp = bias + lane * EPL;
    #pragma unroll
    for (int k = 0; k < EPL; k++) {
        float v = acc[k] * rinv + bp[k];
        if (RELU) v = fmaxf(v, 0.f);
        acc[k] = v;
    }

    if constexpr (FUSE_MLP) {
        float v0 = acc[0], v1 = acc[1];
        float hid = sb1[lane];
        #pragma unroll
        for (int k = 0; k < 32; k++) {
            float r0 = __shfl_sync(0xffffffffu, v0, k);
            float r1 = __shfl_sync(0xffffffffu, v1, k);
            hid = fmaf(r0, sW1[(2 * k) * 32 + lane], hid);
            hid = fmaf(r1, sW1[(2 * k + 1) * 32 + lane], hid);
        }
        hid = fmaxf(hid, 0.f);
        float o = hid * sW2[lane];
        #pragma unroll
        for (int w = 1; w < 32; w <<= 1) o += __shfl_xor_sync(0xffffffffu, o, w);
        if (lane == 0) ((float*)outv)[gw] = o + bo2[0];
    } else if constexpr (OUT_HALF) {
        __half* op = (__half*)outv + (size_t)gw * HC + lane * EPL;
        __half2 h0 = __floats2half2_rn(acc[0], acc[1]);
        __half2 h1 = __floats2half2_rn(acc[2], acc[3]);
        __half2 h2 = __floats2half2_rn(acc[4], acc[5]);
        __half2 h3 = __floats2half2_rn(acc[6], acc[7]);
        *(uint4*)op = make_uint4(*(uint32_t*)&h0, *(uint32_t*)&h1,
                                 *(uint32_t*)&h2, *(uint32_t*)&h3);
    } else {
        float* op = (float*)outv + (size_t)gw * HC + lane * EPL;
        #pragma unroll
        for (int k = 0; k < EPL; k += 4)
            *(float4*)(op + k) = make_float4(acc[k], acc[k + 1], acc[k + 2], acc[k + 3]);
    }
}

// ---------------- launch ----------------
extern "C" void kernel_launch(void* const* d_in, const int* in_sizes, int n_in,
                              void* d_out, int out_size) {
    const float* x     = (const float*)d_in[0];
    const float* W_emb = (const float*)d_in[1];
    const float* b_emb = (const float*)d_in[2];
    const float* W0    = (const float*)d_in[3];
    const float* as0   = (const float*)d_in[4];
    const float* ad0   = (const float*)d_in[5];
    const float* b0    = (const float*)d_in[6];
    const float* W1    = (const float*)d_in[7];
    const float* as1   = (const float*)d_in[8];
    const float* ad1   = (const float*)d_in[9];
    const float* b1    = (const float*)d_in[10];
    const float* W2    = (const float*)d_in[11];
    const float* as2   = (const float*)d_in[12];
    const float* ad2   = (const float*)d_in[13];
    const float* b2    = (const float*)d_in[14];
    const float* Wo1   = (const float*)d_in[15];
    const float* bo1   = (const float*)d_in[16];
    const float* Wo2   = (const float*)d_in[17];
    const float* bo2   = (const float*)d_in[18];
    const int*   ei    = (const int*)d_in[19];
    float* out = (float*)d_out;

    float *p_h0, *p_hA, *p_hB;
    cudaGetSymbolAddress((void**)&p_h0, g_h0);
    cudaGetSymbolAddress((void**)&p_hA, g_hA);
    cudaGetSymbolAddress((void**)&p_hB, g_hB);
    __half* p_h0h = (__half*)p_h0;
    __half* p_hAh = (__half*)p_hA;
    __half* p_hBh = (__half*)p_hB;

    const int WARP_GRID = (NN * 32 + 255) / 256;
    const int WARP_GRID512 = (NN * 32 + 511) / 512;

    // [0] embedding GEMM ∥ edge histogram
    k_emb_hist<<<MBX + HB, 256>>>(x, W_emb, b_emb, p_h0h, ei);
    // [1] L0 GEMM (+fused alpha) ∥ rowptr scan (scan2 inline)
    k_l0_scan<<<2 * MBX + SCAN_BLK, 256>>>(p_h0h, W0, as0, ad0, p_hAh);
    // [2] scatter (rowptr finalized on the fly)
    k_scatter<<<(ET + 255) / 256, 256>>>(ei);
    // [3] layer-0 aggregation (restores scatter cursors)
    k_agg<4, true, true, false, true><<<WARP_GRID, 256>>>(p_hAh, b0, p_hBh,
        nullptr, nullptr, nullptr, nullptr);
    // [4] L1 GEMM + fused alpha
    k_mma<128, true, 4><<<dim3(MBX, 2), 256>>>(p_hBh, W1, as1, ad1, p_hAh, NN, HEADS * HID, 256);
    // [5] (profiled) layer-1 aggregation
    k_agg<4, true, true, false, false><<<WARP_GRID, 256>>>(p_hAh, b1, p_hBh,
        nullptr, nullptr, nullptr, nullptr);
    // [6] L2 GEMM (N=64) + fused alpha (H=1)
    k_mma<64, true, 1><<<dim3(MBX, 1), 256>>>(p_hBh, W2, as2, ad2, p_hAh, NN, HEADS * HID, HID);
    // [7] layer-2 aggregation + fused output MLP
    k_agg<1, false, false, true, false><<<WARP_GRID512, 512>>>(p_hAh, b2, out,
        Wo1, bo1, Wo2, bo2);
}

// round 17
// speedup vs baseline: 2.2626x; 1.0295x over previous
#include <cuda_runtime.h>
#include <cuda_fp16.h>
#include <cstdint>

#define NN 50000
#define NE 800000
#define ET 850000            // NE + NN self loops
#define FIN 128
#define HID 64
#define HEADS 4
#define MBX 391              // (NN+127)/128
#define SCAN_BLK 196         // (NN+255)/256
#define HB 416               // ceil(ET/2048) hist blocks

typedef unsigned long long ull;

// ---------------- device scratch (static allocation only) ----------------
// g_cnt / g_cur2 / g_tk are SELF-RESTORING each launch.
static __device__ float g_h0[NN * HID];            // used as half [NN][64]
static __device__ float g_hA[NN * HEADS * HID];    // used as half [NN][256]
static __device__ float g_hB[NN * HEADS * HID];    // used as half [NN][256]
static __device__ float g_as[NN * HEADS];
static __device__ float g_ad[NN * HEADS];
static __device__ int   g_cnt[NN];
static __device__ int   g_rowptr[NN + 1];
static __device__ int   g_cur2[NN];
static __device__ int   g_csrc[ET];
static __device__ int   g_bsum[256];
static __device__ int   g_boff[256];
static __device__ int   g_tk;

__device__ __forceinline__ float leaky(float v) { return v > 0.f ? v : 0.2f * v; }
__device__ __forceinline__ uint32_t cvt_tf32(float f) {
    uint32_t r; asm("cvt.rna.tf32.f32 %0, %1;" : "=r"(r) : "f"(f)); return r;
}
__device__ __forceinline__ ull dupf(float f) {
    ull r; asm("mov.b64 %0, {%1, %1};" : "=l"(r) : "f"(f)); return r;
}
__device__ __forceinline__ ull packf2(float2 p) {
    ull r; asm("mov.b64 %0, {%1, %2};" : "=l"(r) : "f"(p.x), "f"(p.y)); return r;
}
__device__ __forceinline__ void ffma2(ull& d, ull a, ull b) {
    asm("fma.rn.f32x2 %0, %1, %2, %0;" : "+l"(d) : "l"(a), "l"(b));
}
__device__ __forceinline__ float2 unpack2(ull v) {
    float2 r; asm("mov.b64 {%0, %1}, %2;" : "=f"(r.x), "=f"(r.y) : "l"(v)); return r;
}

// ---------------- block scan helper ----------------
__device__ __forceinline__ int blk_scan_excl(int v, int* total, int lane, int wid, int nw) {
    __shared__ int wsum[32];
    int x = v;
    #pragma unroll
    for (int o = 1; o < 32; o <<= 1) {
        int y = __shfl_up_sync(0xffffffffu, x, o);
        if (lane >= o) x += y;
    }
    if (lane == 31) wsum[wid] = x;
    __syncthreads();
    if (wid == 0) {
        int w = (lane < nw) ? wsum[lane] : 0;
        #pragma unroll
        for (int o = 1; o < 32; o <<= 1) {
            int y = __shfl_up_sync(0xffffffffu, w, o);
            if (lane >= o) w += y;
        }
        wsum[lane] = w;
    }
    __syncthreads();
    int base = (wid > 0) ? wsum[wid - 1] : 0;
    *total = wsum[nw - 1];
    return base + x - v;
}

__device__ void scan_body(int b) {
    int tid = threadIdx.x;
    int i = b * 256 + tid;
    int v = (i < NN) ? g_cnt[i] : 0;
    int total;
    int excl = blk_scan_excl(v, &total, tid & 31, tid >> 5, 8);
    if (i < NN) { g_rowptr[i] = excl; g_cnt[i] = 0; }
    __shared__ int s_last;
    if (tid == 0) {
        g_bsum[b] = total;
        __threadfence();
        int t = atomicAdd(&g_tk, 1);
        s_last = (t == SCAN_BLK - 1) ? 1 : 0;
    }
    __syncthreads();
    if (s_last) {
        int v2 = (tid < SCAN_BLK) ? g_bsum[tid] : 0;
        int tot2;
        int e2 = blk_scan_excl(v2, &tot2, tid & 31, tid >> 5, 8);
        g_boff[tid] = e2;
        if (tid == 0) g_tk = 0;
    }
}

// ========== unified tf32 mma.sync body: Ch[M,N] = A[M,K] @ W[K,N] ==========
// BM=128, BK=16, 256 threads. Paired-k smem for BOTH operands: every
// fragment pair (k, k+4) is one conflict-free LDS.64.
//   A: [m][AST=24], k order 0,4,1,5 | 2,6,3,7
//   B: uint2 pairs, pair-row stride BNP (BNP≡4 mod 16 -> phase conflict-free)
#define AST 24

__device__ __forceinline__ void mma_tf32(float c[4], const uint32_t a[4], const uint32_t b[2]) {
    asm volatile(
        "mma.sync.aligned.m16n8k8.row.col.f32.tf32.tf32.f32 "
        "{%0,%1,%2,%3}, {%4,%5,%6,%7}, {%8,%9}, {%0,%1,%2,%3};"
        : "+f"(c[0]), "+f"(c[1]), "+f"(c[2]), "+f"(c[3])
        : "r"(a[0]), "r"(a[1]), "r"(a[2]), "r"(a[3]), "r"(b[0]), "r"(b[1]));
}

template<int BN, bool A_HALF, bool BIAS, bool RELU, int ALPHA_H>
__device__ __forceinline__ void mma_body(
    int bx, int by,
    const void* __restrict__ Av, const float* __restrict__ W,
    const float* __restrict__ bias,
    const float* __restrict__ a_src, const float* __restrict__ a_dst,
    __half* __restrict__ Ch, int M, int K, int N)
{
    constexpr int BNP = (BN == 128) ? 132 : 68;   // uint2 units per pair-row
    constexpr int NWN = BN / 64;
    constexpr int MT  = (BN == 128) ? 2 : 1;
    constexpr int CPT = BN / 32;                  // B cols per thread (4 or 2)
    __shared__ __align__(16) uint32_t As[2][128 * AST];
    __shared__ __align__(16) uint32_t Bs[2][8 * BNP * 2];

    const int tid = threadIdx.x;
    const int wid = tid >> 5, lane = tid & 31;
    const int g = lane >> 2, tig = lane & 3;
    const int warp_m = (wid / NWN) * (MT * 16);
    const int warp_n = (wid % NWN) * 64;
    const int m0 = bx * 128;
    const int n0 = by * BN;

    float acc[MT][8][4];
    #pragma unroll
    for (int mt = 0; mt < MT; mt++)
        #pragma unroll
        for (int nt = 0; nt < 8; nt++)
            #pragma unroll
            for (int q = 0; q < 4; q++) acc[mt][nt][q] = 0.f;

    // A global mapping
    const int ar = tid >> 1, akh = (tid & 1) << 3;
    const bool av = (m0 + ar) < M;
    const float*  Apf = (const float*)Av  + (size_t)(m0 + ar) * K + akh;
    const __half* Aph = (const __half*)Av + (size_t)(m0 + ar) * K + akh;
    // B global mapping: thread loads k rows (bk0, bk0+4) x CPT cols
    const int bgrp = tid >> 7;              // 0/1 -> k base 0/8
    const int bpi  = (tid >> 5) & 3;        // pair idx
    const int bnl  = (tid & 31) * CPT;      // local n
    const int bk0  = bgrp * 8 + bpi;
    const float* Wp0 = W + (size_t)bk0 * N + n0 + bnl;
    const float* Wp1 = Wp0 + (size_t)4 * N;
    const int WB = ((bgrp * 4 + bpi) * BNP + bnl) * 2;   // smem word base

    const float4 fz4 = make_float4(0.f, 0.f, 0.f, 0.f);
    float4 fa0, fa1, fb0, fb1;
    float2 fc0, fc1;
    uint4  ua = make_uint4(0, 0, 0, 0);

    #define LOAD_A(k0_) do { \
        if (A_HALF) { ua = av ? *(const uint4*)(Aph + (k0_)) : make_uint4(0,0,0,0); } \
        else { fa0 = av ? *(const float4*)(Apf + (k0_)) : fz4; \
               fa1 = av ? *(const float4*)(Apf + (k0_) + 4) : fz4; } \
    } while (0)
    #define LOAD_B(k0_) do { \
        if (BN == 128) { \
            fb0 = *(const float4*)(Wp0 + (size_t)(k0_) * N); \
            fb1 = *(const float4*)(Wp1 + (size_t)(k0_) * N); \
        } else { \
            fc0 = *(const float2*)(Wp0 + (size_t)(k0_) * N); \
            fc1 = *(const float2*)(Wp1 + (size_t)(k0_) * N); \
        } \
    } while (0)
    #define STORE_AB(bf_) do { \
        float x0,x1,x2,x3,x4,x5,x6,x7; \
        if (A_HALF) { \
            float2 p0 = __half22float2(*(__half2*)&ua.x); \
            float2 p1 = __half22float2(*(__half2*)&ua.y); \
            float2 p2 = __half22float2(*(__half2*)&ua.z); \
            float2 p3 = __half22float2(*(__half2*)&ua.w); \
            x0=p0.x; x1=p0.y; x2=p1.x; x3=p1.y; x4=p2.x; x5=p2.y; x6=p3.x; x7=p3.y; \
        } else { x0=fa0.x; x1=fa0.y; x2=fa0.z; x3=fa0.w; x4=fa1.x; x5=fa1.y; x6=fa1.z; x7=fa1.w; } \
        *(uint4*)&As[bf_][ar * AST + akh]     = make_uint4(cvt_tf32(x0), cvt_tf32(x4), cvt_tf32(x1), cvt_tf32(x5)); \
        *(uint4*)&As[bf_][ar * AST + akh + 4] = make_uint4(cvt_tf32(x2), cvt_tf32(x6), cvt_tf32(x3), cvt_tf32(x7)); \
        if (BN == 128) { \
            *(uint4*)&Bs[bf_][WB]     = make_uint4(cvt_tf32(fb0.x), cvt_tf32(fb1.x), cvt_tf32(fb0.y), cvt_tf32(fb1.y)); \
            *(uint4*)&Bs[bf_][WB + 4] = make_uint4(cvt_tf32(fb0.z), cvt_tf32(fb1.z), cvt_tf32(fb0.w), cvt_tf32(fb1.w)); \
        } else { \
            *(uint4*)&Bs[bf_][WB]     = make_uint4(cvt_tf32(fc0.x), cvt_tf32(fc1.x), cvt_tf32(fc0.y), cvt_tf32(fc1.y)); \
        } \
    } while (0)

    LOAD_A(0); LOAD_B(0);
    STORE_AB(0);
    __syncthreads();

    const int nch = K >> 4;
    int buf = 0;
    for (int c = 1; c <= nch; c++) {
        if (c < nch) { LOAD_A(c << 4); LOAD_B(c << 4); }
        #pragma unroll
        for (int ks = 0; ks < 2; ks++) {
            const int kc = ks << 3;
            uint32_t a[MT][4], b[8][2];
            #pragma unroll
            for (int mt = 0; mt < MT; mt++) {
                int mr = warp_m + (mt << 4) + g;
                uint2 pa0 = *(const uint2*)&As[buf][mr * AST + kc + (tig << 1)];
                uint2 pa1 = *(const uint2*)&As[buf][(mr + 8) * AST + kc + (tig << 1)];
                a[mt][0] = pa0.x; a[mt][2] = pa0.y;
                a[mt][1] = pa1.x; a[mt][3] = pa1.y;
            }
            #pragma unroll
            for (int nt = 0; nt < 8; nt++) {
                int nc = warp_n + (nt << 3) + g;
                uint2 pb = *(const uint2*)&Bs[buf][((ks * 4 + tig) * BNP + nc) * 2];
                b[nt][0] = pb.x; b[nt][1] = pb.y;
            }
            #pragma unroll
            for (int mt = 0; mt < MT; mt++)
                #pragma unroll
                for (int nt = 0; nt < 8; nt++)
                    mma_tf32(acc[mt][nt], a[mt], b[nt]);
        }
        if (c < nch) {
            int nb = buf ^ 1;
            STORE_AB(nb);
            __syncthreads();
            buf = nb;
        }
    }
    #undef LOAD_A
    #undef LOAD_B
    #undef STORE_AB

    // ---- epilogue: bias/relu, fp16 store, fused in-warp alpha dots ----
    #pragma unroll
    for (int mt = 0; mt < MT; mt++) {
        int r0 = m0 + warp_m + (mt << 4) + g;
        int r1 = r0 + 8;
        float ps0 = 0.f, pd0 = 0.f, ps1 = 0.f, pd1 = 0.f;
        #pragma unroll
        for (int nt = 0; nt < 8; nt++) {
            int col = n0 + warp_n + (nt << 3) + (tig << 1);
            float c0 = acc[mt][nt][0], c1 = acc[mt][nt][1];
            float c2 = acc[mt][nt][2], c3 = acc[mt][nt][3];
            if (BIAS) {
                float b0v = __ldg(bias + col), b1v = __ldg(bias + col + 1);
                c0 += b0v; c1 += b1v; c2 += b0v; c3 += b1v;
            }
            if (RELU) {
                c0 = fmaxf(c0, 0.f); c1 = fmaxf(c1, 0.f);
                c2 = fmaxf(c2, 0.f); c3 = fmaxf(c3, 0.f);
            }
            if (r0 < M) *(__half2*)(Ch + (size_t)r0 * N + col) = __floats2half2_rn(c0, c1);
            if (r1 < M) *(__half2*)(Ch + (size_t)r1 * N + col) = __floats2half2_rn(c2, c3);
            if (ALPHA_H > 0) {
                float sa0 = __ldg(a_src + col), sa1 = __ldg(a_src + col + 1);
                float sd0 = __ldg(a_dst + col), sd1 = __ldg(a_dst + col + 1);
                ps0 += c0 * sa0 + c1 * sa1; pd0 += c0 * sd0 + c1 * sd1;
                ps1 += c2 * sa0 + c3 * sa1; pd1 += c2 * sd0 + c3 * sd1;
            }
        }
        if (ALPHA_H > 0) {
            #pragma unroll
            for (int o = 1; o < 4; o <<= 1) {
                ps0 += __shfl_xor_sync(0xffffffffu, ps0, o);
                pd0 += __shfl_xor_sync(0xffffffffu, pd0, o);
                ps1 += __shfl_xor_sync(0xffffffffu, ps1, o);
                pd1 += __shfl_xor_sync(0xffffffffu, pd1, o);
            }
            if (tig == 0) {
                int head = (n0 + warp_n) >> 6;
                if (r0 < M) { g_as[r0 * ALPHA_H + head] = ps0; g_ad[r0 * ALPHA_H + head] = pd0; }
                if (r1 < M) { g_as[r1 * ALPHA_H + head] = ps1; g_ad[r1 * ALPHA_H + head] = pd1; }
            }
        }
    }
}

// ---------------- combined kernels ----------------
__global__ __launch_bounds__(256)
void k_emb_hist(const float* __restrict__ x, const float* __restrict__ W_emb,
                const float* __restrict__ b_emb, __half* __restrict__ h0,
                const int* __restrict__ ei) {
    if ((int)blockIdx.x < MBX) {
        mma_body<64, false, true, true, 0>(blockIdx.x, 0, x, W_emb, b_emb,
                                           nullptr, nullptr, h0, NN, FIN, HID);
    } else {
        int base = (blockIdx.x - MBX) * 2048 + threadIdx.x;
        #pragma unroll
        for (int j = 0; j < 8; j++) {
            int i = base + j * 256;
            if (i < ET) {
                int d = (i < NE) ? ei[NE + i] : (i - NE);
                atomicAdd(&g_cnt[d], 1);
            }
        }
    }
}

__global__ __launch_bounds__(256)
void k_l0_scan(const __half* __restrict__ h0, const float* __restrict__ W0,
               const float* __restrict__ as0, const float* __restrict__ ad0,
               __half* __restrict__ hA) {
    if ((int)blockIdx.x < 2 * MBX) {
        mma_body<128, true, false, false, 4>(blockIdx.x >> 1, blockIdx.x & 1,
                                             h0, W0, nullptr, as0, ad0, hA, NN, HID, 256);
    } else {
        scan_body(blockIdx.x - 2 * MBX);
    }
}

template<int BN, bool A_HALF, int ALPHA_H>
__global__ __launch_bounds__(256)
void k_mma(const void* __restrict__ Av, const float* __restrict__ W,
           const float* __restrict__ a_src, const float* __restrict__ a_dst,
           __half* __restrict__ Ch, int M, int K, int N) {
    mma_body<BN, A_HALF, false, false, ALPHA_H>(blockIdx.x, blockIdx.y, Av, W,
                                                nullptr, a_src, a_dst, Ch, M, K, N);
}

__global__ void k_scatter(const int* __restrict__ ei) {
    int i = blockIdx.x * blockDim.x + threadIdx.x;
    if (i >= ET) return;
    int s, d;
    if (i < NE) { s = ei[i]; d = ei[NE + i]; }
    else        { s = i - NE; d = s; }
    int pos = g_rowptr[d] + g_boff[d >> 8] + atomicAdd(&g_cur2[d], 1);
    g_csrc[pos] = s;
}

// ---------- single-pass softmax aggregation (FFMA2 accumulation) ----------
template<int H, bool RELU, bool OUT_HALF, bool FUSE_MLP, bool RESTORE>
__global__ void k_agg(const __half* __restrict__ h, const float* __restrict__ bias,
                      void* __restrict__ outv,
                      const float* __restrict__ Wo1, const float* __restrict__ bo1,
                      const float* __restrict__ Wo2, const float* __restrict__ bo2) {
    constexpr int HC = H * 64, EPL = HC / 32, LPH = 32 / H;
    constexpr int NACC = EPL / 2;
    __shared__ float sW1[FUSE_MLP ? 64 * 32 : 1];
    __shared__ float sW2[FUSE_MLP ? 32 : 1];
    __shared__ float sb1[FUSE_MLP ? 32 : 1];
    if (FUSE_MLP) {
        for (int i = threadIdx.x; i < 64 * 32; i += blockDim.x) sW1[i] = Wo1[i];
        if (threadIdx.x < 32) { sW2[threadIdx.x] = Wo2[threadIdx.x]; sb1[threadIdx.x] = bo1[threadIdx.x]; }
        __syncthreads();
    }
    const int gw = (blockIdx.x * blockDim.x + threadIdx.x) >> 5;
    const int lane = threadIdx.x & 31;
    if (gw >= NN) return;
    const int beg = g_rowptr[gw] + g_boff[gw >> 8];
    const int end = (gw == NN - 1) ? ET : (g_rowptr[gw + 1] + g_boff[(gw + 1) >> 8]);
    if (RESTORE && lane == 0) g_cur2[gw] = 0;
    const int head = lane / LPH;
    const float adv = g_ad[gw * H + head];

    float ws = 0.f;
    ull acc2[NACC];
    #pragma unroll
    for (int k = 0; k < NACC; k++) acc2[k] = 0ull;
    const __half* hb = h + lane * EPL;

    int i = beg;
    if constexpr (EPL == 8) {
        for (; i + 4 <= end; i += 4) {
            int s0 = g_csrc[i],     s1 = g_csrc[i + 1];
            int s2 = g_csrc[i + 2], s3 = g_csrc[i + 3];
            float a0 = g_as[s0 * H + head], a1 = g_as[s1 * H + head];
            float a2 = g_as[s2 * H + head], a3 = g_as[s3 * H + head];
            uint4 u0 = *(const uint4*)(hb + (size_t)s0 * HC);
            uint4 u1 = *(const uint4*)(hb + (size_t)s1 * HC);
            uint4 u2 = *(const uint4*)(hb + (size_t)s2 * HC);
            uint4 u3 = *(const uint4*)(hb + (size_t)s3 * HC);
            float e0 = __expf(leaky(a0 + adv));
            float e1 = __expf(leaky(a1 + adv));
            float e2 = __expf(leaky(a2 + adv));
            float e3 = __expf(leaky(a3 + adv));
            ws += e0 + e1 + e2 + e3;
            ull d0 = dupf(e0), d1 = dupf(e1), d2 = dupf(e2), d3 = dupf(e3);
            ffma2(acc2[0], packf2(__half22float2(*(__half2*)&u0.x)), d0);
            ffma2(acc2[1], packf2(__half22float2(*(__half2*)&u0.y)), d0);
            ffma2(acc2[2], packf2(__half22float2(*(__half2*)&u0.z)), d0);
            ffma2(acc2[3], packf2(__half22float2(*(__half2*)&u0.w)), d0);
            ffma2(acc2[0], packf2(__half22float2(*(__half2*)&u1.x)), d1);
            ffma2(acc2[1], packf2(__half22float2(*(__half2*)&u1.y)), d1);
            ffma2(acc2[2], packf2(__half22float2(*(__half2*)&u1.z)), d1);
            ffma2(acc2[3], packf2(__half22float2(*(__half2*)&u1.w)), d1);
            ffma2(acc2[0], packf2(__half22float2(*(__half2*)&u2.x)), d2);
            ffma2(acc2[1], packf2(__half22float2(*(__half2*)&u2.y)), d2);
            ffma2(acc2[2], packf2(__half22float2(*(__half2*)&u2.z)), d2);
            ffma2(acc2[3], packf2(__half22float2(*(__half2*)&u2.w)), d2);
            ffma2(acc2[0], packf2(__half22float2(*(__half2*)&u3.x)), d3);
            ffma2(acc2[1], packf2(__half22float2(*(__half2*)&u3.y)), d3);
            ffma2(acc2[2], packf2(__half22float2(*(__half2*)&u3.z)), d3);
            ffma2(acc2[3], packf2(__half22float2(*(__half2*)&u3.w)), d3);
        }
        for (; i < end; i++) {
            int s = g_csrc[i];
            float e = __expf(leaky(g_as[s * H + head] + adv));
            ws += e;
            uint4 u0 = *(const uint4*)(hb + (size_t)s * HC);
            ull d0 = dupf(e);
            ffma2(acc2[0], packf2(__half22float2(*(__half2*)&u0.x)), d0);
            ffma2(acc2[1], packf2(__half22float2(*(__half2*)&u0.y)), d0);
            ffma2(acc2[2], packf2(__half22float2(*(__half2*)&u0.z)), d0);
            ffma2(acc2[3], packf2(__half22float2(*(__half2*)&u0.w)), d0);
        }
    } else {
        for (; i + 2 <= end; i += 2) {
            int s0 = g_csrc[i], s1 = g_csrc[i + 1];
            float a0 = g_as[s0 * H + head];
            float a1 = g_as[s1 * H + head];
            __half2 v0 = *(const __half2*)(hb + (size_t)s0 * HC);
            __half2 v1 = *(const __half2*)(hb + (size_t)s1 * HC);
            float e0 = __expf(leaky(a0 + adv));
            float e1 = __expf(leaky(a1 + adv));
            ws += e0 + e1;
            ffma2(acc2[0], packf2(__half22float2(v0)), dupf(e0));
            ffma2(acc2[0], packf2(__half22float2(v1)), dupf(e1));
        }
        if (i < end) {
            int s = g_csrc[i];
            float e = __expf(leaky(g_as[s * H + head] + adv));
            ws += e;
            __half2 v0 = *(const __half2*)(hb + (size_t)s * HC);
            ffma2(acc2[0], packf2(__half22float2(v0)), dupf(e));
        }
    }

    float acc[EPL];
    #pragma unroll
    for (int k = 0; k < NACC; k++) {
        float2 u = unpack2(acc2[k]);
        acc[2 * k] = u.x; acc[2 * k + 1] = u.y;
    }

    const float rinv = 1.f / ws;
    const float* bp = bias + lane * EPL;
    #pragma unroll
    for (int k = 0; k < EPL; k++) {
        float v = acc[k] * rinv + bp[k];
        if (RELU) v = fmaxf(v, 0.f);
        acc[k] = v;
    }

    if constexpr (FUSE_MLP) {
        float v0 = acc[0], v1 = acc[1];
        float hid = sb1[lane];
        #pragma unroll
        for (int k = 0; k < 32; k++) {
            float r0 = __shfl_sync(0xffffffffu, v0, k);
            float r1 = __shfl_sync(0xffffffffu, v1, k);
            hid = fmaf(r0, sW1[(2 * k) * 32 + lane], hid);
            hid = fmaf(r1, sW1[(2 * k + 1) * 32 + lane], hid);
        }
        hid = fmaxf(hid, 0.f);
        float o = hid * sW2[lane];
        #pragma unroll
        for (int w = 1; w < 32; w <<= 1) o += __shfl_xor_sync(0xffffffffu, o, w);
        if (lane == 0) ((float*)outv)[gw] = o + bo2[0];
    } else if constexpr (OUT_HALF) {
        __half* op = (__half*)outv + (size_t)gw * HC + lane * EPL;
        __half2 h0 = __floats2half2_rn(acc[0], acc[1]);
        __half2 h1 = __floats2half2_rn(acc[2], acc[3]);
        __half2 h2 = __floats2half2_rn(acc[4], acc[5]);
        __half2 h3 = __floats2half2_rn(acc[6], acc[7]);
        *(uint4*)op = make_uint4(*(uint32_t*)&h0, *(uint32_t*)&h1,
                                 *(uint32_t*)&h2, *(uint32_t*)&h3);
    } else {
        float* op = (float*)outv + (size_t)gw * HC + lane * EPL;
        #pragma unroll
        for (int k = 0; k < EPL; k += 4)
            *(float4*)(op + k) = make_float4(acc[k], acc[k + 1], acc[k + 2], acc[k + 3]);
    }
}

// ---------------- launch ----------------
extern "C" void kernel_launch(void* const* d_in, const int* in_sizes, int n_in,
                              void* d_out, int out_size) {
    const float* x     = (const float*)d_in[0];
    const float* W_emb = (const float*)d_in[1];
    const float* b_emb = (const float*)d_in[2];
    const float* W0    = (const float*)d_in[3];
    const float* as0   = (const float*)d_in[4];
    const float* ad0   = (const float*)d_in[5];
    const float* b0    = (const float*)d_in[6];
    const float* W1    = (const float*)d_in[7];
    const float* as1   = (const float*)d_in[8];
    const float* ad1   = (const float*)d_in[9];
    const float* b1    = (const float*)d_in[10];
    const float* W2    = (const float*)d_in[11];
    const float* as2   = (const float*)d_in[12];
    const float* ad2   = (const float*)d_in[13];
    const float* b2    = (const float*)d_in[14];
    const float* Wo1   = (const float*)d_in[15];
    const float* bo1   = (const float*)d_in[16];
    const float* Wo2   = (const float*)d_in[17];
    const float* bo2   = (const float*)d_in[18];
    const int*   ei    = (const int*)d_in[19];
    float* out = (float*)d_out;

    float *p_h0, *p_hA, *p_hB;
    cudaGetSymbolAddress((void**)&p_h0, g_h0);
    cudaGetSymbolAddress((void**)&p_hA, g_hA);
    cudaGetSymbolAddress((void**)&p_hB, g_hB);
    __half* p_h0h = (__half*)p_h0;
    __half* p_hAh = (__half*)p_hA;
    __half* p_hBh = (__half*)p_hB;

    const int WARP_GRID = (NN * 32 + 255) / 256;
    const int WARP_GRID512 = (NN * 32 + 511) / 512;

    // [0] embedding GEMM ∥ edge histogram
    k_emb_hist<<<MBX + HB, 256>>>(x, W_emb, b_emb, p_h0h, ei);
    // [1] L0 GEMM (+fused alpha) ∥ rowptr scan (scan2 inline)
    k_l0_scan<<<2 * MBX + SCAN_BLK, 256>>>(p_h0h, W0, as0, ad0, p_hAh);
    // [2] scatter (rowptr finalized on the fly)
    k_scatter<<<(ET + 255) / 256, 256>>>(ei);
    // [3] layer-0 aggregation (restores scatter cursors)
    k_agg<4, true, true, false, true><<<WARP_GRID, 256>>>(p_hAh, b0, p_hBh,
        nullptr, nullptr, nullptr, nullptr);
    // [4] L1 GEMM + fused alpha
    k_mma<128, true, 4><<<dim3(MBX, 2), 256>>>(p_hBh, W1, as1, ad1, p_hAh, NN, HEADS * HID, 256);
    // [5] layer-1 aggregation
    k_agg<4, true, true, false, false><<<WARP_GRID, 256>>>(p_hAh, b1, p_hBh,
        nullptr, nullptr, nullptr, nullptr);
    // [6] L2 GEMM (N=64) + fused alpha (H=1)
    k_mma<64, true, 1><<<dim3(MBX, 1), 256>>>(p_hBh, W2, as2, ad2, p_hAh, NN, HEADS * HID, HID);
    // [7] layer-2 aggregation + fused output MLP
    k_agg<1, false, false, true, false><<<WARP_GRID512, 512>>>(p_hAh, b2, out,
        Wo1, bo1, Wo2, bo2);
}